// round 2
// baseline (speedup 1.0000x reference)
#include <cuda_runtime.h>
#include <cuda_bf16.h>
#include <math.h>

// ----------------------------------------------------------------------------
// Problem constants
// ----------------------------------------------------------------------------
#define BB   16
#define MM   128
#define LL   32
#define SS   512
#define DD   768
#define HH   12
#define HD   64
#define DFF  3072
#define NL   4
#define NE   50000
#define ROWS (BB*MM)          // 2048

// ----------------------------------------------------------------------------
// Device scratch (static allocation — no cudaMalloc allowed)
// ----------------------------------------------------------------------------
__device__ float g_hl[BB*LL];                 // per (b,l) attention logits
__device__ float g_x [ROWS*DD];               // main activation [2048,768]
__device__ float g_qkv[ROWS*3*DD];            // qkv buffer [2048,2304]
__device__ float g_s [BB*HH*MM*MM];           // attention scores [192,128,128]
__device__ float g_ao[ROWS*DD];               // attn-out / ff2-out [2048,768]
__device__ float g_tmp[ROWS*DFF];             // out-proj result / ff hidden
__device__ float g_y [ROWS*100];              // classifier intermediate

// ----------------------------------------------------------------------------
// hl[b,l] = dot(hidden[b,l,:], attn_w)
// ----------------------------------------------------------------------------
__global__ void hl_kernel(const float* __restrict__ lhs,
                          const float* __restrict__ aw,
                          float* __restrict__ hl)
{
    int blk = blockIdx.x;            // 0..511
    int b = blk >> 5, l = blk & 31;
    const float* row = lhs + ((size_t)b * SS + l) * DD;
    int t = threadIdx.x;             // 256
    float p = 0.f;
    for (int i = t; i < DD; i += 256) p += row[i] * aw[i];
    #pragma unroll
    for (int o = 16; o; o >>= 1) p += __shfl_xor_sync(~0u, p, o);
    __shared__ float red[8];
    if ((t & 31) == 0) red[t >> 5] = p;
    __syncthreads();
    if (t == 0) {
        float s = 0.f;
        #pragma unroll
        for (int i = 0; i < 8; i++) s += red[i];
        hl[b * LL + l] = s;
    }
}

// ----------------------------------------------------------------------------
// Mention pooling: x[b,m,:] = sum_{l<nv} softmax_l * hidden[b,l,:]
// Softmax over all 32 slots: valid slots have logit hl, invalid slots 0
// (attn_b uniform shift dropped). nv = leading run of pos != -1, gated by mask.
// NOTE: pos/mask are int32 (JAX x64-disabled: astype(int64) -> int32).
// ----------------------------------------------------------------------------
__global__ void pool_kernel(const float* __restrict__ lhs,
                            const int* __restrict__ pos,
                            const int* __restrict__ mask,
                            const float* __restrict__ hl,
                            float* __restrict__ x)
{
    int bm = blockIdx.x;             // 0..2047
    int b = bm >> 7;
    int t = threadIdx.x;             // 256
    __shared__ float ws[LL];
    __shared__ int s_nv;
    if (t < 32) {
        int p = pos[(size_t)bm * LL + t];
        unsigned bits = __ballot_sync(0xffffffffu, p != -1);
        int nv;
        if (mask[bm] == 0) nv = 0;
        else if (~bits == 0u) nv = 32;
        else nv = __ffs(~bits) - 1;
        float logit = (t < nv) ? hl[b * LL + t] : 0.f;
        float mx = logit;
        #pragma unroll
        for (int o = 16; o; o >>= 1) mx = fmaxf(mx, __shfl_xor_sync(~0u, mx, o));
        float e = expf(logit - mx);
        float s = e;
        #pragma unroll
        for (int o = 16; o; o >>= 1) s += __shfl_xor_sync(~0u, s, o);
        ws[t] = e / s;
        if (t == 0) s_nv = nv;
    }
    __syncthreads();
    int nv = s_nv;
    for (int d = t; d < DD; d += 256) {
        float acc = 0.f;
        for (int l = 0; l < nv; l++)
            acc += ws[l] * lhs[((size_t)b * SS + l) * DD + d];
        x[(size_t)bm * DD + d] = acc;
    }
}

// ----------------------------------------------------------------------------
// General NT GEMM: C[M,N] = A[M,K] * B[N,K]^T (+bias, optional relu)
// 128x128 tile, BK=8, 256 threads, 8x8 microtile.
// M is always a multiple of 128. N guarded. K must be a multiple of 4.
// ----------------------------------------------------------------------------
template<int RELU>
__global__ __launch_bounds__(256)
void gemm_nt(const float* __restrict__ A, const float* __restrict__ B,
             const float* __restrict__ bias, float* __restrict__ C,
             int M, int N, int K)
{
    __shared__ float As[8][128];
    __shared__ float Bs[8][128];
    const int t  = threadIdx.x;
    const int tx = t & 15, ty = t >> 4;
    const int mBase = blockIdx.y * 128;
    const int nBase = blockIdx.x * 128;
    const int lrow  = t >> 1;          // 0..127
    const int lcol0 = (t & 1) * 4;     // 0 or 4

    float acc[8][8];
    #pragma unroll
    for (int i = 0; i < 8; i++)
        #pragma unroll
        for (int j = 0; j < 8; j++) acc[i][j] = 0.f;

    const float4 z4 = make_float4(0.f, 0.f, 0.f, 0.f);
    for (int k0 = 0; k0 < K; k0 += 8) {
        int kk = k0 + lcol0;
        bool kok = (kk + 4 <= K);      // K % 4 == 0 always here
        float4 av = kok ? *(const float4*)(A + (size_t)(mBase + lrow) * K + kk) : z4;
        int brow = nBase + lrow;
        float4 bv = (kok && brow < N) ? *(const float4*)(B + (size_t)brow * K + kk) : z4;
        As[lcol0 + 0][lrow] = av.x; As[lcol0 + 1][lrow] = av.y;
        As[lcol0 + 2][lrow] = av.z; As[lcol0 + 3][lrow] = av.w;
        Bs[lcol0 + 0][lrow] = bv.x; Bs[lcol0 + 1][lrow] = bv.y;
        Bs[lcol0 + 2][lrow] = bv.z; Bs[lcol0 + 3][lrow] = bv.w;
        __syncthreads();
        #pragma unroll
        for (int k = 0; k < 8; k++) {
            float a[8], bb[8];
            #pragma unroll
            for (int i = 0; i < 8; i++) a[i]  = As[k][ty * 8 + i];
            #pragma unroll
            for (int j = 0; j < 8; j++) bb[j] = Bs[k][tx * 8 + j];
            #pragma unroll
            for (int i = 0; i < 8; i++)
                #pragma unroll
                for (int j = 0; j < 8; j++)
                    acc[i][j] += a[i] * bb[j];
        }
        __syncthreads();
    }

    #pragma unroll
    for (int i = 0; i < 8; i++) {
        int r = mBase + ty * 8 + i;
        #pragma unroll
        for (int j = 0; j < 8; j++) {
            int c = nBase + tx * 8 + j;
            if (c < N) {
                float v = acc[i][j] + (bias ? bias[c] : 0.f);
                if (RELU) v = fmaxf(v, 0.f);
                C[(size_t)r * N + c] = v;
            }
        }
    }
}

// ----------------------------------------------------------------------------
// Attention scores: S[bh,m,n] = 0.125 * sum_d Q[m,d] K[n,d]
// One CTA per (b,h). d tiled by 32, 8x8 microtile.
// ----------------------------------------------------------------------------
__global__ __launch_bounds__(256)
void attn_scores(const float* __restrict__ qkv, float* __restrict__ S)
{
    __shared__ float Qt[32][133];
    __shared__ float Kt[32][133];
    int bh = blockIdx.x;
    int b = bh / HH, h = bh % HH;
    const float* base = qkv + (size_t)b * MM * (3 * DD) + h * HD;
    int t = threadIdx.x, tx = t & 15, ty = t >> 4;
    float acc[8][8];
    #pragma unroll
    for (int i = 0; i < 8; i++)
        #pragma unroll
        for (int j = 0; j < 8; j++) acc[i][j] = 0.f;

    for (int d0 = 0; d0 < HD; d0 += 32) {
        #pragma unroll
        for (int i = 0; i < 16; i++) {
            int e = t + 256 * i;       // 4096 elems
            int d = e & 31, m = e >> 5;
            Qt[d][m] = base[(size_t)m * (3 * DD) + d0 + d];
            Kt[d][m] = base[(size_t)m * (3 * DD) + DD + d0 + d];
        }
        __syncthreads();
        #pragma unroll
        for (int d = 0; d < 32; d++) {
            float a[8], bb[8];
            #pragma unroll
            for (int i = 0; i < 8; i++) a[i]  = Qt[d][ty * 8 + i];
            #pragma unroll
            for (int j = 0; j < 8; j++) bb[j] = Kt[d][tx * 8 + j];
            #pragma unroll
            for (int i = 0; i < 8; i++)
                #pragma unroll
                for (int j = 0; j < 8; j++)
                    acc[i][j] += a[i] * bb[j];
        }
        __syncthreads();
    }
    float* Sp = S + (size_t)bh * MM * MM;
    #pragma unroll
    for (int i = 0; i < 8; i++)
        #pragma unroll
        for (int j = 0; j < 8; j++)
            Sp[(size_t)(ty * 8 + i) * MM + tx * 8 + j] = acc[i][j] * 0.125f;
}

// ----------------------------------------------------------------------------
// Row softmax over 128 columns. One block (128 threads) per row.
// ----------------------------------------------------------------------------
__global__ void attn_softmax(float* __restrict__ S)
{
    float* p = S + (size_t)blockIdx.x * MM;
    int t = threadIdx.x;                 // 128
    float v = p[t];
    __shared__ float red[4];
    float mx = v;
    #pragma unroll
    for (int o = 16; o; o >>= 1) mx = fmaxf(mx, __shfl_xor_sync(~0u, mx, o));
    if ((t & 31) == 0) red[t >> 5] = mx;
    __syncthreads();
    mx = fmaxf(fmaxf(red[0], red[1]), fmaxf(red[2], red[3]));
    float e = expf(v - mx);
    float s = e;
    #pragma unroll
    for (int o = 16; o; o >>= 1) s += __shfl_xor_sync(~0u, s, o);
    __syncthreads();
    if ((t & 31) == 0) red[t >> 5] = s;
    __syncthreads();
    s = red[0] + red[1] + red[2] + red[3];
    p[t] = e / s;
}

// ----------------------------------------------------------------------------
// P @ V: ao[b,m,h*64+d] = sum_n P[m,n] V[n,d]. One CTA per (b,h).
// n tiled by 32; microtile 8x4.
// ----------------------------------------------------------------------------
__global__ __launch_bounds__(256)
void attn_pv(const float* __restrict__ qkv, const float* __restrict__ S,
             float* __restrict__ ao)
{
    __shared__ float Ps[128][33];
    __shared__ float Vs[32][68];
    int bh = blockIdx.x;
    int b = bh / HH, h = bh % HH;
    const float* Sp = S + (size_t)bh * MM * MM;
    const float* Vb = qkv + (size_t)b * MM * (3 * DD) + 2 * DD + h * HD;
    int t = threadIdx.x, tx = t & 15, ty = t >> 4;
    float acc[8][4];
    #pragma unroll
    for (int i = 0; i < 8; i++)
        #pragma unroll
        for (int j = 0; j < 4; j++) acc[i][j] = 0.f;

    for (int n0 = 0; n0 < MM; n0 += 32) {
        #pragma unroll
        for (int i = 0; i < 16; i++) {
            int e = t + 256 * i;       // 4096 = 128m x 32n
            int n = e & 31, m = e >> 5;
            Ps[m][n] = Sp[(size_t)m * MM + n0 + n];
        }
        #pragma unroll
        for (int i = 0; i < 8; i++) {
            int e = t + 256 * i;       // 2048 = 32n x 64d
            int d = e & 63, n = e >> 6;
            Vs[n][d] = Vb[(size_t)(n0 + n) * (3 * DD) + d];
        }
        __syncthreads();
        #pragma unroll
        for (int n = 0; n < 32; n++) {
            float a[8], bb[4];
            #pragma unroll
            for (int i = 0; i < 8; i++) a[i]  = Ps[ty * 8 + i][n];
            #pragma unroll
            for (int j = 0; j < 4; j++) bb[j] = Vs[n][tx * 4 + j];
            #pragma unroll
            for (int i = 0; i < 8; i++)
                #pragma unroll
                for (int j = 0; j < 4; j++)
                    acc[i][j] += a[i] * bb[j];
        }
        __syncthreads();
    }
    float* aop = ao + (size_t)b * MM * DD + h * HD;
    #pragma unroll
    for (int i = 0; i < 8; i++)
        #pragma unroll
        for (int j = 0; j < 4; j++)
            aop[(size_t)(ty * 8 + i) * DD + tx * 4 + j] = acc[i][j];
}

// ----------------------------------------------------------------------------
// x = LayerNorm(x + delta) * w + b   (row length 768, 256 threads per row)
// ----------------------------------------------------------------------------
__global__ __launch_bounds__(256)
void add_ln_kernel(float* __restrict__ x, const float* __restrict__ d,
                   const float* __restrict__ w, const float* __restrict__ b)
{
    int row = blockIdx.x, t = threadIdx.x;
    float* xp = x + (size_t)row * DD;
    const float* dp = d + (size_t)row * DD;
    float v0 = xp[t]       + dp[t];
    float v1 = xp[t + 256] + dp[t + 256];
    float v2 = xp[t + 512] + dp[t + 512];
    float s = v0 + v1 + v2;
    __shared__ float red[8];
    #pragma unroll
    for (int o = 16; o; o >>= 1) s += __shfl_xor_sync(~0u, s, o);
    if ((t & 31) == 0) red[t >> 5] = s;
    __syncthreads();
    float tot = red[0] + red[1] + red[2] + red[3] + red[4] + red[5] + red[6] + red[7];
    float mu = tot * (1.f / 768.f);
    float d0 = v0 - mu, d1 = v1 - mu, d2 = v2 - mu;
    float q = d0 * d0 + d1 * d1 + d2 * d2;
    #pragma unroll
    for (int o = 16; o; o >>= 1) q += __shfl_xor_sync(~0u, q, o);
    __syncthreads();
    if ((t & 31) == 0) red[t >> 5] = q;
    __syncthreads();
    float qt = red[0] + red[1] + red[2] + red[3] + red[4] + red[5] + red[6] + red[7];
    float inv = rsqrtf(qt * (1.f / 768.f) + 1e-5f);
    xp[t]       = d0 * inv * w[t]       + b[t];
    xp[t + 256] = d1 * inv * w[t + 256] + b[t + 256];
    xp[t + 512] = d2 * inv * w[t + 512] + b[t + 512];
}

// ----------------------------------------------------------------------------
// Host-side launch
// ----------------------------------------------------------------------------
static float* sym(const void* s)
{
    void* p = nullptr;
    cudaGetSymbolAddress(&p, s);
    return (float*)p;
}

extern "C" void kernel_launch(void* const* d_in, const int* in_sizes, int n_in,
                              void* d_out, int out_size)
{
    // Defensive size-based remapping: match expected element counts (in
    // declaration order) greedily against the provided inputs. Handles the
    // scalar attn_b being dropped or any benign reordering of distinct sizes;
    // equal-size runs keep their relative order.
    static const long long want[20] = {
        6291456LL,   // last_hidden_state
        65536LL,     // entity_position_ids (int32)
        2048LL,      // entity_attention_mask (int32)
        768LL,       // attn_w
        1LL,         // attn_b (unused; uniform softmax shift)
        7077888LL,   // qkv_w
        9216LL,      // qkv_b
        2359296LL,   // out_w
        3072LL,      // out_b
        3072LL,      // ln1_w
        3072LL,      // ln1_b
        9437184LL,   // ff1_w
        12288LL,     // ff1_b
        9437184LL,   // ff2_w
        3072LL,      // ff2_b
        3072LL,      // ln2_w
        3072LL,      // ln2_b
        76800LL,     // cls_w1
        5000000LL,   // cls_w2
        50000LL      // cls_b2
    };
    const void* slot[20];
    bool used[64];
    for (int i = 0; i < 20; i++) slot[i] = nullptr;
    for (int i = 0; i < n_in && i < 64; i++) used[i] = false;
    for (int w = 0; w < 20; w++) {
        for (int i = 0; i < n_in && i < 64; i++) {
            if (!used[i] && (long long)in_sizes[i] == want[w]) {
                slot[w] = d_in[i];
                used[i] = true;
                break;
            }
        }
    }
    // Fall back to positional if anything essential is missing.
    if (!slot[0]) {
        for (int w = 0; w < 20 && w < n_in; w++) slot[w] = d_in[w];
    }

    const float* lhs    = (const float*)slot[0];
    const int*   pos    = (const int*)slot[1];
    const int*   mask   = (const int*)slot[2];
    const float* attn_w = (const float*)slot[3];
    const float* qkv_w  = (const float*)slot[5];
    const float* qkv_b  = (const float*)slot[6];
    const float* out_w  = (const float*)slot[7];
    const float* out_b  = (const float*)slot[8];
    const float* ln1_w  = (const float*)slot[9];
    const float* ln1_b  = (const float*)slot[10];
    const float* ff1_w  = (const float*)slot[11];
    const float* ff1_b  = (const float*)slot[12];
    const float* ff2_w  = (const float*)slot[13];
    const float* ff2_b  = (const float*)slot[14];
    const float* ln2_w  = (const float*)slot[15];
    const float* ln2_b  = (const float*)slot[16];
    const float* cls_w1 = (const float*)slot[17];
    const float* cls_w2 = (const float*)slot[18];
    const float* cls_b2 = (const float*)slot[19];
    float* out = (float*)d_out;

    float* hl  = sym(g_hl);
    float* x   = sym(g_x);
    float* qkv = sym(g_qkv);
    float* s   = sym(g_s);
    float* ao  = sym(g_ao);
    float* tmp = sym(g_tmp);
    float* y   = sym(g_y);

    // mention pooling
    hl_kernel<<<BB * LL, 256>>>(lhs, attn_w, hl);
    pool_kernel<<<ROWS, 256>>>(lhs, pos, mask, hl, x);

    // transformer layers
    for (int i = 0; i < NL; i++) {
        gemm_nt<0><<<dim3(3 * DD / 128, ROWS / 128), 256>>>(
            x, qkv_w + (size_t)i * 3 * DD * DD, qkv_b + (size_t)i * 3 * DD,
            qkv, ROWS, 3 * DD, DD);
        attn_scores<<<BB * HH, 256>>>(qkv, s);
        attn_softmax<<<BB * HH * MM, 128>>>(s);
        attn_pv<<<BB * HH, 256>>>(qkv, s, ao);
        gemm_nt<0><<<dim3(DD / 128, ROWS / 128), 256>>>(
            ao, out_w + (size_t)i * DD * DD, out_b + (size_t)i * DD,
            tmp, ROWS, DD, DD);
        add_ln_kernel<<<ROWS, 256>>>(x, tmp, ln1_w + (size_t)i * DD, ln1_b + (size_t)i * DD);
        gemm_nt<1><<<dim3(DFF / 128, ROWS / 128), 256>>>(
            x, ff1_w + (size_t)i * DFF * DD, ff1_b + (size_t)i * DFF,
            tmp, ROWS, DFF, DD);
        gemm_nt<0><<<dim3(DD / 128, ROWS / 128), 256>>>(
            tmp, ff2_w + (size_t)i * DD * DFF, ff2_b + (size_t)i * DD,
            ao, ROWS, DD, DFF);
        add_ln_kernel<<<ROWS, 256>>>(x, ao, ln2_w + (size_t)i * DD, ln2_b + (size_t)i * DD);
    }

    // classifier head
    gemm_nt<0><<<dim3(1, ROWS / 128), 256>>>(x, cls_w1, nullptr, y, ROWS, 100, DD);
    gemm_nt<0><<<dim3((NE + 127) / 128, ROWS / 128), 256>>>(
        y, cls_w2, cls_b2, out, ROWS, NE, 100);
}

// round 3
// speedup vs baseline: 1.0600x; 1.0600x over previous
#include <cuda_runtime.h>
#include <cuda_bf16.h>
#include <math.h>

// ----------------------------------------------------------------------------
// Problem constants
// ----------------------------------------------------------------------------
#define BB   16
#define MM   128
#define LL   32
#define SS   512
#define DD   768
#define HH   12
#define HD   64
#define DFF  3072
#define NL   4
#define NE   50000
#define ROWS (BB*MM)          // 2048

typedef unsigned long long ull;

// ----------------------------------------------------------------------------
// Device scratch (static allocation — no cudaMalloc allowed)
// ----------------------------------------------------------------------------
__device__ float g_hl[BB*LL];                 // per (b,l) attention logits
__device__ float g_x [ROWS*DD];               // main activation [2048,768]
__device__ float g_qkv[ROWS*3*DD];            // qkv buffer [2048,2304]
__device__ float g_s [BB*HH*MM*MM];           // attention scores [192,128,128]
__device__ float g_ao[ROWS*DD];               // attn-out / ff2-out [2048,768]
__device__ float g_tmp[ROWS*DFF];             // out-proj result / ff hidden
__device__ float g_y [ROWS*100];              // classifier intermediate

// ----------------------------------------------------------------------------
// Packed f32x2 helpers (FFMA2 — PTX-only, ptxas won't auto-fuse)
// ----------------------------------------------------------------------------
__device__ __forceinline__ void ffma2(ull& d, ull a, ull b)
{
    asm("fma.rn.f32x2 %0, %1, %2, %0;" : "+l"(d) : "l"(a), "l"(b));
}
__device__ __forceinline__ ull bcast2(float x)
{
    ull r;
    unsigned u = __float_as_uint(x);
    asm("mov.b64 %0, {%1, %1};" : "=l"(r) : "r"(u));
    return r;
}

// ----------------------------------------------------------------------------
// hl[b,l] = dot(hidden[b,l,:], attn_w)
// ----------------------------------------------------------------------------
__global__ void hl_kernel(const float* __restrict__ lhs,
                          const float* __restrict__ aw,
                          float* __restrict__ hl)
{
    int blk = blockIdx.x;            // 0..511
    int b = blk >> 5, l = blk & 31;
    const float* row = lhs + ((size_t)b * SS + l) * DD;
    int t = threadIdx.x;             // 256
    float p = 0.f;
    for (int i = t; i < DD; i += 256) p += row[i] * aw[i];
    #pragma unroll
    for (int o = 16; o; o >>= 1) p += __shfl_xor_sync(~0u, p, o);
    __shared__ float red[8];
    if ((t & 31) == 0) red[t >> 5] = p;
    __syncthreads();
    if (t == 0) {
        float s = 0.f;
        #pragma unroll
        for (int i = 0; i < 8; i++) s += red[i];
        hl[b * LL + l] = s;
    }
}

// ----------------------------------------------------------------------------
// Mention pooling (pos/mask are int32: JAX x64-disabled).
// ----------------------------------------------------------------------------
__global__ void pool_kernel(const float* __restrict__ lhs,
                            const int* __restrict__ pos,
                            const int* __restrict__ mask,
                            const float* __restrict__ hl,
                            float* __restrict__ x)
{
    int bm = blockIdx.x;             // 0..2047
    int b = bm >> 7;
    int t = threadIdx.x;             // 256
    __shared__ float ws[LL];
    __shared__ int s_nv;
    if (t < 32) {
        int p = pos[(size_t)bm * LL + t];
        unsigned bits = __ballot_sync(0xffffffffu, p != -1);
        int nv;
        if (mask[bm] == 0) nv = 0;
        else if (~bits == 0u) nv = 32;
        else nv = __ffs(~bits) - 1;
        float logit = (t < nv) ? hl[b * LL + t] : 0.f;
        float mx = logit;
        #pragma unroll
        for (int o = 16; o; o >>= 1) mx = fmaxf(mx, __shfl_xor_sync(~0u, mx, o));
        float e = expf(logit - mx);
        float s = e;
        #pragma unroll
        for (int o = 16; o; o >>= 1) s += __shfl_xor_sync(~0u, s, o);
        ws[t] = e / s;
        if (t == 0) s_nv = nv;
    }
    __syncthreads();
    int nv = s_nv;
    for (int d = t; d < DD; d += 256) {
        float acc = 0.f;
        for (int l = 0; l < nv; l++)
            acc += ws[l] * lhs[((size_t)b * SS + l) * DD + d];
        x[(size_t)bm * DD + d] = acc;
    }
}

// ----------------------------------------------------------------------------
// NT GEMM, f32x2 packed math: C[M,N] = A[M,K] * B[N,K]^T (+bias, opt relu)
// Tile: TM x 128, BK=16, 256 threads, microtile (TM/16) x 8.
// Software pipeline: prefetch next K-slab into registers during compute.
// M % TM == 0, N guarded, K % 4 == 0.
// ----------------------------------------------------------------------------
template<int TM, int RELU>
__global__ __launch_bounds__(256)
void gemm_nt(const float* __restrict__ A, const float* __restrict__ B,
             const float* __restrict__ bias, float* __restrict__ C,
             int M, int N, int K)
{
    constexpr int MT = TM / 16;          // rows per thread (8 or 4)
    constexpr int NLA = TM * 4 / 256;    // A float4 loads per thread (2 or 1)
    __shared__ float As[16][TM + 2];
    __shared__ float Bs[16][130];

    const int t  = threadIdx.x;
    const int tx = t & 15, ty = t >> 4;
    const int mBase = blockIdx.y * TM;
    const int nBase = blockIdx.x * 128;

    ull acc[MT][4];
    #pragma unroll
    for (int i = 0; i < MT; i++)
        #pragma unroll
        for (int j = 0; j < 4; j++) acc[i][j] = 0ULL;

    const float4 z4 = make_float4(0.f, 0.f, 0.f, 0.f);
    float4 aR[NLA], bR[2];

    // prefetch slab 0
    #pragma unroll
    for (int r = 0; r < NLA; r++) {
        int e = t + 256 * r, row = e >> 2, kc = (e & 3) * 4;
        aR[r] = (kc + 4 <= K) ? *(const float4*)(A + (size_t)(mBase + row) * K + kc) : z4;
    }
    #pragma unroll
    for (int r = 0; r < 2; r++) {
        int e = t + 256 * r, row = e >> 2, kc = (e & 3) * 4;
        bR[r] = (kc + 4 <= K && nBase + row < N)
                ? *(const float4*)(B + (size_t)(nBase + row) * K + kc) : z4;
    }

    for (int k0 = 0; k0 < K; k0 += 16) {
        // store current slab
        #pragma unroll
        for (int r = 0; r < NLA; r++) {
            int e = t + 256 * r, row = e >> 2, kc = (e & 3) * 4;
            As[kc + 0][row] = aR[r].x; As[kc + 1][row] = aR[r].y;
            As[kc + 2][row] = aR[r].z; As[kc + 3][row] = aR[r].w;
        }
        #pragma unroll
        for (int r = 0; r < 2; r++) {
            int e = t + 256 * r, row = e >> 2, kc = (e & 3) * 4;
            Bs[kc + 0][row] = bR[r].x; Bs[kc + 1][row] = bR[r].y;
            Bs[kc + 2][row] = bR[r].z; Bs[kc + 3][row] = bR[r].w;
        }
        __syncthreads();

        // prefetch next slab
        int kn = k0 + 16;
        if (kn < K) {
            #pragma unroll
            for (int r = 0; r < NLA; r++) {
                int e = t + 256 * r, row = e >> 2, kc = (e & 3) * 4;
                aR[r] = (kn + kc + 4 <= K)
                        ? *(const float4*)(A + (size_t)(mBase + row) * K + kn + kc) : z4;
            }
            #pragma unroll
            for (int r = 0; r < 2; r++) {
                int e = t + 256 * r, row = e >> 2, kc = (e & 3) * 4;
                bR[r] = (kn + kc + 4 <= K && nBase + row < N)
                        ? *(const float4*)(B + (size_t)(nBase + row) * K + kn + kc) : z4;
            }
        }

        // compute 16 k-steps on packed pairs
        #pragma unroll
        for (int k = 0; k < 16; k++) {
            ull a2[MT], b2[4];
            #pragma unroll
            for (int i = 0; i < MT; i++) a2[i] = bcast2(As[k][ty * MT + i]);
            #pragma unroll
            for (int j = 0; j < 4; j++)
                b2[j] = *(const ull*)&Bs[k][tx * 8 + 2 * j];
            #pragma unroll
            for (int i = 0; i < MT; i++)
                #pragma unroll
                for (int j = 0; j < 4; j++)
                    ffma2(acc[i][j], a2[i], b2[j]);
        }
        __syncthreads();
    }

    #pragma unroll
    for (int i = 0; i < MT; i++) {
        int r = mBase + ty * MT + i;
        #pragma unroll
        for (int j = 0; j < 4; j++) {
            int c0 = nBase + tx * 8 + 2 * j;
            float lo = __uint_as_float((unsigned)(acc[i][j] & 0xffffffffULL));
            float hi = __uint_as_float((unsigned)(acc[i][j] >> 32));
            if (c0 < N) {
                float v = lo + (bias ? bias[c0] : 0.f);
                if (RELU) v = fmaxf(v, 0.f);
                C[(size_t)r * N + c0] = v;
            }
            if (c0 + 1 < N) {
                float v = hi + (bias ? bias[c0 + 1] : 0.f);
                if (RELU) v = fmaxf(v, 0.f);
                C[(size_t)r * N + c0 + 1] = v;
            }
        }
    }
}

// ----------------------------------------------------------------------------
// Attention scores: S[bh,m,n] = 0.125 * sum_d Q[m,d] K[n,d]
// ----------------------------------------------------------------------------
__global__ __launch_bounds__(256)
void attn_scores(const float* __restrict__ qkv, float* __restrict__ S)
{
    __shared__ float Qt[32][133];
    __shared__ float Kt[32][133];
    int bh = blockIdx.x;
    int b = bh / HH, h = bh % HH;
    const float* base = qkv + (size_t)b * MM * (3 * DD) + h * HD;
    int t = threadIdx.x, tx = t & 15, ty = t >> 4;
    float acc[8][8];
    #pragma unroll
    for (int i = 0; i < 8; i++)
        #pragma unroll
        for (int j = 0; j < 8; j++) acc[i][j] = 0.f;

    for (int d0 = 0; d0 < HD; d0 += 32) {
        #pragma unroll
        for (int i = 0; i < 16; i++) {
            int e = t + 256 * i;       // 4096 elems
            int d = e & 31, m = e >> 5;
            Qt[d][m] = base[(size_t)m * (3 * DD) + d0 + d];
            Kt[d][m] = base[(size_t)m * (3 * DD) + DD + d0 + d];
        }
        __syncthreads();
        #pragma unroll
        for (int d = 0; d < 32; d++) {
            float a[8], bb[8];
            #pragma unroll
            for (int i = 0; i < 8; i++) a[i]  = Qt[d][ty * 8 + i];
            #pragma unroll
            for (int j = 0; j < 8; j++) bb[j] = Kt[d][tx * 8 + j];
            #pragma unroll
            for (int i = 0; i < 8; i++)
                #pragma unroll
                for (int j = 0; j < 8; j++)
                    acc[i][j] += a[i] * bb[j];
        }
        __syncthreads();
    }
    float* Sp = S + (size_t)bh * MM * MM;
    #pragma unroll
    for (int i = 0; i < 8; i++)
        #pragma unroll
        for (int j = 0; j < 8; j++)
            Sp[(size_t)(ty * 8 + i) * MM + tx * 8 + j] = acc[i][j] * 0.125f;
}

// ----------------------------------------------------------------------------
// Row softmax over 128 columns.
// ----------------------------------------------------------------------------
__global__ void attn_softmax(float* __restrict__ S)
{
    float* p = S + (size_t)blockIdx.x * MM;
    int t = threadIdx.x;                 // 128
    float v = p[t];
    __shared__ float red[4];
    float mx = v;
    #pragma unroll
    for (int o = 16; o; o >>= 1) mx = fmaxf(mx, __shfl_xor_sync(~0u, mx, o));
    if ((t & 31) == 0) red[t >> 5] = mx;
    __syncthreads();
    mx = fmaxf(fmaxf(red[0], red[1]), fmaxf(red[2], red[3]));
    float e = expf(v - mx);
    float s = e;
    #pragma unroll
    for (int o = 16; o; o >>= 1) s += __shfl_xor_sync(~0u, s, o);
    __syncthreads();
    if ((t & 31) == 0) red[t >> 5] = s;
    __syncthreads();
    s = red[0] + red[1] + red[2] + red[3];
    p[t] = e / s;
}

// ----------------------------------------------------------------------------
// P @ V
// ----------------------------------------------------------------------------
__global__ __launch_bounds__(256)
void attn_pv(const float* __restrict__ qkv, const float* __restrict__ S,
             float* __restrict__ ao)
{
    __shared__ float Ps[128][33];
    __shared__ float Vs[32][68];
    int bh = blockIdx.x;
    int b = bh / HH, h = bh % HH;
    const float* Sp = S + (size_t)bh * MM * MM;
    const float* Vb = qkv + (size_t)b * MM * (3 * DD) + 2 * DD + h * HD;
    int t = threadIdx.x, tx = t & 15, ty = t >> 4;
    float acc[8][4];
    #pragma unroll
    for (int i = 0; i < 8; i++)
        #pragma unroll
        for (int j = 0; j < 4; j++) acc[i][j] = 0.f;

    for (int n0 = 0; n0 < MM; n0 += 32) {
        #pragma unroll
        for (int i = 0; i < 16; i++) {
            int e = t + 256 * i;       // 4096 = 128m x 32n
            int n = e & 31, m = e >> 5;
            Ps[m][n] = Sp[(size_t)m * MM + n0 + n];
        }
        #pragma unroll
        for (int i = 0; i < 8; i++) {
            int e = t + 256 * i;       // 2048 = 32n x 64d
            int d = e & 63, n = e >> 6;
            Vs[n][d] = Vb[(size_t)(n0 + n) * (3 * DD) + d];
        }
        __syncthreads();
        #pragma unroll
        for (int n = 0; n < 32; n++) {
            float a[8], bb[4];
            #pragma unroll
            for (int i = 0; i < 8; i++) a[i]  = Ps[ty * 8 + i][n];
            #pragma unroll
            for (int j = 0; j < 4; j++) bb[j] = Vs[n][tx * 4 + j];
            #pragma unroll
            for (int i = 0; i < 8; i++)
                #pragma unroll
                for (int j = 0; j < 4; j++)
                    acc[i][j] += a[i] * bb[j];
        }
        __syncthreads();
    }
    float* aop = ao + (size_t)b * MM * DD + h * HD;
    #pragma unroll
    for (int i = 0; i < 8; i++)
        #pragma unroll
        for (int j = 0; j < 4; j++)
            aop[(size_t)(ty * 8 + i) * DD + tx * 4 + j] = acc[i][j];
}

// ----------------------------------------------------------------------------
// x = LayerNorm(x + delta) * w + b
// ----------------------------------------------------------------------------
__global__ __launch_bounds__(256)
void add_ln_kernel(float* __restrict__ x, const float* __restrict__ d,
                   const float* __restrict__ w, const float* __restrict__ b)
{
    int row = blockIdx.x, t = threadIdx.x;
    float* xp = x + (size_t)row * DD;
    const float* dp = d + (size_t)row * DD;
    float v0 = xp[t]       + dp[t];
    float v1 = xp[t + 256] + dp[t + 256];
    float v2 = xp[t + 512] + dp[t + 512];
    float s = v0 + v1 + v2;
    __shared__ float red[8];
    #pragma unroll
    for (int o = 16; o; o >>= 1) s += __shfl_xor_sync(~0u, s, o);
    if ((t & 31) == 0) red[t >> 5] = s;
    __syncthreads();
    float tot = red[0] + red[1] + red[2] + red[3] + red[4] + red[5] + red[6] + red[7];
    float mu = tot * (1.f / 768.f);
    float d0 = v0 - mu, d1 = v1 - mu, d2 = v2 - mu;
    float q = d0 * d0 + d1 * d1 + d2 * d2;
    #pragma unroll
    for (int o = 16; o; o >>= 1) q += __shfl_xor_sync(~0u, q, o);
    __syncthreads();
    if ((t & 31) == 0) red[t >> 5] = q;
    __syncthreads();
    float qt = red[0] + red[1] + red[2] + red[3] + red[4] + red[5] + red[6] + red[7];
    float inv = rsqrtf(qt * (1.f / 768.f) + 1e-5f);
    xp[t]       = d0 * inv * w[t]       + b[t];
    xp[t + 256] = d1 * inv * w[t + 256] + b[t + 256];
    xp[t + 512] = d2 * inv * w[t + 512] + b[t + 512];
}

// ----------------------------------------------------------------------------
// Host-side launch
// ----------------------------------------------------------------------------
static float* sym(const void* s)
{
    void* p = nullptr;
    cudaGetSymbolAddress(&p, s);
    return (float*)p;
}

extern "C" void kernel_launch(void* const* d_in, const int* in_sizes, int n_in,
                              void* d_out, int out_size)
{
    static const long long want[20] = {
        6291456LL, 65536LL, 2048LL, 768LL, 1LL,
        7077888LL, 9216LL, 2359296LL, 3072LL, 3072LL, 3072LL,
        9437184LL, 12288LL, 9437184LL, 3072LL, 3072LL, 3072LL,
        76800LL, 5000000LL, 50000LL
    };
    const void* slot[20];
    bool used[64];
    for (int i = 0; i < 20; i++) slot[i] = nullptr;
    for (int i = 0; i < n_in && i < 64; i++) used[i] = false;
    for (int w = 0; w < 20; w++) {
        for (int i = 0; i < n_in && i < 64; i++) {
            if (!used[i] && (long long)in_sizes[i] == want[w]) {
                slot[w] = d_in[i];
                used[i] = true;
                break;
            }
        }
    }
    if (!slot[0]) {
        for (int w = 0; w < 20 && w < n_in; w++) slot[w] = d_in[w];
    }

    const float* lhs    = (const float*)slot[0];
    const int*   pos    = (const int*)slot[1];
    const int*   mask   = (const int*)slot[2];
    const float* attn_w = (const float*)slot[3];
    const float* qkv_w  = (const float*)slot[5];
    const float* qkv_b  = (const float*)slot[6];
    const float* out_w  = (const float*)slot[7];
    const float* out_b  = (const float*)slot[8];
    const float* ln1_w  = (const float*)slot[9];
    const float* ln1_b  = (const float*)slot[10];
    const float* ff1_w  = (const float*)slot[11];
    const float* ff1_b  = (const float*)slot[12];
    const float* ff2_w  = (const float*)slot[13];
    const float* ff2_b  = (const float*)slot[14];
    const float* ln2_w  = (const float*)slot[15];
    const float* ln2_b  = (const float*)slot[16];
    const float* cls_w1 = (const float*)slot[17];
    const float* cls_w2 = (const float*)slot[18];
    const float* cls_b2 = (const float*)slot[19];
    float* out = (float*)d_out;

    float* hl  = sym(g_hl);
    float* x   = sym(g_x);
    float* qkv = sym(g_qkv);
    float* s   = sym(g_s);
    float* ao  = sym(g_ao);
    float* tmp = sym(g_tmp);
    float* y   = sym(g_y);

    // mention pooling
    hl_kernel<<<BB * LL, 256>>>(lhs, attn_w, hl);
    pool_kernel<<<ROWS, 256>>>(lhs, pos, mask, hl, x);

    // transformer layers
    for (int i = 0; i < NL; i++) {
        gemm_nt<128, 0><<<dim3(3 * DD / 128, ROWS / 128), 256>>>(
            x, qkv_w + (size_t)i * 3 * DD * DD, qkv_b + (size_t)i * 3 * DD,
            qkv, ROWS, 3 * DD, DD);
        attn_scores<<<BB * HH, 256>>>(qkv, s);
        attn_softmax<<<BB * HH * MM, 128>>>(s);
        attn_pv<<<BB * HH, 256>>>(qkv, s, ao);
        gemm_nt<64, 0><<<dim3(DD / 128, ROWS / 64), 256>>>(
            ao, out_w + (size_t)i * DD * DD, out_b + (size_t)i * DD,
            tmp, ROWS, DD, DD);
        add_ln_kernel<<<ROWS, 256>>>(x, tmp, ln1_w + (size_t)i * DD, ln1_b + (size_t)i * DD);
        gemm_nt<128, 1><<<dim3(DFF / 128, ROWS / 128), 256>>>(
            x, ff1_w + (size_t)i * DFF * DD, ff1_b + (size_t)i * DFF,
            tmp, ROWS, DFF, DD);
        gemm_nt<64, 0><<<dim3(DD / 128, ROWS / 64), 256>>>(
            tmp, ff2_w + (size_t)i * DD * DFF, ff2_b + (size_t)i * DD,
            ao, ROWS, DD, DFF);
        add_ln_kernel<<<ROWS, 256>>>(x, ao, ln2_w + (size_t)i * DD, ln2_b + (size_t)i * DD);
    }

    // classifier head
    gemm_nt<64, 0><<<dim3(1, ROWS / 64), 256>>>(x, cls_w1, nullptr, y, ROWS, 100, DD);
    gemm_nt<128, 0><<<dim3((NE + 127) / 128, ROWS / 128), 256>>>(
        y, cls_w2, cls_b2, out, ROWS, NE, 100);
}

// round 4
// speedup vs baseline: 2.1944x; 2.0702x over previous
#include <cuda_runtime.h>
#include <cuda_bf16.h>
#include <math.h>

// ----------------------------------------------------------------------------
// Problem constants
// ----------------------------------------------------------------------------
#define BB   16
#define MM   128
#define LL   32
#define SS   512
#define DD   768
#define HH   12
#define HD   64
#define DFF  3072
#define NL   4
#define NE   50000
#define ROWS (BB*MM)          // 2048

typedef unsigned long long ull;
typedef unsigned int u32;
typedef __nv_bfloat16 bf16;

// weight scratch offsets (elements)
#define OW_QKV  0ULL
#define OW_OUT  7077888ULL
#define OW_FF1  9437184ULL
#define OW_FF2  18874368ULL
#define OW_CLS1 28311552ULL
#define OW_CLS2 28388352ULL
#define NW_TOT  33388352ULL

// ----------------------------------------------------------------------------
// Device scratch (static allocation — no cudaMalloc allowed)
// ----------------------------------------------------------------------------
__device__ float g_hl[BB*LL];
__device__ float g_x [ROWS*DD];
__device__ float g_qkv[ROWS*3*DD];
__device__ float g_s [BB*HH*MM*MM];
__device__ float g_ao[ROWS*DD];
__device__ float g_tmp[ROWS*DFF];
__device__ float g_y [ROWS*128];
__device__ bf16  g_wh[NW_TOT];
__device__ bf16  g_wl[NW_TOT];
__device__ bf16  g_ah[ROWS*DFF];
__device__ bf16  g_al[ROWS*DFF];

// ----------------------------------------------------------------------------
// fp32 -> bf16 hi/lo split
// ----------------------------------------------------------------------------
__global__ void cvt_kernel(const float* __restrict__ x,
                           bf16* __restrict__ h, bf16* __restrict__ l, int n)
{
    for (int i = blockIdx.x * 256 + threadIdx.x; i < n; i += gridDim.x * 256) {
        float v = x[i];
        bf16 hh = __float2bfloat16(v);
        h[i] = hh;
        l[i] = __float2bfloat16(v - __bfloat162float(hh));
    }
}

// ----------------------------------------------------------------------------
// hl[b,l] = dot(hidden[b,l,:], attn_w)
// ----------------------------------------------------------------------------
__global__ void hl_kernel(const float* __restrict__ lhs,
                          const float* __restrict__ aw,
                          float* __restrict__ hl)
{
    int blk = blockIdx.x;
    int b = blk >> 5, l = blk & 31;
    const float* row = lhs + ((size_t)b * SS + l) * DD;
    int t = threadIdx.x;
    float p = 0.f;
    for (int i = t; i < DD; i += 256) p += row[i] * aw[i];
    #pragma unroll
    for (int o = 16; o; o >>= 1) p += __shfl_xor_sync(~0u, p, o);
    __shared__ float red[8];
    if ((t & 31) == 0) red[t >> 5] = p;
    __syncthreads();
    if (t == 0) {
        float s = 0.f;
        #pragma unroll
        for (int i = 0; i < 8; i++) s += red[i];
        hl[b * LL + l] = s;
    }
}

// ----------------------------------------------------------------------------
// Mention pooling (pos/mask int32)
// ----------------------------------------------------------------------------
__global__ void pool_kernel(const float* __restrict__ lhs,
                            const int* __restrict__ pos,
                            const int* __restrict__ mask,
                            const float* __restrict__ hl,
                            float* __restrict__ x)
{
    int bm = blockIdx.x;
    int b = bm >> 7;
    int t = threadIdx.x;
    __shared__ float ws[LL];
    __shared__ int s_nv;
    if (t < 32) {
        int p = pos[(size_t)bm * LL + t];
        unsigned bits = __ballot_sync(0xffffffffu, p != -1);
        int nv;
        if (mask[bm] == 0) nv = 0;
        else if (~bits == 0u) nv = 32;
        else nv = __ffs(~bits) - 1;
        float logit = (t < nv) ? hl[b * LL + t] : 0.f;
        float mx = logit;
        #pragma unroll
        for (int o = 16; o; o >>= 1) mx = fmaxf(mx, __shfl_xor_sync(~0u, mx, o));
        float e = expf(logit - mx);
        float s = e;
        #pragma unroll
        for (int o = 16; o; o >>= 1) s += __shfl_xor_sync(~0u, s, o);
        ws[t] = e / s;
        if (t == 0) s_nv = nv;
    }
    __syncthreads();
    int nv = s_nv;
    for (int d = t; d < DD; d += 256) {
        float acc = 0.f;
        for (int l = 0; l < nv; l++)
            acc += ws[l] * lhs[((size_t)b * SS + l) * DD + d];
        x[(size_t)bm * DD + d] = acc;
    }
}

// ----------------------------------------------------------------------------
// Tensor-core split-bf16 NT GEMM: C[M,N] = A*B^T (+bias, opt relu)
// A,B given as bf16 (hi,lo) pairs; product = AhBh + AhBl + AlBh, fp32 accum.
// 128x128 tile, BK=32, 8 warps (4m x 2n), warp tile 32x64, mma m16n8k16.
// M % 128 == 0; N, K guarded (K % 4 == 0).
// ----------------------------------------------------------------------------
__device__ __forceinline__ void mma_bf16(float* d, const u32* a, u32 b0, u32 b1)
{
    asm volatile(
        "mma.sync.aligned.m16n8k16.row.col.f32.bf16.bf16.f32 "
        "{%0,%1,%2,%3},{%4,%5,%6,%7},{%8,%9},{%0,%1,%2,%3};"
        : "+f"(d[0]), "+f"(d[1]), "+f"(d[2]), "+f"(d[3])
        : "r"(a[0]), "r"(a[1]), "r"(a[2]), "r"(a[3]), "r"(b0), "r"(b1));
}

template<int RELU>
__global__ __launch_bounds__(256)
void gemm_bf16(const bf16* __restrict__ Ah, const bf16* __restrict__ Al,
               const bf16* __restrict__ Bh, const bf16* __restrict__ Bl,
               const float* __restrict__ bias, float* __restrict__ C,
               int M, int N, int K)
{
    constexpr int LDS = 36;             // padded row stride (bf16), 72B: 8B-aligned
    __shared__ bf16 sAh[128 * LDS];
    __shared__ bf16 sAl[128 * LDS];
    __shared__ bf16 sBh[128 * LDS];
    __shared__ bf16 sBl[128 * LDS];

    const int t = threadIdx.x;
    const int mBase = blockIdx.y * 128;
    const int nBase = blockIdx.x * 128;
    const int lane = t & 31, warp = t >> 5;
    const int wm = (warp >> 1) * 32;    // warp m-offset within tile
    const int wn = (warp & 1) * 64;     // warp n-offset within tile
    const int g  = lane >> 2, tg = lane & 3;

    float acc[2][8][4];
    #pragma unroll
    for (int mi = 0; mi < 2; mi++)
        #pragma unroll
        for (int nj = 0; nj < 8; nj++)
            #pragma unroll
            for (int r = 0; r < 4; r++) acc[mi][nj][r] = 0.f;

    ull pAh[4], pAl[4], pBh[4], pBl[4];

    // slab prefetch: 128 rows x 32 cols bf16 per matrix; 4 ull chunks/thread
    auto loadSlab = [&](int k0) {
        #pragma unroll
        for (int p = 0; p < 4; p++) {
            int c = t + 256 * p;
            int row = c >> 3, col = (c & 7) * 4;
            int kk = k0 + col;
            bool kok = (kk + 4 <= K);
            pAh[p] = kok ? *(const ull*)(Ah + (size_t)(mBase + row) * K + kk) : 0ULL;
            pAl[p] = kok ? *(const ull*)(Al + (size_t)(mBase + row) * K + kk) : 0ULL;
            bool bok = kok && (nBase + row < N);
            pBh[p] = bok ? *(const ull*)(Bh + (size_t)(nBase + row) * K + kk) : 0ULL;
            pBl[p] = bok ? *(const ull*)(Bl + (size_t)(nBase + row) * K + kk) : 0ULL;
        }
    };

    loadSlab(0);

    for (int k0 = 0; k0 < K; k0 += 32) {
        // store current slab to smem
        #pragma unroll
        for (int p = 0; p < 4; p++) {
            int c = t + 256 * p;
            int row = c >> 3, col = (c & 7) * 4;
            *(ull*)&sAh[row * LDS + col] = pAh[p];
            *(ull*)&sAl[row * LDS + col] = pAl[p];
            *(ull*)&sBh[row * LDS + col] = pBh[p];
            *(ull*)&sBl[row * LDS + col] = pBl[p];
        }
        __syncthreads();

        if (k0 + 32 < K) loadSlab(k0 + 32);

        #pragma unroll
        for (int ks = 0; ks < 2; ks++) {
            const int kb = ks * 16 + 2 * tg;
            u32 ah[2][4], al[2][4];
            #pragma unroll
            for (int mi = 0; mi < 2; mi++) {
                int r0 = (wm + mi * 16 + g) * LDS;
                int r1 = r0 + 8 * LDS;
                ah[mi][0] = *(const u32*)&sAh[r0 + kb];
                ah[mi][1] = *(const u32*)&sAh[r1 + kb];
                ah[mi][2] = *(const u32*)&sAh[r0 + kb + 8];
                ah[mi][3] = *(const u32*)&sAh[r1 + kb + 8];
                al[mi][0] = *(const u32*)&sAl[r0 + kb];
                al[mi][1] = *(const u32*)&sAl[r1 + kb];
                al[mi][2] = *(const u32*)&sAl[r0 + kb + 8];
                al[mi][3] = *(const u32*)&sAl[r1 + kb + 8];
            }
            #pragma unroll
            for (int nj = 0; nj < 8; nj++) {
                int rb = (wn + nj * 8 + g) * LDS;
                u32 bh0 = *(const u32*)&sBh[rb + kb];
                u32 bh1 = *(const u32*)&sBh[rb + kb + 8];
                u32 bl0 = *(const u32*)&sBl[rb + kb];
                u32 bl1 = *(const u32*)&sBl[rb + kb + 8];
                #pragma unroll
                for (int mi = 0; mi < 2; mi++) {
                    mma_bf16(acc[mi][nj], ah[mi], bh0, bh1);
                    mma_bf16(acc[mi][nj], ah[mi], bl0, bl1);
                    mma_bf16(acc[mi][nj], al[mi], bh0, bh1);
                }
            }
        }
        __syncthreads();
    }

    // epilogue
    #pragma unroll
    for (int mi = 0; mi < 2; mi++) {
        int row0 = mBase + wm + mi * 16 + g;
        #pragma unroll
        for (int nj = 0; nj < 8; nj++) {
            int col0 = nBase + wn + nj * 8 + 2 * tg;
            if (col0 < N) {
                float bv = bias ? bias[col0] : 0.f;
                float v0 = acc[mi][nj][0] + bv;
                float v2 = acc[mi][nj][2] + bv;
                if (RELU) { v0 = fmaxf(v0, 0.f); v2 = fmaxf(v2, 0.f); }
                C[(size_t)row0 * N + col0] = v0;
                C[(size_t)(row0 + 8) * N + col0] = v2;
            }
            if (col0 + 1 < N) {
                float bv = bias ? bias[col0 + 1] : 0.f;
                float v1 = acc[mi][nj][1] + bv;
                float v3 = acc[mi][nj][3] + bv;
                if (RELU) { v1 = fmaxf(v1, 0.f); v3 = fmaxf(v3, 0.f); }
                C[(size_t)row0 * N + col0 + 1] = v1;
                C[(size_t)(row0 + 8) * N + col0 + 1] = v3;
            }
        }
    }
}

// ----------------------------------------------------------------------------
// Attention scores: S[bh,m,n] = 0.125 * sum_d Q[m,d] K[n,d]
// ----------------------------------------------------------------------------
__global__ __launch_bounds__(256)
void attn_scores(const float* __restrict__ qkv, float* __restrict__ S)
{
    __shared__ float Qt[32][133];
    __shared__ float Kt[32][133];
    int bh = blockIdx.x;
    int b = bh / HH, h = bh % HH;
    const float* base = qkv + (size_t)b * MM * (3 * DD) + h * HD;
    int t = threadIdx.x, tx = t & 15, ty = t >> 4;
    float acc[8][8];
    #pragma unroll
    for (int i = 0; i < 8; i++)
        #pragma unroll
        for (int j = 0; j < 8; j++) acc[i][j] = 0.f;

    for (int d0 = 0; d0 < HD; d0 += 32) {
        #pragma unroll
        for (int i = 0; i < 16; i++) {
            int e = t + 256 * i;
            int d = e & 31, m = e >> 5;
            Qt[d][m] = base[(size_t)m * (3 * DD) + d0 + d];
            Kt[d][m] = base[(size_t)m * (3 * DD) + DD + d0 + d];
        }
        __syncthreads();
        #pragma unroll
        for (int d = 0; d < 32; d++) {
            float a[8], bb[8];
            #pragma unroll
            for (int i = 0; i < 8; i++) a[i]  = Qt[d][ty * 8 + i];
            #pragma unroll
            for (int j = 0; j < 8; j++) bb[j] = Kt[d][tx * 8 + j];
            #pragma unroll
            for (int i = 0; i < 8; i++)
                #pragma unroll
                for (int j = 0; j < 8; j++)
                    acc[i][j] += a[i] * bb[j];
        }
        __syncthreads();
    }
    float* Sp = S + (size_t)bh * MM * MM;
    #pragma unroll
    for (int i = 0; i < 8; i++)
        #pragma unroll
        for (int j = 0; j < 8; j++)
            Sp[(size_t)(ty * 8 + i) * MM + tx * 8 + j] = acc[i][j] * 0.125f;
}

// ----------------------------------------------------------------------------
// Row softmax
// ----------------------------------------------------------------------------
__global__ void attn_softmax(float* __restrict__ S)
{
    float* p = S + (size_t)blockIdx.x * MM;
    int t = threadIdx.x;
    float v = p[t];
    __shared__ float red[4];
    float mx = v;
    #pragma unroll
    for (int o = 16; o; o >>= 1) mx = fmaxf(mx, __shfl_xor_sync(~0u, mx, o));
    if ((t & 31) == 0) red[t >> 5] = mx;
    __syncthreads();
    mx = fmaxf(fmaxf(red[0], red[1]), fmaxf(red[2], red[3]));
    float e = expf(v - mx);
    float s = e;
    #pragma unroll
    for (int o = 16; o; o >>= 1) s += __shfl_xor_sync(~0u, s, o);
    __syncthreads();
    if ((t & 31) == 0) red[t >> 5] = s;
    __syncthreads();
    s = red[0] + red[1] + red[2] + red[3];
    p[t] = e / s;
}

// ----------------------------------------------------------------------------
// P @ V
// ----------------------------------------------------------------------------
__global__ __launch_bounds__(256)
void attn_pv(const float* __restrict__ qkv, const float* __restrict__ S,
             float* __restrict__ ao)
{
    __shared__ float Ps[128][33];
    __shared__ float Vs[32][68];
    int bh = blockIdx.x;
    int b = bh / HH, h = bh % HH;
    const float* Sp = S + (size_t)bh * MM * MM;
    const float* Vb = qkv + (size_t)b * MM * (3 * DD) + 2 * DD + h * HD;
    int t = threadIdx.x, tx = t & 15, ty = t >> 4;
    float acc[8][4];
    #pragma unroll
    for (int i = 0; i < 8; i++)
        #pragma unroll
        for (int j = 0; j < 4; j++) acc[i][j] = 0.f;

    for (int n0 = 0; n0 < MM; n0 += 32) {
        #pragma unroll
        for (int i = 0; i < 16; i++) {
            int e = t + 256 * i;
            int n = e & 31, m = e >> 5;
            Ps[m][n] = Sp[(size_t)m * MM + n0 + n];
        }
        #pragma unroll
        for (int i = 0; i < 8; i++) {
            int e = t + 256 * i;
            int d = e & 63, n = e >> 6;
            Vs[n][d] = Vb[(size_t)(n0 + n) * (3 * DD) + d];
        }
        __syncthreads();
        #pragma unroll
        for (int n = 0; n < 32; n++) {
            float a[8], bb[4];
            #pragma unroll
            for (int i = 0; i < 8; i++) a[i]  = Ps[ty * 8 + i][n];
            #pragma unroll
            for (int j = 0; j < 4; j++) bb[j] = Vs[n][tx * 4 + j];
            #pragma unroll
            for (int i = 0; i < 8; i++)
                #pragma unroll
                for (int j = 0; j < 4; j++)
                    acc[i][j] += a[i] * bb[j];
        }
        __syncthreads();
    }
    float* aop = ao + (size_t)b * MM * DD + h * HD;
    #pragma unroll
    for (int i = 0; i < 8; i++)
        #pragma unroll
        for (int j = 0; j < 4; j++)
            aop[(size_t)(ty * 8 + i) * DD + tx * 4 + j] = acc[i][j];
}

// ----------------------------------------------------------------------------
// x = LayerNorm(x + delta) * w + b
// ----------------------------------------------------------------------------
__global__ __launch_bounds__(256)
void add_ln_kernel(float* __restrict__ x, const float* __restrict__ d,
                   const float* __restrict__ w, const float* __restrict__ b)
{
    int row = blockIdx.x, t = threadIdx.x;
    float* xp = x + (size_t)row * DD;
    const float* dp = d + (size_t)row * DD;
    float v0 = xp[t]       + dp[t];
    float v1 = xp[t + 256] + dp[t + 256];
    float v2 = xp[t + 512] + dp[t + 512];
    float s = v0 + v1 + v2;
    __shared__ float red[8];
    #pragma unroll
    for (int o = 16; o; o >>= 1) s += __shfl_xor_sync(~0u, s, o);
    if ((t & 31) == 0) red[t >> 5] = s;
    __syncthreads();
    float tot = red[0] + red[1] + red[2] + red[3] + red[4] + red[5] + red[6] + red[7];
    float mu = tot * (1.f / 768.f);
    float d0 = v0 - mu, d1 = v1 - mu, d2 = v2 - mu;
    float q = d0 * d0 + d1 * d1 + d2 * d2;
    #pragma unroll
    for (int o = 16; o; o >>= 1) q += __shfl_xor_sync(~0u, q, o);
    __syncthreads();
    if ((t & 31) == 0) red[t >> 5] = q;
    __syncthreads();
    float qt = red[0] + red[1] + red[2] + red[3] + red[4] + red[5] + red[6] + red[7];
    float inv = rsqrtf(qt * (1.f / 768.f) + 1e-5f);
    xp[t]       = d0 * inv * w[t]       + b[t];
    xp[t + 256] = d1 * inv * w[t + 256] + b[t + 256];
    xp[t + 512] = d2 * inv * w[t + 512] + b[t + 512];
}

// ----------------------------------------------------------------------------
// Host-side launch
// ----------------------------------------------------------------------------
template<typename T>
static T* sym(const void* s)
{
    void* p = nullptr;
    cudaGetSymbolAddress(&p, s);
    return (T*)p;
}

extern "C" void kernel_launch(void* const* d_in, const int* in_sizes, int n_in,
                              void* d_out, int out_size)
{
    static const long long want[20] = {
        6291456LL, 65536LL, 2048LL, 768LL, 1LL,
        7077888LL, 9216LL, 2359296LL, 3072LL, 3072LL, 3072LL,
        9437184LL, 12288LL, 9437184LL, 3072LL, 3072LL, 3072LL,
        76800LL, 5000000LL, 50000LL
    };
    const void* slot[20];
    bool used[64];
    for (int i = 0; i < 20; i++) slot[i] = nullptr;
    for (int i = 0; i < n_in && i < 64; i++) used[i] = false;
    for (int w = 0; w < 20; w++) {
        for (int i = 0; i < n_in && i < 64; i++) {
            if (!used[i] && (long long)in_sizes[i] == want[w]) {
                slot[w] = d_in[i];
                used[i] = true;
                break;
            }
        }
    }
    if (!slot[0]) {
        for (int w = 0; w < 20 && w < n_in; w++) slot[w] = d_in[w];
    }

    const float* lhs    = (const float*)slot[0];
    const int*   pos    = (const int*)slot[1];
    const int*   mask   = (const int*)slot[2];
    const float* attn_w = (const float*)slot[3];
    const float* qkv_w  = (const float*)slot[5];
    const float* qkv_b  = (const float*)slot[6];
    const float* out_w  = (const float*)slot[7];
    const float* out_b  = (const float*)slot[8];
    const float* ln1_w  = (const float*)slot[9];
    const float* ln1_b  = (const float*)slot[10];
    const float* ff1_w  = (const float*)slot[11];
    const float* ff1_b  = (const float*)slot[12];
    const float* ff2_w  = (const float*)slot[13];
    const float* ff2_b  = (const float*)slot[14];
    const float* ln2_w  = (const float*)slot[15];
    const float* ln2_b  = (const float*)slot[16];
    const float* cls_w1 = (const float*)slot[17];
    const float* cls_w2 = (const float*)slot[18];
    const float* cls_b2 = (const float*)slot[19];
    float* out = (float*)d_out;

    float* hl  = sym<float>(g_hl);
    float* x   = sym<float>(g_x);
    float* qkv = sym<float>(g_qkv);
    float* s   = sym<float>(g_s);
    float* ao  = sym<float>(g_ao);
    float* tmp = sym<float>(g_tmp);
    float* y   = sym<float>(g_y);
    bf16*  wh  = sym<bf16>(g_wh);
    bf16*  wl  = sym<bf16>(g_wl);
    bf16*  ah  = sym<bf16>(g_ah);
    bf16*  al  = sym<bf16>(g_al);

    // --- weight conversion (every launch; deterministic) ---
    cvt_kernel<<<4096, 256>>>(qkv_w,  wh + OW_QKV,  wl + OW_QKV,  7077888);
    cvt_kernel<<<2048, 256>>>(out_w,  wh + OW_OUT,  wl + OW_OUT,  2359296);
    cvt_kernel<<<4096, 256>>>(ff1_w,  wh + OW_FF1,  wl + OW_FF1,  9437184);
    cvt_kernel<<<4096, 256>>>(ff2_w,  wh + OW_FF2,  wl + OW_FF2,  9437184);
    cvt_kernel<<<128,  256>>>(cls_w1, wh + OW_CLS1, wl + OW_CLS1, 76800);
    cvt_kernel<<<4096, 256>>>(cls_w2, wh + OW_CLS2, wl + OW_CLS2, 5000000);

    // --- mention pooling ---
    hl_kernel<<<BB * LL, 256>>>(lhs, attn_w, hl);
    pool_kernel<<<ROWS, 256>>>(lhs, pos, mask, hl, x);

    // --- transformer layers ---
    for (int i = 0; i < NL; i++) {
        cvt_kernel<<<1024, 256>>>(x, ah, al, ROWS * DD);
        gemm_bf16<0><<<dim3(3 * DD / 128, ROWS / 128), 256>>>(
            ah, al, wh + OW_QKV + (size_t)i * 3 * DD * DD,
            wl + OW_QKV + (size_t)i * 3 * DD * DD,
            qkv_b + (size_t)i * 3 * DD, qkv, ROWS, 3 * DD, DD);
        attn_scores<<<BB * HH, 256>>>(qkv, s);
        attn_softmax<<<BB * HH * MM, 128>>>(s);
        attn_pv<<<BB * HH, 256>>>(qkv, s, ao);
        cvt_kernel<<<1024, 256>>>(ao, ah, al, ROWS * DD);
        gemm_bf16<0><<<dim3(DD / 128, ROWS / 128), 256>>>(
            ah, al, wh + OW_OUT + (size_t)i * DD * DD,
            wl + OW_OUT + (size_t)i * DD * DD,
            out_b + (size_t)i * DD, tmp, ROWS, DD, DD);
        add_ln_kernel<<<ROWS, 256>>>(x, tmp, ln1_w + (size_t)i * DD, ln1_b + (size_t)i * DD);
        cvt_kernel<<<1024, 256>>>(x, ah, al, ROWS * DD);
        gemm_bf16<1><<<dim3(DFF / 128, ROWS / 128), 256>>>(
            ah, al, wh + OW_FF1 + (size_t)i * DFF * DD,
            wl + OW_FF1 + (size_t)i * DFF * DD,
            ff1_b + (size_t)i * DFF, tmp, ROWS, DFF, DD);
        cvt_kernel<<<2048, 256>>>(tmp, ah, al, ROWS * DFF);
        gemm_bf16<0><<<dim3(DD / 128, ROWS / 128), 256>>>(
            ah, al, wh + OW_FF2 + (size_t)i * DD * DFF,
            wl + OW_FF2 + (size_t)i * DD * DFF,
            ff2_b + (size_t)i * DD, ao, ROWS, DD, DFF);
        add_ln_kernel<<<ROWS, 256>>>(x, ao, ln2_w + (size_t)i * DD, ln2_b + (size_t)i * DD);
    }

    // --- classifier head ---
    cvt_kernel<<<1024, 256>>>(x, ah, al, ROWS * DD);
    gemm_bf16<0><<<dim3(1, ROWS / 128), 256>>>(
        ah, al, wh + OW_CLS1, wl + OW_CLS1, nullptr, y, ROWS, 100, DD);
    cvt_kernel<<<256, 256>>>(y, ah, al, ROWS * 100);
    gemm_bf16<0><<<dim3((NE + 127) / 128, ROWS / 128), 256>>>(
        ah, al, wh + OW_CLS2, wl + OW_CLS2, cls_b2, out, ROWS, NE, 100);
}

// round 6
// speedup vs baseline: 3.2515x; 1.4817x over previous
#include <cuda_runtime.h>
#include <cuda_bf16.h>
#include <math.h>
#include <cstdint>

// ----------------------------------------------------------------------------
// Problem constants
// ----------------------------------------------------------------------------
#define BB   16
#define MM   128
#define LL   32
#define SS   512
#define DD   768
#define HH   12
#define HD   64
#define DFF  3072
#define NL   4
#define NE   50000
#define ROWS (BB*MM)          // 2048
#define KPAD 112              // padded K for classifier stage 2 (16B-aligned rows)

typedef unsigned long long ull;
typedef unsigned int u32;
typedef __nv_bfloat16 bf16;

// weight scratch offsets (elements)
#define OW_QKV  0ULL
#define OW_OUT  7077888ULL
#define OW_FF1  9437184ULL
#define OW_FF2  18874368ULL
#define OW_CLS1 28311552ULL
#define OW_CLS2 28388352ULL
#define NW_TOT  (28388352ULL + 50000ULL*KPAD)

// ----------------------------------------------------------------------------
// Device scratch (static allocation — no cudaMalloc allowed)
// ----------------------------------------------------------------------------
__device__ float g_hl[BB*LL];
__device__ float g_x [ROWS*DD];
__device__ float g_qkv[ROWS*3*DD];
__device__ float g_s [BB*HH*MM*MM];
__device__ float g_tmp[ROWS*DFF];
__device__ __align__(256) bf16 g_wh[NW_TOT];
__device__ __align__(256) bf16 g_wl[NW_TOT];
__device__ __align__(256) bf16 g_ah[ROWS*DFF];
__device__ __align__(256) bf16 g_al[ROWS*DFF];
__device__ __align__(256) bf16 g_bh[ROWS*DFF];
__device__ __align__(256) bf16 g_bl[ROWS*DFF];

// ----------------------------------------------------------------------------
// PTX helpers
// ----------------------------------------------------------------------------
__device__ __forceinline__ u32 smem_u32(const void* p)
{
    u32 a;
    asm("{ .reg .u64 t; cvta.to.shared.u64 t, %1; cvt.u32.u64 %0, t; }"
        : "=r"(a) : "l"(p));
    return a;
}

__device__ __forceinline__ void cp_async16(u32 dst, const void* src, int sz)
{
    asm volatile("cp.async.cg.shared.global [%0], [%1], 16, %2;"
        :: "r"(dst), "l"(src), "r"(sz));
}
#define CP_COMMIT() asm volatile("cp.async.commit_group;" ::: "memory")
#define CP_WAIT1()  asm volatile("cp.async.wait_group 1;" ::: "memory")
#define CP_WAIT0()  asm volatile("cp.async.wait_group 0;" ::: "memory")

__device__ __forceinline__ void ldsm4(u32 addr, u32& r0, u32& r1, u32& r2, u32& r3)
{
    asm volatile("ldmatrix.sync.aligned.m8n8.x4.shared.b16 {%0,%1,%2,%3}, [%4];"
        : "=r"(r0), "=r"(r1), "=r"(r2), "=r"(r3) : "r"(addr));
}

__device__ __forceinline__ void mma_bf16(float* d, const u32* a, u32 b0, u32 b1)
{
    asm volatile(
        "mma.sync.aligned.m16n8k16.row.col.f32.bf16.bf16.f32 "
        "{%0,%1,%2,%3},{%4,%5,%6,%7},{%8,%9},{%0,%1,%2,%3};"
        : "+f"(d[0]), "+f"(d[1]), "+f"(d[2]), "+f"(d[3])
        : "r"(a[0]), "r"(a[1]), "r"(a[2]), "r"(a[3]), "r"(b0), "r"(b1));
}

__device__ __forceinline__ void split_write(bf16* h, bf16* l, size_t idx, float v)
{
    bf16 hh = __float2bfloat16(v);
    h[idx] = hh;
    l[idx] = __float2bfloat16(v - __bfloat162float(hh));
}

// ----------------------------------------------------------------------------
// weight fp32 -> bf16 hi/lo split
// ----------------------------------------------------------------------------
__global__ void cvt_kernel(const float* __restrict__ x,
                           bf16* __restrict__ h, bf16* __restrict__ l, int n)
{
    for (int i = blockIdx.x * 256 + threadIdx.x; i < n; i += gridDim.x * 256) {
        float v = x[i];
        split_write(h, l, i, v);
    }
}

// padded variant for cls_w2: [rows,100] -> [rows,112] zero-padded
__global__ void cvt_pad_kernel(const float* __restrict__ x,
                               bf16* __restrict__ h, bf16* __restrict__ l,
                               int rows, int kin)
{
    int n = rows * KPAD;
    for (int i = blockIdx.x * 256 + threadIdx.x; i < n; i += gridDim.x * 256) {
        int r = i / KPAD, c = i - r * KPAD;
        float v = (c < kin) ? x[(size_t)r * kin + c] : 0.f;
        split_write(h, l, i, v);
    }
}

// ----------------------------------------------------------------------------
// hl[b,l] = dot(hidden[b,l,:], attn_w)
// ----------------------------------------------------------------------------
__global__ void hl_kernel(const float* __restrict__ lhs,
                          const float* __restrict__ aw,
                          float* __restrict__ hl)
{
    int blk = blockIdx.x;
    int b = blk >> 5, l = blk & 31;
    const float* row = lhs + ((size_t)b * SS + l) * DD;
    int t = threadIdx.x;
    float p = 0.f;
    for (int i = t; i < DD; i += 256) p += row[i] * aw[i];
    #pragma unroll
    for (int o = 16; o; o >>= 1) p += __shfl_xor_sync(~0u, p, o);
    __shared__ float red[8];
    if ((t & 31) == 0) red[t >> 5] = p;
    __syncthreads();
    if (t == 0) {
        float s = 0.f;
        #pragma unroll
        for (int i = 0; i < 8; i++) s += red[i];
        hl[b * LL + l] = s;
    }
}

// ----------------------------------------------------------------------------
// Mention pooling (pos/mask int32). Writes x fp32 + bf16 split.
// ----------------------------------------------------------------------------
__global__ void pool_kernel(const float* __restrict__ lhs,
                            const int* __restrict__ pos,
                            const int* __restrict__ mask,
                            const float* __restrict__ hl,
                            float* __restrict__ x,
                            bf16* __restrict__ xh, bf16* __restrict__ xl)
{
    int bm = blockIdx.x;
    int b = bm >> 7;
    int t = threadIdx.x;
    __shared__ float ws[LL];
    __shared__ int s_nv;
    if (t < 32) {
        int p = pos[(size_t)bm * LL + t];
        unsigned bits = __ballot_sync(0xffffffffu, p != -1);
        int nv;
        if (mask[bm] == 0) nv = 0;
        else if (~bits == 0u) nv = 32;
        else nv = __ffs(~bits) - 1;
        float logit = (t < nv) ? hl[b * LL + t] : 0.f;
        float mx = logit;
        #pragma unroll
        for (int o = 16; o; o >>= 1) mx = fmaxf(mx, __shfl_xor_sync(~0u, mx, o));
        float e = expf(logit - mx);
        float s = e;
        #pragma unroll
        for (int o = 16; o; o >>= 1) s += __shfl_xor_sync(~0u, s, o);
        ws[t] = e / s;
        if (t == 0) s_nv = nv;
    }
    __syncthreads();
    int nv = s_nv;
    for (int d = t; d < DD; d += 256) {
        float acc = 0.f;
        for (int l = 0; l < nv; l++)
            acc += ws[l] * lhs[((size_t)b * SS + l) * DD + d];
        size_t idx = (size_t)bm * DD + d;
        x[idx] = acc;
        split_write(xh, xl, idx, acc);
    }
}

// ----------------------------------------------------------------------------
// Tensor-core split-bf16 NT GEMM via mma.sync + ldmatrix + cp.async pipeline.
// C[M,N] = A*B^T (+bias, opt relu). A,B as bf16 (hi,lo) pairs.
// CTA tile 128 x TN, BK=32 bf16 (64B rows), XOR-swizzled smem, double buffer.
// 8 warps: 4m x 2n, warp tile 32 x TN/2. M%128==0.
// Output: SPLIT=0 -> fp32 C (ldout); SPLIT=1 -> bf16 hi/lo (ldout), cols
// [N,padN) zero-filled.
// ----------------------------------------------------------------------------
template<int TN, int RELU, int SPLIT>
__global__ __launch_bounds__(256)
void gemm_tc(const bf16* __restrict__ Ah, const bf16* __restrict__ Al,
             const bf16* __restrict__ Bh, const bf16* __restrict__ Bl,
             const float* __restrict__ bias,
             float* __restrict__ C, bf16* __restrict__ Ch, bf16* __restrict__ Cl,
             int M, int N, int K, int ldout, int padN)
{
    constexpr int NJW = TN / 16;        // n8 frags per warp
    constexpr int ASZ = 128 * 64;       // bytes per A split slab
    constexpr int BSZ = TN * 64;
    constexpr int BUF = 2 * ASZ + 2 * BSZ;

    extern __shared__ char smem[];
    const u32 base = smem_u32(smem);
    const int t = threadIdx.x, lane = t & 31, warp = t >> 5;
    const int mBase = blockIdx.y * 128, nBase = blockIdx.x * TN;
    const int wm = (warp >> 1) * 32, wn = (warp & 1) * (TN / 2);
    const int ar0 = wm + (lane & 15);            // +16 per mi
    const int ahi = lane >> 4;
    const int br0 = wn + (lane & 7) + ((lane >> 4) << 3);  // +16 per j
    const int bhi = (lane >> 3) & 1;

    float acc[2][NJW][4];
    #pragma unroll
    for (int mi = 0; mi < 2; mi++)
        #pragma unroll
        for (int nj = 0; nj < NJW; nj++)
            #pragma unroll
            for (int r = 0; r < 4; r++) acc[mi][nj][r] = 0.f;

    const int S = (K + 31) / 32;

    auto loadSlab = [&](int s) {
        const int k0 = s * 32;
        const u32 bb = base + (s & 1) * BUF;
        #pragma unroll
        for (int p = 0; p < 2; p++) {
            int c = p * 256 + t, row = c >> 2, ch = c & 3;
            int kk = k0 + ch * 8;
            int avail = K - kk;
            int sz = (avail >= 8) ? 16 : (avail > 0 ? avail * 2 : 0);
            u32 off = row * 64 + ((u32)(ch ^ ((row >> 1) & 3)) << 4);
            const bf16* sh = Ah + (size_t)(mBase + row) * K + kk;
            const bf16* sl = Al + (size_t)(mBase + row) * K + kk;
            cp_async16(bb + off, sh, sz);
            cp_async16(bb + ASZ + off, sl, sz);
        }
        #pragma unroll
        for (int p = 0; p < TN / 64; p++) {
            int c = p * 256 + t, row = c >> 2, ch = c & 3;
            int kk = k0 + ch * 8;
            int avail = K - kk;
            int sz = (avail >= 8) ? 16 : (avail > 0 ? avail * 2 : 0);
            if (nBase + row >= N) sz = 0;
            u32 off = row * 64 + ((u32)(ch ^ ((row >> 1) & 3)) << 4);
            const bf16* sh = Bh + (size_t)(nBase + row) * K + kk;
            const bf16* sl = Bl + (size_t)(nBase + row) * K + kk;
            cp_async16(bb + 2 * ASZ + off, sh, sz);
            cp_async16(bb + 2 * ASZ + BSZ + off, sl, sz);
        }
    };

    loadSlab(0);
    CP_COMMIT();

    for (int s = 0; s < S; s++) {
        if (s + 1 < S) { loadSlab(s + 1); CP_COMMIT(); CP_WAIT1(); }
        else           { CP_WAIT0(); }
        __syncthreads();

        const u32 bb = base + (s & 1) * BUF;
        const u32 aB0 = bb, aB1 = bb + ASZ;
        const u32 bB0 = bb + 2 * ASZ, bB1 = bb + 2 * ASZ + BSZ;

        #pragma unroll
        for (int ks = 0; ks < 2; ks++) {
            u32 ahf[2][4], alf[2][4];
            #pragma unroll
            for (int mi = 0; mi < 2; mi++) {
                int row = ar0 + mi * 16;
                u32 off = row * 64 + ((u32)((ks * 2 + ahi) ^ ((row >> 1) & 3)) << 4);
                ldsm4(aB0 + off, ahf[mi][0], ahf[mi][1], ahf[mi][2], ahf[mi][3]);
                ldsm4(aB1 + off, alf[mi][0], alf[mi][1], alf[mi][2], alf[mi][3]);
            }
            #pragma unroll
            for (int j = 0; j < NJW / 2; j++) {
                int row = br0 + j * 16;
                u32 off = row * 64 + ((u32)((ks * 2 + bhi) ^ ((row >> 1) & 3)) << 4);
                u32 b0, b1, b2, b3, l0, l1, l2, l3;
                ldsm4(bB0 + off, b0, b1, b2, b3);
                ldsm4(bB1 + off, l0, l1, l2, l3);
                #pragma unroll
                for (int mi = 0; mi < 2; mi++) {
                    mma_bf16(acc[mi][2 * j],     ahf[mi], b0, b1);
                    mma_bf16(acc[mi][2 * j],     ahf[mi], l0, l1);
                    mma_bf16(acc[mi][2 * j],     alf[mi], b0, b1);
                    mma_bf16(acc[mi][2 * j + 1], ahf[mi], b2, b3);
                    mma_bf16(acc[mi][2 * j + 1], ahf[mi], l2, l3);
                    mma_bf16(acc[mi][2 * j + 1], alf[mi], b2, b3);
                }
            }
        }
        __syncthreads();
    }

    // epilogue
    const int g = lane >> 2, tg = lane & 3;
    #pragma unroll
    for (int mi = 0; mi < 2; mi++) {
        int row0 = mBase + wm + mi * 16 + g;
        #pragma unroll
        for (int nj = 0; nj < NJW; nj++) {
            int col0 = nBase + wn + nj * 8 + 2 * tg;
            #pragma unroll
            for (int half = 0; half < 2; half++) {
                int col = col0 + half;
                if (col < padN) {
                    #pragma unroll
                    for (int rr = 0; rr < 2; rr++) {
                        int row = row0 + rr * 8;
                        float v = 0.f;
                        if (col < N) {
                            v = acc[mi][nj][rr * 2 + half] + (bias ? bias[col] : 0.f);
                            if (RELU) v = fmaxf(v, 0.f);
                        }
                        if (SPLIT) split_write(Ch, Cl, (size_t)row * ldout + col, v);
                        else       C[(size_t)row * ldout + col] = v;
                    }
                }
            }
        }
    }
}

// ----------------------------------------------------------------------------
// Attention scores: S[bh,m,n] = 0.125 * sum_d Q[m,d] K[n,d]
// ----------------------------------------------------------------------------
__global__ __launch_bounds__(256)
void attn_scores(const float* __restrict__ qkv, float* __restrict__ S)
{
    __shared__ float Qt[32][133];
    __shared__ float Kt[32][133];
    int bh = blockIdx.x;
    int b = bh / HH, h = bh % HH;
    const float* base = qkv + (size_t)b * MM * (3 * DD) + h * HD;
    int t = threadIdx.x, tx = t & 15, ty = t >> 4;
    float acc[8][8];
    #pragma unroll
    for (int i = 0; i < 8; i++)
        #pragma unroll
        for (int j = 0; j < 8; j++) acc[i][j] = 0.f;

    for (int d0 = 0; d0 < HD; d0 += 32) {
        #pragma unroll
        for (int i = 0; i < 16; i++) {
            int e = t + 256 * i;
            int d = e & 31, m = e >> 5;
            Qt[d][m] = base[(size_t)m * (3 * DD) + d0 + d];
            Kt[d][m] = base[(size_t)m * (3 * DD) + DD + d0 + d];
        }
        __syncthreads();
        #pragma unroll
        for (int d = 0; d < 32; d++) {
            float a[8], bb[8];
            #pragma unroll
            for (int i = 0; i < 8; i++) a[i]  = Qt[d][ty * 8 + i];
            #pragma unroll
            for (int j = 0; j < 8; j++) bb[j] = Kt[d][tx * 8 + j];
            #pragma unroll
            for (int i = 0; i < 8; i++)
                #pragma unroll
                for (int j = 0; j < 8; j++)
                    acc[i][j] += a[i] * bb[j];
        }
        __syncthreads();
    }
    float* Sp = S + (size_t)bh * MM * MM;
    #pragma unroll
    for (int i = 0; i < 8; i++)
        #pragma unroll
        for (int j = 0; j < 8; j++)
            Sp[(size_t)(ty * 8 + i) * MM + tx * 8 + j] = acc[i][j] * 0.125f;
}

// ----------------------------------------------------------------------------
// Row softmax
// ----------------------------------------------------------------------------
__global__ void attn_softmax(float* __restrict__ S)
{
    float* p = S + (size_t)blockIdx.x * MM;
    int t = threadIdx.x;
    float v = p[t];
    __shared__ float red[4];
    float mx = v;
    #pragma unroll
    for (int o = 16; o; o >>= 1) mx = fmaxf(mx, __shfl_xor_sync(~0u, mx, o));
    if ((t & 31) == 0) red[t >> 5] = mx;
    __syncthreads();
    mx = fmaxf(fmaxf(red[0], red[1]), fmaxf(red[2], red[3]));
    float e = expf(v - mx);
    float s = e;
    #pragma unroll
    for (int o = 16; o; o >>= 1) s += __shfl_xor_sync(~0u, s, o);
    __syncthreads();
    if ((t & 31) == 0) red[t >> 5] = s;
    __syncthreads();
    s = red[0] + red[1] + red[2] + red[3];
    p[t] = e / s;
}

// ----------------------------------------------------------------------------
// P @ V -> attention output written directly as bf16 split
// ----------------------------------------------------------------------------
__global__ __launch_bounds__(256)
void attn_pv(const float* __restrict__ qkv, const float* __restrict__ S,
             bf16* __restrict__ aoh, bf16* __restrict__ aol)
{
    __shared__ float Ps[128][33];
    __shared__ float Vs[32][68];
    int bh = blockIdx.x;
    int b = bh / HH, h = bh % HH;
    const float* Sp = S + (size_t)bh * MM * MM;
    const float* Vb = qkv + (size_t)b * MM * (3 * DD) + 2 * DD + h * HD;
    int t = threadIdx.x, tx = t & 15, ty = t >> 4;
    float acc[8][4];
    #pragma unroll
    for (int i = 0; i < 8; i++)
        #pragma unroll
        for (int j = 0; j < 4; j++) acc[i][j] = 0.f;

    for (int n0 = 0; n0 < MM; n0 += 32) {
        #pragma unroll
        for (int i = 0; i < 16; i++) {
            int e = t + 256 * i;
            int n = e & 31, m = e >> 5;
            Ps[m][n] = Sp[(size_t)m * MM + n0 + n];
        }
        #pragma unroll
        for (int i = 0; i < 8; i++) {
            int e = t + 256 * i;
            int d = e & 63, n = e >> 6;
            Vs[n][d] = Vb[(size_t)(n0 + n) * (3 * DD) + d];
        }
        __syncthreads();
        #pragma unroll
        for (int n = 0; n < 32; n++) {
            float a[8], bb[4];
            #pragma unroll
            for (int i = 0; i < 8; i++) a[i]  = Ps[ty * 8 + i][n];
            #pragma unroll
            for (int j = 0; j < 4; j++) bb[j] = Vs[n][tx * 4 + j];
            #pragma unroll
            for (int i = 0; i < 8; i++)
                #pragma unroll
                for (int j = 0; j < 4; j++)
                    acc[i][j] += a[i] * bb[j];
        }
        __syncthreads();
    }
    size_t ob = (size_t)b * MM * DD + h * HD;
    #pragma unroll
    for (int i = 0; i < 8; i++)
        #pragma unroll
        for (int j = 0; j < 4; j++)
            split_write(aoh, aol, ob + (size_t)(ty * 8 + i) * DD + tx * 4 + j,
                        acc[i][j]);
}

// ----------------------------------------------------------------------------
// x = LayerNorm(x + delta) * w + b; also writes bf16 split of x
// ----------------------------------------------------------------------------
__global__ __launch_bounds__(256)
void add_ln_kernel(float* __restrict__ x, const float* __restrict__ d,
                   const float* __restrict__ w, const float* __restrict__ b,
                   bf16* __restrict__ xh, bf16* __restrict__ xl)
{
    int row = blockIdx.x, t = threadIdx.x;
    float* xp = x + (size_t)row * DD;
    const float* dp = d + (size_t)row * DD;
    float v0 = xp[t]       + dp[t];
    float v1 = xp[t + 256] + dp[t + 256];
    float v2 = xp[t + 512] + dp[t + 512];
    float s = v0 + v1 + v2;
    __shared__ float red[8];
    #pragma unroll
    for (int o = 16; o; o >>= 1) s += __shfl_xor_sync(~0u, s, o);
    if ((t & 31) == 0) red[t >> 5] = s;
    __syncthreads();
    float tot = red[0] + red[1] + red[2] + red[3] + red[4] + red[5] + red[6] + red[7];
    float mu = tot * (1.f / 768.f);
    float d0 = v0 - mu, d1 = v1 - mu, d2 = v2 - mu;
    float q = d0 * d0 + d1 * d1 + d2 * d2;
    #pragma unroll
    for (int o = 16; o; o >>= 1) q += __shfl_xor_sync(~0u, q, o);
    __syncthreads();
    if ((t & 31) == 0) red[t >> 5] = q;
    __syncthreads();
    float qt = red[0] + red[1] + red[2] + red[3] + red[4] + red[5] + red[6] + red[7];
    float inv = rsqrtf(qt * (1.f / 768.f) + 1e-5f);
    float o0 = d0 * inv * w[t]       + b[t];
    float o1 = d1 * inv * w[t + 256] + b[t + 256];
    float o2 = d2 * inv * w[t + 512] + b[t + 512];
    size_t rb = (size_t)row * DD;
    xp[t] = o0;       split_write(xh, xl, rb + t,       o0);
    xp[t + 256] = o1; split_write(xh, xl, rb + t + 256, o1);
    xp[t + 512] = o2; split_write(xh, xl, rb + t + 512, o2);
}

// ----------------------------------------------------------------------------
// Host-side launch
// ----------------------------------------------------------------------------
template<typename T>
static T* sym(const void* s)
{
    void* p = nullptr;
    cudaGetSymbolAddress(&p, s);
    return (T*)p;
}

#define SMEM128 (2 * (2 * 128 * 64 + 2 * 128 * 64))   // 65536
#define SMEM64  (2 * (2 * 128 * 64 + 2 * 64  * 64))   // 49152

extern "C" void kernel_launch(void* const* d_in, const int* in_sizes, int n_in,
                              void* d_out, int out_size)
{
    static const long long want[20] = {
        6291456LL, 65536LL, 2048LL, 768LL, 1LL,
        7077888LL, 9216LL, 2359296LL, 3072LL, 3072LL, 3072LL,
        9437184LL, 12288LL, 9437184LL, 3072LL, 3072LL, 3072LL,
        76800LL, 5000000LL, 50000LL
    };
    const void* slot[20];
    bool used[64];
    for (int i = 0; i < 20; i++) slot[i] = nullptr;
    for (int i = 0; i < n_in && i < 64; i++) used[i] = false;
    for (int w = 0; w < 20; w++) {
        for (int i = 0; i < n_in && i < 64; i++) {
            if (!used[i] && (long long)in_sizes[i] == want[w]) {
                slot[w] = d_in[i];
                used[i] = true;
                break;
            }
        }
    }
    if (!slot[0]) {
        for (int w = 0; w < 20 && w < n_in; w++) slot[w] = d_in[w];
    }

    const float* lhs    = (const float*)slot[0];
    const int*   pos    = (const int*)slot[1];
    const int*   mask   = (const int*)slot[2];
    const float* attn_w = (const float*)slot[3];
    const float* qkv_w  = (const float*)slot[5];
    const float* qkv_b  = (const float*)slot[6];
    const float* out_w  = (const float*)slot[7];
    const float* out_b  = (const float*)slot[8];
    const float* ln1_w  = (const float*)slot[9];
    const float* ln1_b  = (const float*)slot[10];
    const float* ff1_w  = (const float*)slot[11];
    const float* ff1_b  = (const float*)slot[12];
    const float* ff2_w  = (const float*)slot[13];
    const float* ff2_b  = (const float*)slot[14];
    const float* ln2_w  = (const float*)slot[15];
    const float* ln2_b  = (const float*)slot[16];
    const float* cls_w1 = (const float*)slot[17];
    const float* cls_w2 = (const float*)slot[18];
    const float* cls_b2 = (const float*)slot[19];
    float* out = (float*)d_out;

    float* hl  = sym<float>(g_hl);
    float* x   = sym<float>(g_x);
    float* qkv = sym<float>(g_qkv);
    float* s   = sym<float>(g_s);
    float* tmp = sym<float>(g_tmp);
    bf16*  wh  = sym<bf16>(g_wh);
    bf16*  wl  = sym<bf16>(g_wl);
    bf16*  ah  = sym<bf16>(g_ah);
    bf16*  al  = sym<bf16>(g_al);
    bf16*  bh2 = sym<bf16>(g_bh);
    bf16*  bl2 = sym<bf16>(g_bl);

    cudaFuncSetAttribute(gemm_tc<128, 0, 0>, cudaFuncAttributeMaxDynamicSharedMemorySize, SMEM128);
    cudaFuncSetAttribute(gemm_tc<128, 1, 1>, cudaFuncAttributeMaxDynamicSharedMemorySize, SMEM128);
    cudaFuncSetAttribute(gemm_tc<64, 0, 0>,  cudaFuncAttributeMaxDynamicSharedMemorySize, SMEM64);
    cudaFuncSetAttribute(gemm_tc<64, 0, 1>,  cudaFuncAttributeMaxDynamicSharedMemorySize, SMEM64);

    // --- weight conversion (every launch; deterministic) ---
    cvt_kernel<<<4096, 256>>>(qkv_w,  wh + OW_QKV,  wl + OW_QKV,  7077888);
    cvt_kernel<<<2048, 256>>>(out_w,  wh + OW_OUT,  wl + OW_OUT,  2359296);
    cvt_kernel<<<4096, 256>>>(ff1_w,  wh + OW_FF1,  wl + OW_FF1,  9437184);
    cvt_kernel<<<4096, 256>>>(ff2_w,  wh + OW_FF2,  wl + OW_FF2,  9437184);
    cvt_kernel<<<128,  256>>>(cls_w1, wh + OW_CLS1, wl + OW_CLS1, 76800);
    cvt_pad_kernel<<<4096, 256>>>(cls_w2, wh + OW_CLS2, wl + OW_CLS2, NE, 100);

    // --- mention pooling (writes x + split) ---
    hl_kernel<<<BB * LL, 256>>>(lhs, attn_w, hl);
    pool_kernel<<<ROWS, 256>>>(lhs, pos, mask, hl, x, ah, al);

    // --- transformer layers ---
    for (int i = 0; i < NL; i++) {
        gemm_tc<128, 0, 0><<<dim3(3 * DD / 128, ROWS / 128), 256, SMEM128>>>(
            ah, al, wh + OW_QKV + (size_t)i * 3 * DD * DD,
            wl + OW_QKV + (size_t)i * 3 * DD * DD,
            qkv_b + (size_t)i * 3 * DD, qkv, nullptr, nullptr,
            ROWS, 3 * DD, DD, 3 * DD, 3 * DD);
        attn_scores<<<BB * HH, 256>>>(qkv, s);
        attn_softmax<<<BB * HH * MM, 128>>>(s);
        attn_pv<<<BB * HH, 256>>>(qkv, s, ah, al);
        gemm_tc<64, 0, 0><<<dim3(DD / 64, ROWS / 128), 256, SMEM64>>>(
            ah, al, wh + OW_OUT + (size_t)i * DD * DD,
            wl + OW_OUT + (size_t)i * DD * DD,
            out_b + (size_t)i * DD, tmp, nullptr, nullptr,
            ROWS, DD, DD, DD, DD);
        add_ln_kernel<<<ROWS, 256>>>(x, tmp, ln1_w + (size_t)i * DD,
                                     ln1_b + (size_t)i * DD, ah, al);
        gemm_tc<128, 1, 1><<<dim3(DFF / 128, ROWS / 128), 256, SMEM128>>>(
            ah, al, wh + OW_FF1 + (size_t)i * DFF * DD,
            wl + OW_FF1 + (size_t)i * DFF * DD,
            ff1_b + (size_t)i * DFF, nullptr, bh2, bl2,
            ROWS, DFF, DD, DFF, DFF);
        gemm_tc<64, 0, 0><<<dim3(DD / 64, ROWS / 128), 256, SMEM64>>>(
            bh2, bl2, wh + OW_FF2 + (size_t)i * DD * DFF,
            wl + OW_FF2 + (size_t)i * DD * DFF,
            ff2_b + (size_t)i * DD, tmp, nullptr, nullptr,
            ROWS, DD, DFF, DD, DD);
        add_ln_kernel<<<ROWS, 256>>>(x, tmp, ln2_w + (size_t)i * DD,
                                     ln2_b + (size_t)i * DD, ah, al);
    }

    // --- classifier head ---
    gemm_tc<64, 0, 1><<<dim3(2, ROWS / 128), 256, SMEM64>>>(
        ah, al, wh + OW_CLS1, wl + OW_CLS1, nullptr,
        nullptr, bh2, bl2, ROWS, 100, DD, KPAD, KPAD);
    gemm_tc<128, 0, 0><<<dim3((NE + 127) / 128, ROWS / 128), 256, SMEM128>>>(
        bh2, bl2, wh + OW_CLS2, wl + OW_CLS2, cls_b2,
        out, nullptr, nullptr, ROWS, NE, KPAD, NE, NE);
}

// round 7
// speedup vs baseline: 3.4963x; 1.0753x over previous
#include <cuda_runtime.h>
#include <cuda_bf16.h>
#include <math.h>
#include <cstdint>

// ----------------------------------------------------------------------------
// Problem constants
// ----------------------------------------------------------------------------
#define BB   16
#define MM   128
#define LL   32
#define SS   512
#define DD   768
#define HH   12
#define HD   64
#define DFF  3072
#define NL   4
#define NE   50000
#define ROWS (BB*MM)          // 2048
#define KPAD 112              // padded K for classifier stage 2

typedef unsigned long long ull;
typedef unsigned int u32;
typedef __nv_bfloat16 bf16;

// weight scratch offsets (elements)
#define OW_QKV  0ULL
#define OW_OUT  7077888ULL
#define OW_FF1  9437184ULL
#define OW_FF2  18874368ULL
#define OW_CLS1 28311552ULL
#define OW_CLS2 28388352ULL
#define NW_TOT  (28388352ULL + 50000ULL*KPAD)

// ----------------------------------------------------------------------------
// Device scratch (static allocation — no cudaMalloc allowed)
// ----------------------------------------------------------------------------
__device__ float g_hl[BB*LL];
__device__ float g_x [ROWS*DD];
__device__ float g_tmp[ROWS*DFF];
__device__ __align__(256) bf16 g_wh[NW_TOT];
__device__ __align__(256) bf16 g_wl[NW_TOT];
__device__ __align__(256) bf16 g_ah[ROWS*DFF];
__device__ __align__(256) bf16 g_al[ROWS*DFF];
__device__ __align__(256) bf16 g_bh[ROWS*DFF];
__device__ __align__(256) bf16 g_bl[ROWS*DFF];

// ----------------------------------------------------------------------------
// PTX helpers
// ----------------------------------------------------------------------------
__device__ __forceinline__ u32 smem_u32(const void* p)
{
    u32 a;
    asm("{ .reg .u64 t; cvta.to.shared.u64 t, %1; cvt.u32.u64 %0, t; }"
        : "=r"(a) : "l"(p));
    return a;
}

__device__ __forceinline__ void cp_async16(u32 dst, const void* src, int sz)
{
    asm volatile("cp.async.cg.shared.global [%0], [%1], 16, %2;"
        :: "r"(dst), "l"(src), "r"(sz));
}
#define CP_COMMIT() asm volatile("cp.async.commit_group;" ::: "memory")
#define CP_WAIT1()  asm volatile("cp.async.wait_group 1;" ::: "memory")
#define CP_WAIT0()  asm volatile("cp.async.wait_group 0;" ::: "memory")

__device__ __forceinline__ void ldsm4(u32 addr, u32& r0, u32& r1, u32& r2, u32& r3)
{
    asm volatile("ldmatrix.sync.aligned.m8n8.x4.shared.b16 {%0,%1,%2,%3}, [%4];"
        : "=r"(r0), "=r"(r1), "=r"(r2), "=r"(r3) : "r"(addr));
}
__device__ __forceinline__ void ldsm4t(u32 addr, u32& r0, u32& r1, u32& r2, u32& r3)
{
    asm volatile("ldmatrix.sync.aligned.m8n8.x4.trans.shared.b16 {%0,%1,%2,%3}, [%4];"
        : "=r"(r0), "=r"(r1), "=r"(r2), "=r"(r3) : "r"(addr));
}

__device__ __forceinline__ void mma_bf16(float* d, const u32* a, u32 b0, u32 b1)
{
    asm volatile(
        "mma.sync.aligned.m16n8k16.row.col.f32.bf16.bf16.f32 "
        "{%0,%1,%2,%3},{%4,%5,%6,%7},{%8,%9},{%0,%1,%2,%3};"
        : "+f"(d[0]), "+f"(d[1]), "+f"(d[2]), "+f"(d[3])
        : "r"(a[0]), "r"(a[1]), "r"(a[2]), "r"(a[3]), "r"(b0), "r"(b1));
}

// pack two fp32 into bf16x2 word: lo at lower halfword
__device__ __forceinline__ u32 pack_bf(float lo, float hi)
{
    u32 r;
    asm("cvt.rn.bf16x2.f32 %0, %1, %2;" : "=r"(r) : "f"(hi), "f"(lo));
    return r;
}

__device__ __forceinline__ float bf_round(float v)
{
    return __bfloat162float(__float2bfloat16(v));
}

__device__ __forceinline__ void split_write(bf16* h, bf16* l, size_t idx, float v)
{
    bf16 hh = __float2bfloat16(v);
    h[idx] = hh;
    l[idx] = __float2bfloat16(v - __bfloat162float(hh));
}

// packed pair store (idx even, arrays 4B-aligned)
__device__ __forceinline__ void split_store2(bf16* h, bf16* l, size_t idx,
                                             float v0, float v1)
{
    float h0 = bf_round(v0), h1 = bf_round(v1);
    *(u32*)(h + idx) = pack_bf(h0, h1);
    *(u32*)(l + idx) = pack_bf(v0 - h0, v1 - h1);
}

// ----------------------------------------------------------------------------
// weight fp32 -> bf16 hi/lo split, 8 elems/thread/iter (n % 8 == 0)
// ----------------------------------------------------------------------------
__global__ void cvt_kernel(const float* __restrict__ x,
                           bf16* __restrict__ h, bf16* __restrict__ l, int n)
{
    int n8 = n >> 3;
    for (int i = blockIdx.x * 256 + threadIdx.x; i < n8; i += gridDim.x * 256) {
        const float4* xp = (const float4*)x + 2 * (size_t)i;
        float4 a = xp[0], b = xp[1];
        float h0 = bf_round(a.x), h1 = bf_round(a.y),
              h2 = bf_round(a.z), h3 = bf_round(a.w),
              h4 = bf_round(b.x), h5 = bf_round(b.y),
              h6 = bf_round(b.z), h7 = bf_round(b.w);
        uint4 H, L;
        H.x = pack_bf(h0, h1); H.y = pack_bf(h2, h3);
        H.z = pack_bf(h4, h5); H.w = pack_bf(h6, h7);
        L.x = pack_bf(a.x - h0, a.y - h1); L.y = pack_bf(a.z - h2, a.w - h3);
        L.z = pack_bf(b.x - h4, b.y - h5); L.w = pack_bf(b.z - h6, b.w - h7);
        ((uint4*)h)[i] = H;
        ((uint4*)l)[i] = L;
    }
}

// cls_w2: [NE,100] -> [NE,112] zero-padded split (4 cols/thread/iter)
__global__ void cvt_pad_kernel(const float* __restrict__ x,
                               bf16* __restrict__ h, bf16* __restrict__ l)
{
    int total = NE * 28;
    for (int i = blockIdx.x * 256 + threadIdx.x; i < total; i += gridDim.x * 256) {
        int r = i / 28, c4 = (i - r * 28) * 4;
        u32 ha = 0, hb = 0, la = 0, lb = 0;
        if (c4 < 100) {
            float4 v = *(const float4*)(x + (size_t)r * 100 + c4);
            float h0 = bf_round(v.x), h1 = bf_round(v.y),
                  h2 = bf_round(v.z), h3 = bf_round(v.w);
            ha = pack_bf(h0, h1); hb = pack_bf(h2, h3);
            la = pack_bf(v.x - h0, v.y - h1); lb = pack_bf(v.z - h2, v.w - h3);
        }
        size_t o = (size_t)r * KPAD + c4;
        *(uint2*)(h + o) = make_uint2(ha, hb);
        *(uint2*)(l + o) = make_uint2(la, lb);
    }
}

// ----------------------------------------------------------------------------
// hl[b,l] = dot(hidden[b,l,:], attn_w)
// ----------------------------------------------------------------------------
__global__ void hl_kernel(const float* __restrict__ lhs,
                          const float* __restrict__ aw,
                          float* __restrict__ hl)
{
    int blk = blockIdx.x;
    int b = blk >> 5, l = blk & 31;
    const float* row = lhs + ((size_t)b * SS + l) * DD;
    int t = threadIdx.x;
    float p = 0.f;
    for (int i = t; i < DD; i += 256) p += row[i] * aw[i];
    #pragma unroll
    for (int o = 16; o; o >>= 1) p += __shfl_xor_sync(~0u, p, o);
    __shared__ float red[8];
    if ((t & 31) == 0) red[t >> 5] = p;
    __syncthreads();
    if (t == 0) {
        float s = 0.f;
        #pragma unroll
        for (int i = 0; i < 8; i++) s += red[i];
        hl[b * LL + l] = s;
    }
}

// ----------------------------------------------------------------------------
// Mention pooling (pos/mask int32). Writes x fp32 + bf16 split.
// ----------------------------------------------------------------------------
__global__ void pool_kernel(const float* __restrict__ lhs,
                            const int* __restrict__ pos,
                            const int* __restrict__ mask,
                            const float* __restrict__ hl,
                            float* __restrict__ x,
                            bf16* __restrict__ xh, bf16* __restrict__ xl)
{
    int bm = blockIdx.x;
    int b = bm >> 7;
    int t = threadIdx.x;
    __shared__ float ws[LL];
    __shared__ int s_nv;
    if (t < 32) {
        int p = pos[(size_t)bm * LL + t];
        unsigned bits = __ballot_sync(0xffffffffu, p != -1);
        int nv;
        if (mask[bm] == 0) nv = 0;
        else if (~bits == 0u) nv = 32;
        else nv = __ffs(~bits) - 1;
        float logit = (t < nv) ? hl[b * LL + t] : 0.f;
        float mx = logit;
        #pragma unroll
        for (int o = 16; o; o >>= 1) mx = fmaxf(mx, __shfl_xor_sync(~0u, mx, o));
        float e = expf(logit - mx);
        float s = e;
        #pragma unroll
        for (int o = 16; o; o >>= 1) s += __shfl_xor_sync(~0u, s, o);
        ws[t] = e / s;
        if (t == 0) s_nv = nv;
    }
    __syncthreads();
    int nv = s_nv;
    for (int d = t; d < DD; d += 256) {
        float acc = 0.f;
        for (int l = 0; l < nv; l++)
            acc += ws[l] * lhs[((size_t)b * SS + l) * DD + d];
        size_t idx = (size_t)bm * DD + d;
        x[idx] = acc;
        split_write(xh, xl, idx, acc);
    }
}

// ----------------------------------------------------------------------------
// Tensor-core split-bf16 NT GEMM: mma.sync + ldmatrix + 3-stage cp.async ring.
// C[M,N] = A*B^T (+bias, opt relu). BK=32, XOR-swizzled 64B rows, one sync/slab.
// 8 warps: 4m x 2n, warp tile 32 x TN/2. M%128==0; N,K guarded; N even.
// SPLIT=0 -> fp32 C; SPLIT=1 -> bf16 hi/lo, cols [N,padN) zero-filled.
// ----------------------------------------------------------------------------
template<int TN, int RELU, int SPLIT>
__global__ __launch_bounds__(256)
void gemm_tc(const bf16* __restrict__ Ah, const bf16* __restrict__ Al,
             const bf16* __restrict__ Bh, const bf16* __restrict__ Bl,
             const float* __restrict__ bias,
             float* __restrict__ C, bf16* __restrict__ Ch, bf16* __restrict__ Cl,
             int M, int N, int K, int ldout, int padN)
{
    constexpr int NJW = TN / 16;
    constexpr int ASZ = 128 * 64;
    constexpr int BSZ = TN * 64;
    constexpr int BUF = 2 * ASZ + 2 * BSZ;

    extern __shared__ char smem[];
    const u32 base = smem_u32(smem);
    const int t = threadIdx.x, lane = t & 31, warp = t >> 5;
    const int mBase = blockIdx.y * 128, nBase = blockIdx.x * TN;
    const int wm = (warp >> 1) * 32, wn = (warp & 1) * (TN / 2);
    const int ar0 = wm + (lane & 15);
    const int ahi = lane >> 4;
    const int br0 = wn + (lane & 7) + ((lane >> 4) << 3);
    const int bhi = (lane >> 3) & 1;

    float acc[2][NJW][4];
    #pragma unroll
    for (int mi = 0; mi < 2; mi++)
        #pragma unroll
        for (int nj = 0; nj < NJW; nj++)
            #pragma unroll
            for (int r = 0; r < 4; r++) acc[mi][nj][r] = 0.f;

    const int S = (K + 31) / 32;

    auto loadSlab = [&](int s) {
        const int k0 = s * 32;
        const u32 bb = base + (s % 3) * BUF;
        #pragma unroll
        for (int p = 0; p < 2; p++) {
            int c = p * 256 + t, row = c >> 2, ch = c & 3;
            int kk = k0 + ch * 8;
            int avail = K - kk;
            int sz = (avail >= 8) ? 16 : (avail > 0 ? avail * 2 : 0);
            u32 off = row * 64 + ((u32)(ch ^ ((row >> 1) & 3)) << 4);
            cp_async16(bb + off, Ah + (size_t)(mBase + row) * K + kk, sz);
            cp_async16(bb + ASZ + off, Al + (size_t)(mBase + row) * K + kk, sz);
        }
        #pragma unroll
        for (int p = 0; p < TN / 64; p++) {
            int c = p * 256 + t, row = c >> 2, ch = c & 3;
            int kk = k0 + ch * 8;
            int avail = K - kk;
            int sz = (avail >= 8) ? 16 : (avail > 0 ? avail * 2 : 0);
            if (nBase + row >= N) sz = 0;
            u32 off = row * 64 + ((u32)(ch ^ ((row >> 1) & 3)) << 4);
            cp_async16(bb + 2 * ASZ + off, Bh + (size_t)(nBase + row) * K + kk, sz);
            cp_async16(bb + 2 * ASZ + BSZ + off, Bl + (size_t)(nBase + row) * K + kk, sz);
        }
    };

    loadSlab(0);
    CP_COMMIT();
    if (S > 1) loadSlab(1);
    CP_COMMIT();

    for (int s = 0; s < S; s++) {
        CP_WAIT1();
        __syncthreads();
        if (s + 2 < S) loadSlab(s + 2);
        CP_COMMIT();

        const u32 bb = base + (s % 3) * BUF;
        const u32 aB0 = bb, aB1 = bb + ASZ;
        const u32 bB0 = bb + 2 * ASZ, bB1 = bb + 2 * ASZ + BSZ;

        #pragma unroll
        for (int ks = 0; ks < 2; ks++) {
            u32 ahf[2][4], alf[2][4];
            #pragma unroll
            for (int mi = 0; mi < 2; mi++) {
                int row = ar0 + mi * 16;
                u32 off = row * 64 + ((u32)((ks * 2 + ahi) ^ ((row >> 1) & 3)) << 4);
                ldsm4(aB0 + off, ahf[mi][0], ahf[mi][1], ahf[mi][2], ahf[mi][3]);
                ldsm4(aB1 + off, alf[mi][0], alf[mi][1], alf[mi][2], alf[mi][3]);
            }
            #pragma unroll
            for (int j = 0; j < NJW / 2; j++) {
                int row = br0 + j * 16;
                u32 off = row * 64 + ((u32)((ks * 2 + bhi) ^ ((row >> 1) & 3)) << 4);
                u32 b0, b1, b2, b3, l0, l1, l2, l3;
                ldsm4(bB0 + off, b0, b1, b2, b3);
                ldsm4(bB1 + off, l0, l1, l2, l3);
                #pragma unroll
                for (int mi = 0; mi < 2; mi++) {
                    mma_bf16(acc[mi][2 * j],     ahf[mi], b0, b1);
                    mma_bf16(acc[mi][2 * j],     ahf[mi], l0, l1);
                    mma_bf16(acc[mi][2 * j],     alf[mi], b0, b1);
                    mma_bf16(acc[mi][2 * j + 1], ahf[mi], b2, b3);
                    mma_bf16(acc[mi][2 * j + 1], ahf[mi], l2, l3);
                    mma_bf16(acc[mi][2 * j + 1], alf[mi], b2, b3);
                }
            }
        }
    }

    // epilogue (packed pair stores; all N/padN even)
    const int g = lane >> 2, tg = lane & 3;
    #pragma unroll
    for (int mi = 0; mi < 2; mi++) {
        int row0 = mBase + wm + mi * 16 + g;
        #pragma unroll
        for (int nj = 0; nj < NJW; nj++) {
            int col0 = nBase + wn + nj * 8 + 2 * tg;
            if (col0 < padN) {
                #pragma unroll
                for (int rr = 0; rr < 2; rr++) {
                    int row = row0 + rr * 8;
                    float v0 = 0.f, v1 = 0.f;
                    if (col0 < N) {
                        v0 = acc[mi][nj][rr * 2 + 0] + (bias ? bias[col0] : 0.f);
                        v1 = acc[mi][nj][rr * 2 + 1] + (bias ? bias[col0 + 1] : 0.f);
                        if (RELU) { v0 = fmaxf(v0, 0.f); v1 = fmaxf(v1, 0.f); }
                    }
                    if (SPLIT)
                        split_store2(Ch, Cl, (size_t)row * ldout + col0, v0, v1);
                    else
                        *(float2*)(C + (size_t)row * ldout + col0) = make_float2(v0, v1);
                }
            }
        }
    }
}

// ----------------------------------------------------------------------------
// Fused attention: one CTA per (b,h), 8 warps x 16 Q-rows.
// qkvh/qkvl: bf16 split of qkv [ROWS][3*DD]. Output: split attention out.
// S = Q.K^T (split, 3 prod) -> softmax in regs -> P frags from accums -> P.V.
// ----------------------------------------------------------------------------
__global__ __launch_bounds__(256)
void attn_fused(const bf16* __restrict__ qkvh, const bf16* __restrict__ qkvl,
                bf16* __restrict__ aoh, bf16* __restrict__ aol)
{
    extern __shared__ char smem[];
    const u32 base = smem_u32(smem);
    const int t = threadIdx.x, lane = t & 31, warp = t >> 5;
    const int bh = blockIdx.x, b = bh / HH, h = bh % HH;
    const size_t rowBase = (size_t)b * MM;
    const int g = lane >> 2, tg = lane & 3;

    // smem tiles: Qh Ql Kh Kl Vh Vl, each 128 rows x 64 bf16 (128B rows)
    #pragma unroll
    for (int m = 0; m < 6; m++) {
        const bf16* src = (m & 1) ? qkvl : qkvh;
        int colOff = (m >> 1) * DD + h * HD;
        u32 dst = base + m * 16384;
        #pragma unroll
        for (int p = 0; p < 4; p++) {
            int c = p * 256 + t;
            int row = c >> 3, ch = c & 7;
            u32 off = row * 128 + ((u32)(ch ^ (row & 7)) << 4);
            cp_async16(dst + off,
                       src + (rowBase + row) * (3 * DD) + colOff + ch * 8, 16);
        }
    }
    CP_COMMIT(); CP_WAIT0();
    __syncthreads();

    const u32 sQh = base, sQl = base + 16384;
    const u32 sKh = base + 32768, sKl = base + 49152;
    const u32 sVh = base + 65536, sVl = base + 81920;
    const int m0 = warp * 16;

    // ---- scores: S[16x128] per warp ----
    float acc[16][4];
    #pragma unroll
    for (int nj = 0; nj < 16; nj++)
        #pragma unroll
        for (int r = 0; r < 4; r++) acc[nj][r] = 0.f;

    const int tile = lane >> 3, wr = lane & 7;
    #pragma unroll
    for (int kk = 0; kk < 4; kk++) {
        u32 qh4[4], ql4[4];
        {
            int row = m0 + wr + (tile & 1) * 8;
            int ch = kk * 2 + (tile >> 1);
            u32 off = row * 128 + ((u32)(ch ^ (row & 7)) << 4);
            ldsm4(sQh + off, qh4[0], qh4[1], qh4[2], qh4[3]);
            ldsm4(sQl + off, ql4[0], ql4[1], ql4[2], ql4[3]);
        }
        #pragma unroll
        for (int nj2 = 0; nj2 < 8; nj2++) {
            int row = nj2 * 16 + wr + (tile >> 1) * 8;
            int ch = kk * 2 + (tile & 1);
            u32 off = row * 128 + ((u32)(ch ^ (row & 7)) << 4);
            u32 b0, b1, b2, b3, l0, l1, l2, l3;
            ldsm4(sKh + off, b0, b1, b2, b3);
            ldsm4(sKl + off, l0, l1, l2, l3);
            mma_bf16(acc[2 * nj2],     qh4, b0, b1);
            mma_bf16(acc[2 * nj2],     qh4, l0, l1);
            mma_bf16(acc[2 * nj2],     ql4, b0, b1);
            mma_bf16(acc[2 * nj2 + 1], qh4, b2, b3);
            mma_bf16(acc[2 * nj2 + 1], qh4, l2, l3);
            mma_bf16(acc[2 * nj2 + 1], ql4, b2, b3);
        }
    }

    // ---- softmax over 128 cols (rows g and g+8; cols spread over quad) ----
    {
        float mx0 = -1e30f, mx1 = -1e30f;
        #pragma unroll
        for (int nj = 0; nj < 16; nj++) {
            acc[nj][0] *= 0.125f; acc[nj][1] *= 0.125f;
            acc[nj][2] *= 0.125f; acc[nj][3] *= 0.125f;
            mx0 = fmaxf(mx0, fmaxf(acc[nj][0], acc[nj][1]));
            mx1 = fmaxf(mx1, fmaxf(acc[nj][2], acc[nj][3]));
        }
        mx0 = fmaxf(mx0, __shfl_xor_sync(~0u, mx0, 1));
        mx0 = fmaxf(mx0, __shfl_xor_sync(~0u, mx0, 2));
        mx1 = fmaxf(mx1, __shfl_xor_sync(~0u, mx1, 1));
        mx1 = fmaxf(mx1, __shfl_xor_sync(~0u, mx1, 2));
        float s0 = 0.f, s1 = 0.f;
        #pragma unroll
        for (int nj = 0; nj < 16; nj++) {
            acc[nj][0] = expf(acc[nj][0] - mx0);
            acc[nj][1] = expf(acc[nj][1] - mx0);
            acc[nj][2] = expf(acc[nj][2] - mx1);
            acc[nj][3] = expf(acc[nj][3] - mx1);
            s0 += acc[nj][0] + acc[nj][1];
            s1 += acc[nj][2] + acc[nj][3];
        }
        s0 += __shfl_xor_sync(~0u, s0, 1);
        s0 += __shfl_xor_sync(~0u, s0, 2);
        s1 += __shfl_xor_sync(~0u, s1, 1);
        s1 += __shfl_xor_sync(~0u, s1, 2);
        float i0 = 1.f / s0, i1 = 1.f / s1;
        #pragma unroll
        for (int nj = 0; nj < 16; nj++) {
            acc[nj][0] *= i0; acc[nj][1] *= i0;
            acc[nj][2] *= i1; acc[nj][3] *= i1;
        }
    }

    // ---- P @ V ----
    float o[8][4];
    #pragma unroll
    for (int nj = 0; nj < 8; nj++)
        #pragma unroll
        for (int r = 0; r < 4; r++) o[nj][r] = 0.f;

    #pragma unroll
    for (int j = 0; j < 8; j++) {
        // repack P accum frags -> A frags (hi + lo split)
        u32 pa_h[4], pa_l[4];
        #pragma unroll
        for (int q = 0; q < 2; q++) {         // q: acc frag 2j+q
            float p0 = acc[2 * j + q][0], p1 = acc[2 * j + q][1];
            float p2 = acc[2 * j + q][2], p3 = acc[2 * j + q][3];
            float h0 = bf_round(p0), h1 = bf_round(p1);
            float h2 = bf_round(p2), h3 = bf_round(p3);
            pa_h[0 + 2 * q] = pack_bf(h0, h1);
            pa_h[1 + 2 * q] = pack_bf(h2, h3);
            pa_l[0 + 2 * q] = pack_bf(p0 - h0, p1 - h1);
            pa_l[1 + 2 * q] = pack_bf(p2 - h2, p3 - h3);
        }
        // NOTE: a-frag order is {rowg-klo, rowg8-klo, rowg-khi, rowg8-khi};
        // q=0 gives k-lo pair (indices 0,1), q=1 gives k-hi pair (2,3). The
        // mapping above places them as {0:rowg-klo, 1:rowg8-klo, 2:rowg-khi,
        // 3:rowg8-khi} as required.
        #pragma unroll
        for (int c2 = 0; c2 < 4; c2++) {
            int row = j * 16 + wr + (tile & 1) * 8;
            int ch = 2 * c2 + (tile >> 1);
            u32 off = row * 128 + ((u32)(ch ^ (row & 7)) << 4);
            u32 v0, v1, v2, v3, w0, w1, w2, w3;
            ldsm4t(sVh + off, v0, v1, v2, v3);
            ldsm4t(sVl + off, w0, w1, w2, w3);
            mma_bf16(o[2 * c2],     pa_h, v0, v1);
            mma_bf16(o[2 * c2],     pa_h, w0, w1);
            mma_bf16(o[2 * c2],     pa_l, v0, v1);
            mma_bf16(o[2 * c2 + 1], pa_h, v2, v3);
            mma_bf16(o[2 * c2 + 1], pa_h, w2, w3);
            mma_bf16(o[2 * c2 + 1], pa_l, v2, v3);
        }
    }

    // ---- store O split ----
    {
        size_t gr = rowBase + m0 + g;
        #pragma unroll
        for (int nj = 0; nj < 8; nj++) {
            int col = h * HD + nj * 8 + 2 * tg;
            split_store2(aoh, aol, gr * DD + col, o[nj][0], o[nj][1]);
            split_store2(aoh, aol, (gr + 8) * DD + col, o[nj][2], o[nj][3]);
        }
    }
}

// ----------------------------------------------------------------------------
// x = LayerNorm(x + delta) * w + b; also writes bf16 split of x
// ----------------------------------------------------------------------------
__global__ __launch_bounds__(256)
void add_ln_kernel(float* __restrict__ x, const float* __restrict__ d,
                   const float* __restrict__ w, const float* __restrict__ b,
                   bf16* __restrict__ xh, bf16* __restrict__ xl)
{
    int row = blockIdx.x, t = threadIdx.x;
    float* xp = x + (size_t)row * DD;
    const float* dp = d + (size_t)row * DD;
    float v0 = xp[t]       + dp[t];
    float v1 = xp[t + 256] + dp[t + 256];
    float v2 = xp[t + 512] + dp[t + 512];
    float s = v0 + v1 + v2;
    __shared__ float red[8];
    #pragma unroll
    for (int o = 16; o; o >>= 1) s += __shfl_xor_sync(~0u, s, o);
    if ((t & 31) == 0) red[t >> 5] = s;
    __syncthreads();
    float tot = red[0] + red[1] + red[2] + red[3] + red[4] + red[5] + red[6] + red[7];
    float mu = tot * (1.f / 768.f);
    float d0 = v0 - mu, d1 = v1 - mu, d2 = v2 - mu;
    float q = d0 * d0 + d1 * d1 + d2 * d2;
    #pragma unroll
    for (int o = 16; o; o >>= 1) q += __shfl_xor_sync(~0u, q, o);
    __syncthreads();
    if ((t & 31) == 0) red[t >> 5] = q;
    __syncthreads();
    float qt = red[0] + red[1] + red[2] + red[3] + red[4] + red[5] + red[6] + red[7];
    float inv = rsqrtf(qt * (1.f / 768.f) + 1e-5f);
    float o0 = d0 * inv * w[t]       + b[t];
    float o1 = d1 * inv * w[t + 256] + b[t + 256];
    float o2 = d2 * inv * w[t + 512] + b[t + 512];
    size_t rb = (size_t)row * DD;
    xp[t] = o0;       split_write(xh, xl, rb + t,       o0);
    xp[t + 256] = o1; split_write(xh, xl, rb + t + 256, o1);
    xp[t + 512] = o2; split_write(xh, xl, rb + t + 512, o2);
}

// ----------------------------------------------------------------------------
// Host-side launch
// ----------------------------------------------------------------------------
template<typename T>
static T* sym(const void* s)
{
    void* p = nullptr;
    cudaGetSymbolAddress(&p, s);
    return (T*)p;
}

#define SMEM128 (3 * (2 * 128 * 64 + 2 * 128 * 64))   // 98304
#define SMEM64  (3 * (2 * 128 * 64 + 2 * 64  * 64))   // 73728
#define SMEMATT (6 * 16384)                            // 98304

extern "C" void kernel_launch(void* const* d_in, const int* in_sizes, int n_in,
                              void* d_out, int out_size)
{
    static const long long want[20] = {
        6291456LL, 65536LL, 2048LL, 768LL, 1LL,
        7077888LL, 9216LL, 2359296LL, 3072LL, 3072LL, 3072LL,
        9437184LL, 12288LL, 9437184LL, 3072LL, 3072LL, 3072LL,
        76800LL, 5000000LL, 50000LL
    };
    const void* slot[20];
    bool used[64];
    for (int i = 0; i < 20; i++) slot[i] = nullptr;
    for (int i = 0; i < n_in && i < 64; i++) used[i] = false;
    for (int w = 0; w < 20; w++) {
        for (int i = 0; i < n_in && i < 64; i++) {
            if (!used[i] && (long long)in_sizes[i] == want[w]) {
                slot[w] = d_in[i];
                used[i] = true;
                break;
            }
        }
    }
    if (!slot[0]) {
        for (int w = 0; w < 20 && w < n_in; w++) slot[w] = d_in[w];
    }

    const float* lhs    = (const float*)slot[0];
    const int*   pos    = (const int*)slot[1];
    const int*   mask   = (const int*)slot[2];
    const float* attn_w = (const float*)slot[3];
    const float* qkv_w  = (const float*)slot[5];
    const float* qkv_b  = (const float*)slot[6];
    const float* out_w  = (const float*)slot[7];
    const float* out_b  = (const float*)slot[8];
    const float* ln1_w  = (const float*)slot[9];
    const float* ln1_b  = (const float*)slot[10];
    const float* ff1_w  = (const float*)slot[11];
    const float* ff1_b  = (const float*)slot[12];
    const float* ff2_w  = (const float*)slot[13];
    const float* ff2_b  = (const float*)slot[14];
    const float* ln2_w  = (const float*)slot[15];
    const float* ln2_b  = (const float*)slot[16];
    const float* cls_w1 = (const float*)slot[17];
    const float* cls_w2 = (const float*)slot[18];
    const float* cls_b2 = (const float*)slot[19];
    float* out = (float*)d_out;

    float* hl  = sym<float>(g_hl);
    float* x   = sym<float>(g_x);
    float* tmp = sym<float>(g_tmp);
    bf16*  wh  = sym<bf16>(g_wh);
    bf16*  wl  = sym<bf16>(g_wl);
    bf16*  ah  = sym<bf16>(g_ah);
    bf16*  al  = sym<bf16>(g_al);
    bf16*  bh2 = sym<bf16>(g_bh);
    bf16*  bl2 = sym<bf16>(g_bl);

    cudaFuncSetAttribute(gemm_tc<128, 0, 0>, cudaFuncAttributeMaxDynamicSharedMemorySize, SMEM128);
    cudaFuncSetAttribute(gemm_tc<128, 0, 1>, cudaFuncAttributeMaxDynamicSharedMemorySize, SMEM128);
    cudaFuncSetAttribute(gemm_tc<128, 1, 1>, cudaFuncAttributeMaxDynamicSharedMemorySize, SMEM128);
    cudaFuncSetAttribute(gemm_tc<64, 0, 0>,  cudaFuncAttributeMaxDynamicSharedMemorySize, SMEM64);
    cudaFuncSetAttribute(gemm_tc<64, 0, 1>,  cudaFuncAttributeMaxDynamicSharedMemorySize, SMEM64);
    cudaFuncSetAttribute(attn_fused, cudaFuncAttributeMaxDynamicSharedMemorySize, SMEMATT);

    // --- weight conversion (every launch; deterministic) ---
    cvt_kernel<<<2048, 256>>>(qkv_w,  wh + OW_QKV,  wl + OW_QKV,  7077888);
    cvt_kernel<<<1024, 256>>>(out_w,  wh + OW_OUT,  wl + OW_OUT,  2359296);
    cvt_kernel<<<2048, 256>>>(ff1_w,  wh + OW_FF1,  wl + OW_FF1,  9437184);
    cvt_kernel<<<2048, 256>>>(ff2_w,  wh + OW_FF2,  wl + OW_FF2,  9437184);
    cvt_kernel<<<64,   256>>>(cls_w1, wh + OW_CLS1, wl + OW_CLS1, 76800);
    cvt_pad_kernel<<<2048, 256>>>(cls_w2, wh + OW_CLS2, wl + OW_CLS2);

    // --- mention pooling (writes x + split) ---
    hl_kernel<<<BB * LL, 256>>>(lhs, attn_w, hl);
    pool_kernel<<<ROWS, 256>>>(lhs, pos, mask, hl, x, ah, al);

    // --- transformer layers ---
    for (int i = 0; i < NL; i++) {
        gemm_tc<128, 0, 1><<<dim3(3 * DD / 128, ROWS / 128), 256, SMEM128>>>(
            ah, al, wh + OW_QKV + (size_t)i * 3 * DD * DD,
            wl + OW_QKV + (size_t)i * 3 * DD * DD,
            qkv_b + (size_t)i * 3 * DD, nullptr, bh2, bl2,
            ROWS, 3 * DD, DD, 3 * DD, 3 * DD);
        attn_fused<<<BB * HH, 256, SMEMATT>>>(bh2, bl2, ah, al);
        gemm_tc<64, 0, 0><<<dim3(DD / 64, ROWS / 128), 256, SMEM64>>>(
            ah, al, wh + OW_OUT + (size_t)i * DD * DD,
            wl + OW_OUT + (size_t)i * DD * DD,
            out_b + (size_t)i * DD, tmp, nullptr, nullptr,
            ROWS, DD, DD, DD, DD);
        add_ln_kernel<<<ROWS, 256>>>(x, tmp, ln1_w + (size_t)i * DD,
                                     ln1_b + (size_t)i * DD, ah, al);
        gemm_tc<128, 1, 1><<<dim3(DFF / 128, ROWS / 128), 256, SMEM128>>>(
            ah, al, wh + OW_FF1 + (size_t)i * DFF * DD,
            wl + OW_FF1 + (size_t)i * DFF * DD,
            ff1_b + (size_t)i * DFF, nullptr, bh2, bl2,
            ROWS, DFF, DD, DFF, DFF);
        gemm_tc<64, 0, 0><<<dim3(DD / 64, ROWS / 128), 256, SMEM64>>>(
            bh2, bl2, wh + OW_FF2 + (size_t)i * DD * DFF,
            wl + OW_FF2 + (size_t)i * DD * DFF,
            ff2_b + (size_t)i * DD, tmp, nullptr, nullptr,
            ROWS, DD, DFF, DD, DD);
        add_ln_kernel<<<ROWS, 256>>>(x, tmp, ln2_w + (size_t)i * DD,
                                     ln2_b + (size_t)i * DD, ah, al);
    }

    // --- classifier head ---
    gemm_tc<64, 0, 1><<<dim3(2, ROWS / 128), 256, SMEM64>>>(
        ah, al, wh + OW_CLS1, wl + OW_CLS1, nullptr,
        nullptr, bh2, bl2, ROWS, 100, DD, KPAD, KPAD);
    gemm_tc<128, 0, 0><<<dim3((NE + 127) / 128, ROWS / 128), 256, SMEM128>>>(
        bh2, bl2, wh + OW_CLS2, wl + OW_CLS2, cls_b2,
        out, nullptr, nullptr, ROWS, NE, KPAD, NE, NE);
}

// round 8
// speedup vs baseline: 4.0997x; 1.1726x over previous
#include <cuda_runtime.h>
#include <cuda_bf16.h>
#include <math.h>
#include <cstdint>

// ----------------------------------------------------------------------------
// Problem constants
// ----------------------------------------------------------------------------
#define BB   16
#define MM   128
#define LL   32
#define SS   512
#define DD   768
#define HH   12
#define HD   64
#define DFF  3072
#define NL   4
#define NE   50000
#define ROWS (BB*MM)          // 2048
#define KPAD 112              // padded K for classifier stage 2

typedef unsigned long long ull;
typedef unsigned int u32;
typedef __nv_bfloat16 bf16;

// weight scratch offsets (elements)
#define OW_QKV  0ULL
#define OW_OUT  7077888ULL
#define OW_FF1  9437184ULL
#define OW_FF2  18874368ULL
#define OW_CLS1 28311552ULL
#define OW_CLS2 28388352ULL
#define NW_TOT  (28388352ULL + 50000ULL*KPAD)

// ----------------------------------------------------------------------------
// Device scratch (static allocation — no cudaMalloc allowed)
// ----------------------------------------------------------------------------
__device__ float g_hl[BB*LL];
__device__ float g_x [ROWS*DD];
__device__ float g_tmp[ROWS*DFF];
__device__ __align__(256) bf16 g_wh[NW_TOT];
__device__ __align__(256) bf16 g_wl[NW_TOT];
__device__ __align__(256) bf16 g_ah[ROWS*DFF];
__device__ __align__(256) bf16 g_al[ROWS*DFF];
__device__ __align__(256) bf16 g_bh[ROWS*DFF];
__device__ __align__(256) bf16 g_bl[ROWS*DFF];

// ----------------------------------------------------------------------------
// PTX helpers
// ----------------------------------------------------------------------------
__device__ __forceinline__ u32 smem_u32(const void* p)
{
    u32 a;
    asm("{ .reg .u64 t; cvta.to.shared.u64 t, %1; cvt.u32.u64 %0, t; }"
        : "=r"(a) : "l"(p));
    return a;
}

__device__ __forceinline__ void cp_async16(u32 dst, const void* src, int sz)
{
    asm volatile("cp.async.cg.shared.global [%0], [%1], 16, %2;"
        :: "r"(dst), "l"(src), "r"(sz));
}
#define CP_COMMIT() asm volatile("cp.async.commit_group;" ::: "memory")
#define CP_WAIT1()  asm volatile("cp.async.wait_group 1;" ::: "memory")
#define CP_WAIT0()  asm volatile("cp.async.wait_group 0;" ::: "memory")

__device__ __forceinline__ void ldsm4(u32 addr, u32& r0, u32& r1, u32& r2, u32& r3)
{
    asm volatile("ldmatrix.sync.aligned.m8n8.x4.shared.b16 {%0,%1,%2,%3}, [%4];"
        : "=r"(r0), "=r"(r1), "=r"(r2), "=r"(r3) : "r"(addr));
}
__device__ __forceinline__ void ldsm4t(u32 addr, u32& r0, u32& r1, u32& r2, u32& r3)
{
    asm volatile("ldmatrix.sync.aligned.m8n8.x4.trans.shared.b16 {%0,%1,%2,%3}, [%4];"
        : "=r"(r0), "=r"(r1), "=r"(r2), "=r"(r3) : "r"(addr));
}

__device__ __forceinline__ void mma_bf16(float* d, const u32* a, u32 b0, u32 b1)
{
    asm volatile(
        "mma.sync.aligned.m16n8k16.row.col.f32.bf16.bf16.f32 "
        "{%0,%1,%2,%3},{%4,%5,%6,%7},{%8,%9},{%0,%1,%2,%3};"
        : "+f"(d[0]), "+f"(d[1]), "+f"(d[2]), "+f"(d[3])
        : "r"(a[0]), "r"(a[1]), "r"(a[2]), "r"(a[3]), "r"(b0), "r"(b1));
}

// pack two fp32 into bf16x2 word: lo at lower halfword
__device__ __forceinline__ u32 pack_bf(float lo, float hi)
{
    u32 r;
    asm("cvt.rn.bf16x2.f32 %0, %1, %2;" : "=r"(r) : "f"(hi), "f"(lo));
    return r;
}

__device__ __forceinline__ float bf_round(float v)
{
    return __bfloat162float(__float2bfloat16(v));
}

__device__ __forceinline__ void split_write(bf16* h, bf16* l, size_t idx, float v)
{
    bf16 hh = __float2bfloat16(v);
    h[idx] = hh;
    l[idx] = __float2bfloat16(v - __bfloat162float(hh));
}

// packed pair store (idx even, arrays 4B-aligned)
__device__ __forceinline__ void split_store2(bf16* h, bf16* l, size_t idx,
                                             float v0, float v1)
{
    float h0 = bf_round(v0), h1 = bf_round(v1);
    *(u32*)(h + idx) = pack_bf(h0, h1);
    *(u32*)(l + idx) = pack_bf(v0 - h0, v1 - h1);
}

// ----------------------------------------------------------------------------
// weight fp32 -> bf16 hi/lo split, 8 elems/thread/iter (n % 8 == 0)
// ----------------------------------------------------------------------------
__global__ void cvt_kernel(const float* __restrict__ x,
                           bf16* __restrict__ h, bf16* __restrict__ l, int n)
{
    int n8 = n >> 3;
    for (int i = blockIdx.x * 256 + threadIdx.x; i < n8; i += gridDim.x * 256) {
        const float4* xp = (const float4*)x + 2 * (size_t)i;
        float4 a = xp[0], b = xp[1];
        float h0 = bf_round(a.x), h1 = bf_round(a.y),
              h2 = bf_round(a.z), h3 = bf_round(a.w),
              h4 = bf_round(b.x), h5 = bf_round(b.y),
              h6 = bf_round(b.z), h7 = bf_round(b.w);
        uint4 H, L;
        H.x = pack_bf(h0, h1); H.y = pack_bf(h2, h3);
        H.z = pack_bf(h4, h5); H.w = pack_bf(h6, h7);
        L.x = pack_bf(a.x - h0, a.y - h1); L.y = pack_bf(a.z - h2, a.w - h3);
        L.z = pack_bf(b.x - h4, b.y - h5); L.w = pack_bf(b.z - h6, b.w - h7);
        ((uint4*)h)[i] = H;
        ((uint4*)l)[i] = L;
    }
}

// cls_w2: [NE,100] -> [NE,112] zero-padded split (4 cols/thread/iter)
__global__ void cvt_pad_kernel(const float* __restrict__ x,
                               bf16* __restrict__ h, bf16* __restrict__ l)
{
    int total = NE * 28;
    for (int i = blockIdx.x * 256 + threadIdx.x; i < total; i += gridDim.x * 256) {
        int r = i / 28, c4 = (i - r * 28) * 4;
        u32 ha = 0, hb = 0, la = 0, lb = 0;
        if (c4 < 100) {
            float4 v = *(const float4*)(x + (size_t)r * 100 + c4);
            float h0 = bf_round(v.x), h1 = bf_round(v.y),
                  h2 = bf_round(v.z), h3 = bf_round(v.w);
            ha = pack_bf(h0, h1); hb = pack_bf(h2, h3);
            la = pack_bf(v.x - h0, v.y - h1); lb = pack_bf(v.z - h2, v.w - h3);
        }
        size_t o = (size_t)r * KPAD + c4;
        *(uint2*)(h + o) = make_uint2(ha, hb);
        *(uint2*)(l + o) = make_uint2(la, lb);
    }
}

// ----------------------------------------------------------------------------
// hl[b,l] = dot(hidden[b,l,:], attn_w)
// ----------------------------------------------------------------------------
__global__ void hl_kernel(const float* __restrict__ lhs,
                          const float* __restrict__ aw,
                          float* __restrict__ hl)
{
    int blk = blockIdx.x;
    int b = blk >> 5, l = blk & 31;
    const float* row = lhs + ((size_t)b * SS + l) * DD;
    int t = threadIdx.x;
    float p = 0.f;
    for (int i = t; i < DD; i += 256) p += row[i] * aw[i];
    #pragma unroll
    for (int o = 16; o; o >>= 1) p += __shfl_xor_sync(~0u, p, o);
    __shared__ float red[8];
    if ((t & 31) == 0) red[t >> 5] = p;
    __syncthreads();
    if (t == 0) {
        float s = 0.f;
        #pragma unroll
        for (int i = 0; i < 8; i++) s += red[i];
        hl[b * LL + l] = s;
    }
}

// ----------------------------------------------------------------------------
// Mention pooling (pos/mask int32). Writes x fp32 + bf16 split.
// ----------------------------------------------------------------------------
__global__ void pool_kernel(const float* __restrict__ lhs,
                            const int* __restrict__ pos,
                            const int* __restrict__ mask,
                            const float* __restrict__ hl,
                            float* __restrict__ x,
                            bf16* __restrict__ xh, bf16* __restrict__ xl)
{
    int bm = blockIdx.x;
    int b = bm >> 7;
    int t = threadIdx.x;
    __shared__ float ws[LL];
    __shared__ int s_nv;
    if (t < 32) {
        int p = pos[(size_t)bm * LL + t];
        unsigned bits = __ballot_sync(0xffffffffu, p != -1);
        int nv;
        if (mask[bm] == 0) nv = 0;
        else if (~bits == 0u) nv = 32;
        else nv = __ffs(~bits) - 1;
        float logit = (t < nv) ? hl[b * LL + t] : 0.f;
        float mx = logit;
        #pragma unroll
        for (int o = 16; o; o >>= 1) mx = fmaxf(mx, __shfl_xor_sync(~0u, mx, o));
        float e = expf(logit - mx);
        float s = e;
        #pragma unroll
        for (int o = 16; o; o >>= 1) s += __shfl_xor_sync(~0u, s, o);
        ws[t] = e / s;
        if (t == 0) s_nv = nv;
    }
    __syncthreads();
    int nv = s_nv;
    for (int d = t; d < DD; d += 256) {
        float acc = 0.f;
        for (int l = 0; l < nv; l++)
            acc += ws[l] * lhs[((size_t)b * SS + l) * DD + d];
        size_t idx = (size_t)bm * DD + d;
        x[idx] = acc;
        split_write(xh, xl, idx, acc);
    }
}

// ----------------------------------------------------------------------------
// Tensor-core split-bf16 NT GEMM: mma.sync + ldmatrix + 3-stage cp.async ring.
// 2 CTAs/SM for latency hiding + wave packing.
// C[M,N] = A*B^T (+bias, opt relu). BK=32, XOR-swizzled 64B rows.
// 8 warps: 4m x 2n, warp tile 32 x TN/2. M%128==0; N,K guarded; N even.
// SPLIT=0 -> fp32 C; SPLIT=1 -> bf16 hi/lo, cols [N,padN) zero-filled.
// ----------------------------------------------------------------------------
template<int TN, int RELU, int SPLIT>
__global__ __launch_bounds__(256, 2)
void gemm_tc(const bf16* __restrict__ Ah, const bf16* __restrict__ Al,
             const bf16* __restrict__ Bh, const bf16* __restrict__ Bl,
             const float* __restrict__ bias,
             float* __restrict__ C, bf16* __restrict__ Ch, bf16* __restrict__ Cl,
             int M, int N, int K, int ldout, int padN)
{
    constexpr int NJW = TN / 16;
    constexpr int ASZ = 128 * 64;
    constexpr int BSZ = TN * 64;
    constexpr int BUF = 2 * ASZ + 2 * BSZ;

    extern __shared__ char smem[];
    const u32 base = smem_u32(smem);
    const int t = threadIdx.x, lane = t & 31, warp = t >> 5;
    const int mBase = blockIdx.y * 128, nBase = blockIdx.x * TN;
    const int wm = (warp >> 1) * 32, wn = (warp & 1) * (TN / 2);
    const int ar0 = wm + (lane & 15);
    const int ahi = lane >> 4;
    const int br0 = wn + (lane & 7) + ((lane >> 4) << 3);
    const int bhi = (lane >> 3) & 1;

    float acc[2][NJW][4];
    #pragma unroll
    for (int mi = 0; mi < 2; mi++)
        #pragma unroll
        for (int nj = 0; nj < NJW; nj++)
            #pragma unroll
            for (int r = 0; r < 4; r++) acc[mi][nj][r] = 0.f;

    const int S = (K + 31) / 32;

    auto loadSlab = [&](int s) {
        const int k0 = s * 32;
        const u32 bb = base + (s % 3) * BUF;
        #pragma unroll
        for (int p = 0; p < 2; p++) {
            int c = p * 256 + t, row = c >> 2, ch = c & 3;
            int kk = k0 + ch * 8;
            int avail = K - kk;
            int sz = (avail >= 8) ? 16 : (avail > 0 ? avail * 2 : 0);
            u32 off = row * 64 + ((u32)(ch ^ ((row >> 1) & 3)) << 4);
            cp_async16(bb + off, Ah + (size_t)(mBase + row) * K + kk, sz);
            cp_async16(bb + ASZ + off, Al + (size_t)(mBase + row) * K + kk, sz);
        }
        #pragma unroll
        for (int p = 0; p < TN / 64; p++) {
            int c = p * 256 + t, row = c >> 2, ch = c & 3;
            int kk = k0 + ch * 8;
            int avail = K - kk;
            int sz = (avail >= 8) ? 16 : (avail > 0 ? avail * 2 : 0);
            if (nBase + row >= N) sz = 0;
            u32 off = row * 64 + ((u32)(ch ^ ((row >> 1) & 3)) << 4);
            cp_async16(bb + 2 * ASZ + off, Bh + (size_t)(nBase + row) * K + kk, sz);
            cp_async16(bb + 2 * ASZ + BSZ + off, Bl + (size_t)(nBase + row) * K + kk, sz);
        }
    };

    loadSlab(0);
    CP_COMMIT();
    if (S > 1) loadSlab(1);
    CP_COMMIT();

    for (int s = 0; s < S; s++) {
        CP_WAIT1();
        __syncthreads();
        if (s + 2 < S) loadSlab(s + 2);
        CP_COMMIT();

        const u32 bb = base + (s % 3) * BUF;
        const u32 aB0 = bb, aB1 = bb + ASZ;
        const u32 bB0 = bb + 2 * ASZ, bB1 = bb + 2 * ASZ + BSZ;

        #pragma unroll
        for (int ks = 0; ks < 2; ks++) {
            u32 ahf[2][4], alf[2][4];
            #pragma unroll
            for (int mi = 0; mi < 2; mi++) {
                int row = ar0 + mi * 16;
                u32 off = row * 64 + ((u32)((ks * 2 + ahi) ^ ((row >> 1) & 3)) << 4);
                ldsm4(aB0 + off, ahf[mi][0], ahf[mi][1], ahf[mi][2], ahf[mi][3]);
                ldsm4(aB1 + off, alf[mi][0], alf[mi][1], alf[mi][2], alf[mi][3]);
            }
            #pragma unroll
            for (int j = 0; j < NJW / 2; j++) {
                int row = br0 + j * 16;
                u32 off = row * 64 + ((u32)((ks * 2 + bhi) ^ ((row >> 1) & 3)) << 4);
                u32 b0, b1, b2, b3, l0, l1, l2, l3;
                ldsm4(bB0 + off, b0, b1, b2, b3);
                ldsm4(bB1 + off, l0, l1, l2, l3);
                #pragma unroll
                for (int mi = 0; mi < 2; mi++) {
                    mma_bf16(acc[mi][2 * j],     ahf[mi], b0, b1);
                    mma_bf16(acc[mi][2 * j],     ahf[mi], l0, l1);
                    mma_bf16(acc[mi][2 * j],     alf[mi], b0, b1);
                    mma_bf16(acc[mi][2 * j + 1], ahf[mi], b2, b3);
                    mma_bf16(acc[mi][2 * j + 1], ahf[mi], l2, l3);
                    mma_bf16(acc[mi][2 * j + 1], alf[mi], b2, b3);
                }
            }
        }
    }

    // epilogue (packed pair stores; all N/padN even)
    const int g = lane >> 2, tg = lane & 3;
    #pragma unroll
    for (int mi = 0; mi < 2; mi++) {
        int row0 = mBase + wm + mi * 16 + g;
        #pragma unroll
        for (int nj = 0; nj < NJW; nj++) {
            int col0 = nBase + wn + nj * 8 + 2 * tg;
            if (col0 < padN) {
                #pragma unroll
                for (int rr = 0; rr < 2; rr++) {
                    int row = row0 + rr * 8;
                    float v0 = 0.f, v1 = 0.f;
                    if (col0 < N) {
                        v0 = acc[mi][nj][rr * 2 + 0] + (bias ? bias[col0] : 0.f);
                        v1 = acc[mi][nj][rr * 2 + 1] + (bias ? bias[col0 + 1] : 0.f);
                        if (RELU) { v0 = fmaxf(v0, 0.f); v1 = fmaxf(v1, 0.f); }
                    }
                    if (SPLIT)
                        split_store2(Ch, Cl, (size_t)row * ldout + col0, v0, v1);
                    else
                        *(float2*)(C + (size_t)row * ldout + col0) = make_float2(v0, v1);
                }
            }
        }
    }
}

// ----------------------------------------------------------------------------
// Fused attention: one CTA per (b,h), 8 warps x 16 Q-rows.
// ----------------------------------------------------------------------------
__global__ __launch_bounds__(256)
void attn_fused(const bf16* __restrict__ qkvh, const bf16* __restrict__ qkvl,
                bf16* __restrict__ aoh, bf16* __restrict__ aol)
{
    extern __shared__ char smem[];
    const u32 base = smem_u32(smem);
    const int t = threadIdx.x, lane = t & 31, warp = t >> 5;
    const int bh = blockIdx.x, b = bh / HH, h = bh % HH;
    const size_t rowBase = (size_t)b * MM;
    const int g = lane >> 2, tg = lane & 3;

    #pragma unroll
    for (int m = 0; m < 6; m++) {
        const bf16* src = (m & 1) ? qkvl : qkvh;
        int colOff = (m >> 1) * DD + h * HD;
        u32 dst = base + m * 16384;
        #pragma unroll
        for (int p = 0; p < 4; p++) {
            int c = p * 256 + t;
            int row = c >> 3, ch = c & 7;
            u32 off = row * 128 + ((u32)(ch ^ (row & 7)) << 4);
            cp_async16(dst + off,
                       src + (rowBase + row) * (3 * DD) + colOff + ch * 8, 16);
        }
    }
    CP_COMMIT(); CP_WAIT0();
    __syncthreads();

    const u32 sQh = base, sQl = base + 16384;
    const u32 sKh = base + 32768, sKl = base + 49152;
    const u32 sVh = base + 65536, sVl = base + 81920;
    const int m0 = warp * 16;

    float acc[16][4];
    #pragma unroll
    for (int nj = 0; nj < 16; nj++)
        #pragma unroll
        for (int r = 0; r < 4; r++) acc[nj][r] = 0.f;

    const int tile = lane >> 3, wr = lane & 7;
    #pragma unroll
    for (int kk = 0; kk < 4; kk++) {
        u32 qh4[4], ql4[4];
        {
            int row = m0 + wr + (tile & 1) * 8;
            int ch = kk * 2 + (tile >> 1);
            u32 off = row * 128 + ((u32)(ch ^ (row & 7)) << 4);
            ldsm4(sQh + off, qh4[0], qh4[1], qh4[2], qh4[3]);
            ldsm4(sQl + off, ql4[0], ql4[1], ql4[2], ql4[3]);
        }
        #pragma unroll
        for (int nj2 = 0; nj2 < 8; nj2++) {
            int row = nj2 * 16 + wr + (tile >> 1) * 8;
            int ch = kk * 2 + (tile & 1);
            u32 off = row * 128 + ((u32)(ch ^ (row & 7)) << 4);
            u32 b0, b1, b2, b3, l0, l1, l2, l3;
            ldsm4(sKh + off, b0, b1, b2, b3);
            ldsm4(sKl + off, l0, l1, l2, l3);
            mma_bf16(acc[2 * nj2],     qh4, b0, b1);
            mma_bf16(acc[2 * nj2],     qh4, l0, l1);
            mma_bf16(acc[2 * nj2],     ql4, b0, b1);
            mma_bf16(acc[2 * nj2 + 1], qh4, b2, b3);
            mma_bf16(acc[2 * nj2 + 1], qh4, l2, l3);
            mma_bf16(acc[2 * nj2 + 1], ql4, b2, b3);
        }
    }

    {
        float mx0 = -1e30f, mx1 = -1e30f;
        #pragma unroll
        for (int nj = 0; nj < 16; nj++) {
            acc[nj][0] *= 0.125f; acc[nj][1] *= 0.125f;
            acc[nj][2] *= 0.125f; acc[nj][3] *= 0.125f;
            mx0 = fmaxf(mx0, fmaxf(acc[nj][0], acc[nj][1]));
            mx1 = fmaxf(mx1, fmaxf(acc[nj][2], acc[nj][3]));
        }
        mx0 = fmaxf(mx0, __shfl_xor_sync(~0u, mx0, 1));
        mx0 = fmaxf(mx0, __shfl_xor_sync(~0u, mx0, 2));
        mx1 = fmaxf(mx1, __shfl_xor_sync(~0u, mx1, 1));
        mx1 = fmaxf(mx1, __shfl_xor_sync(~0u, mx1, 2));
        float s0 = 0.f, s1 = 0.f;
        #pragma unroll
        for (int nj = 0; nj < 16; nj++) {
            acc[nj][0] = expf(acc[nj][0] - mx0);
            acc[nj][1] = expf(acc[nj][1] - mx0);
            acc[nj][2] = expf(acc[nj][2] - mx1);
            acc[nj][3] = expf(acc[nj][3] - mx1);
            s0 += acc[nj][0] + acc[nj][1];
            s1 += acc[nj][2] + acc[nj][3];
        }
        s0 += __shfl_xor_sync(~0u, s0, 1);
        s0 += __shfl_xor_sync(~0u, s0, 2);
        s1 += __shfl_xor_sync(~0u, s1, 1);
        s1 += __shfl_xor_sync(~0u, s1, 2);
        float i0 = 1.f / s0, i1 = 1.f / s1;
        #pragma unroll
        for (int nj = 0; nj < 16; nj++) {
            acc[nj][0] *= i0; acc[nj][1] *= i0;
            acc[nj][2] *= i1; acc[nj][3] *= i1;
        }
    }

    float o[8][4];
    #pragma unroll
    for (int nj = 0; nj < 8; nj++)
        #pragma unroll
        for (int r = 0; r < 4; r++) o[nj][r] = 0.f;

    #pragma unroll
    for (int j = 0; j < 8; j++) {
        u32 pa_h[4], pa_l[4];
        #pragma unroll
        for (int q = 0; q < 2; q++) {
            float p0 = acc[2 * j + q][0], p1 = acc[2 * j + q][1];
            float p2 = acc[2 * j + q][2], p3 = acc[2 * j + q][3];
            float h0 = bf_round(p0), h1 = bf_round(p1);
            float h2 = bf_round(p2), h3 = bf_round(p3);
            pa_h[0 + 2 * q] = pack_bf(h0, h1);
            pa_h[1 + 2 * q] = pack_bf(h2, h3);
            pa_l[0 + 2 * q] = pack_bf(p0 - h0, p1 - h1);
            pa_l[1 + 2 * q] = pack_bf(p2 - h2, p3 - h3);
        }
        #pragma unroll
        for (int c2 = 0; c2 < 4; c2++) {
            int row = j * 16 + wr + (tile & 1) * 8;
            int ch = 2 * c2 + (tile >> 1);
            u32 off = row * 128 + ((u32)(ch ^ (row & 7)) << 4);
            u32 v0, v1, v2, v3, w0, w1, w2, w3;
            ldsm4t(sVh + off, v0, v1, v2, v3);
            ldsm4t(sVl + off, w0, w1, w2, w3);
            mma_bf16(o[2 * c2],     pa_h, v0, v1);
            mma_bf16(o[2 * c2],     pa_h, w0, w1);
            mma_bf16(o[2 * c2],     pa_l, v0, v1);
            mma_bf16(o[2 * c2 + 1], pa_h, v2, v3);
            mma_bf16(o[2 * c2 + 1], pa_h, w2, w3);
            mma_bf16(o[2 * c2 + 1], pa_l, v2, v3);
        }
    }

    {
        size_t gr = rowBase + m0 + g;
        #pragma unroll
        for (int nj = 0; nj < 8; nj++) {
            int col = h * HD + nj * 8 + 2 * tg;
            split_store2(aoh, aol, gr * DD + col, o[nj][0], o[nj][1]);
            split_store2(aoh, aol, (gr + 8) * DD + col, o[nj][2], o[nj][3]);
        }
    }
}

// ----------------------------------------------------------------------------
// x = LayerNorm(x + delta) * w + b; also writes bf16 split of x
// ----------------------------------------------------------------------------
__global__ __launch_bounds__(256)
void add_ln_kernel(float* __restrict__ x, const float* __restrict__ d,
                   const float* __restrict__ w, const float* __restrict__ b,
                   bf16* __restrict__ xh, bf16* __restrict__ xl)
{
    int row = blockIdx.x, t = threadIdx.x;
    float* xp = x + (size_t)row * DD;
    const float* dp = d + (size_t)row * DD;
    float v0 = xp[t]       + dp[t];
    float v1 = xp[t + 256] + dp[t + 256];
    float v2 = xp[t + 512] + dp[t + 512];
    float s = v0 + v1 + v2;
    __shared__ float red[8];
    #pragma unroll
    for (int o = 16; o; o >>= 1) s += __shfl_xor_sync(~0u, s, o);
    if ((t & 31) == 0) red[t >> 5] = s;
    __syncthreads();
    float tot = red[0] + red[1] + red[2] + red[3] + red[4] + red[5] + red[6] + red[7];
    float mu = tot * (1.f / 768.f);
    float d0 = v0 - mu, d1 = v1 - mu, d2 = v2 - mu;
    float q = d0 * d0 + d1 * d1 + d2 * d2;
    #pragma unroll
    for (int o = 16; o; o >>= 1) q += __shfl_xor_sync(~0u, q, o);
    __syncthreads();
    if ((t & 31) == 0) red[t >> 5] = q;
    __syncthreads();
    float qt = red[0] + red[1] + red[2] + red[3] + red[4] + red[5] + red[6] + red[7];
    float inv = rsqrtf(qt * (1.f / 768.f) + 1e-5f);
    float o0 = d0 * inv * w[t]       + b[t];
    float o1 = d1 * inv * w[t + 256] + b[t + 256];
    float o2 = d2 * inv * w[t + 512] + b[t + 512];
    size_t rb = (size_t)row * DD;
    xp[t] = o0;       split_write(xh, xl, rb + t,       o0);
    xp[t + 256] = o1; split_write(xh, xl, rb + t + 256, o1);
    xp[t + 512] = o2; split_write(xh, xl, rb + t + 512, o2);
}

// ----------------------------------------------------------------------------
// Host-side launch
// ----------------------------------------------------------------------------
template<typename T>
static T* sym(const void* s)
{
    void* p = nullptr;
    cudaGetSymbolAddress(&p, s);
    return (T*)p;
}

#define SMEM128 (3 * (2 * 128 * 64 + 2 * 128 * 64))   // 98304
#define SMEM64  (3 * (2 * 128 * 64 + 2 * 64  * 64))   // 73728
#define SMEMATT (6 * 16384)                            // 98304

extern "C" void kernel_launch(void* const* d_in, const int* in_sizes, int n_in,
                              void* d_out, int out_size)
{
    static const long long want[20] = {
        6291456LL, 65536LL, 2048LL, 768LL, 1LL,
        7077888LL, 9216LL, 2359296LL, 3072LL, 3072LL, 3072LL,
        9437184LL, 12288LL, 9437184LL, 3072LL, 3072LL, 3072LL,
        76800LL, 5000000LL, 50000LL
    };
    const void* slot[20];
    bool used[64];
    for (int i = 0; i < 20; i++) slot[i] = nullptr;
    for (int i = 0; i < n_in && i < 64; i++) used[i] = false;
    for (int w = 0; w < 20; w++) {
        for (int i = 0; i < n_in && i < 64; i++) {
            if (!used[i] && (long long)in_sizes[i] == want[w]) {
                slot[w] = d_in[i];
                used[i] = true;
                break;
            }
        }
    }
    if (!slot[0]) {
        for (int w = 0; w < 20 && w < n_in; w++) slot[w] = d_in[w];
    }

    const float* lhs    = (const float*)slot[0];
    const int*   pos    = (const int*)slot[1];
    const int*   mask   = (const int*)slot[2];
    const float* attn_w = (const float*)slot[3];
    const float* qkv_w  = (const float*)slot[5];
    const float* qkv_b  = (const float*)slot[6];
    const float* out_w  = (const float*)slot[7];
    const float* out_b  = (const float*)slot[8];
    const float* ln1_w  = (const float*)slot[9];
    const float* ln1_b  = (const float*)slot[10];
    const float* ff1_w  = (const float*)slot[11];
    const float* ff1_b  = (const float*)slot[12];
    const float* ff2_w  = (const float*)slot[13];
    const float* ff2_b  = (const float*)slot[14];
    const float* ln2_w  = (const float*)slot[15];
    const float* ln2_b  = (const float*)slot[16];
    const float* cls_w1 = (const float*)slot[17];
    const float* cls_w2 = (const float*)slot[18];
    const float* cls_b2 = (const float*)slot[19];
    float* out = (float*)d_out;

    float* hl  = sym<float>(g_hl);
    float* x   = sym<float>(g_x);
    float* tmp = sym<float>(g_tmp);
    bf16*  wh  = sym<bf16>(g_wh);
    bf16*  wl  = sym<bf16>(g_wl);
    bf16*  ah  = sym<bf16>(g_ah);
    bf16*  al  = sym<bf16>(g_al);
    bf16*  bh2 = sym<bf16>(g_bh);
    bf16*  bl2 = sym<bf16>(g_bl);

    cudaFuncSetAttribute(gemm_tc<128, 0, 0>, cudaFuncAttributeMaxDynamicSharedMemorySize, SMEM128);
    cudaFuncSetAttribute(gemm_tc<128, 0, 1>, cudaFuncAttributeMaxDynamicSharedMemorySize, SMEM128);
    cudaFuncSetAttribute(gemm_tc<128, 1, 1>, cudaFuncAttributeMaxDynamicSharedMemorySize, SMEM128);
    cudaFuncSetAttribute(gemm_tc<64, 0, 0>,  cudaFuncAttributeMaxDynamicSharedMemorySize, SMEM64);
    cudaFuncSetAttribute(gemm_tc<64, 0, 1>,  cudaFuncAttributeMaxDynamicSharedMemorySize, SMEM64);
    cudaFuncSetAttribute(attn_fused, cudaFuncAttributeMaxDynamicSharedMemorySize, SMEMATT);

    // --- weight conversion (every launch; deterministic) ---
    cvt_kernel<<<3456, 256>>>(qkv_w,  wh + OW_QKV,  wl + OW_QKV,  7077888);
    cvt_kernel<<<1152, 256>>>(out_w,  wh + OW_OUT,  wl + OW_OUT,  2359296);
    cvt_kernel<<<4608, 256>>>(ff1_w,  wh + OW_FF1,  wl + OW_FF1,  9437184);
    cvt_kernel<<<4608, 256>>>(ff2_w,  wh + OW_FF2,  wl + OW_FF2,  9437184);
    cvt_kernel<<<38,   256>>>(cls_w1, wh + OW_CLS1, wl + OW_CLS1, 76800);
    cvt_pad_kernel<<<5469, 256>>>(cls_w2, wh + OW_CLS2, wl + OW_CLS2);

    // --- mention pooling (writes x + split) ---
    hl_kernel<<<BB * LL, 256>>>(lhs, attn_w, hl);
    pool_kernel<<<ROWS, 256>>>(lhs, pos, mask, hl, x, ah, al);

    // --- transformer layers ---
    for (int i = 0; i < NL; i++) {
        gemm_tc<128, 0, 1><<<dim3(3 * DD / 128, ROWS / 128), 256, SMEM128>>>(
            ah, al, wh + OW_QKV + (size_t)i * 3 * DD * DD,
            wl + OW_QKV + (size_t)i * 3 * DD * DD,
            qkv_b + (size_t)i * 3 * DD, nullptr, bh2, bl2,
            ROWS, 3 * DD, DD, 3 * DD, 3 * DD);
        attn_fused<<<BB * HH, 256, SMEMATT>>>(bh2, bl2, ah, al);
        gemm_tc<64, 0, 0><<<dim3(DD / 64, ROWS / 128), 256, SMEM64>>>(
            ah, al, wh + OW_OUT + (size_t)i * DD * DD,
            wl + OW_OUT + (size_t)i * DD * DD,
            out_b + (size_t)i * DD, tmp, nullptr, nullptr,
            ROWS, DD, DD, DD, DD);
        add_ln_kernel<<<ROWS, 256>>>(x, tmp, ln1_w + (size_t)i * DD,
                                     ln1_b + (size_t)i * DD, ah, al);
        gemm_tc<128, 1, 1><<<dim3(DFF / 128, ROWS / 128), 256, SMEM128>>>(
            ah, al, wh + OW_FF1 + (size_t)i * DFF * DD,
            wl + OW_FF1 + (size_t)i * DFF * DD,
            ff1_b + (size_t)i * DFF, nullptr, bh2, bl2,
            ROWS, DFF, DD, DFF, DFF);
        gemm_tc<64, 0, 0><<<dim3(DD / 64, ROWS / 128), 256, SMEM64>>>(
            bh2, bl2, wh + OW_FF2 + (size_t)i * DD * DFF,
            wl + OW_FF2 + (size_t)i * DD * DFF,
            ff2_b + (size_t)i * DD, tmp, nullptr, nullptr,
            ROWS, DD, DFF, DD, DD);
        add_ln_kernel<<<ROWS, 256>>>(x, tmp, ln2_w + (size_t)i * DD,
                                     ln2_b + (size_t)i * DD, ah, al);
    }

    // --- classifier head ---
    gemm_tc<64, 0, 1><<<dim3(2, ROWS / 128), 256, SMEM64>>>(
        ah, al, wh + OW_CLS1, wl + OW_CLS1, nullptr,
        nullptr, bh2, bl2, ROWS, 100, DD, KPAD, KPAD);
    gemm_tc<128, 0, 0><<<dim3((NE + 127) / 128, ROWS / 128), 256, SMEM128>>>(
        bh2, bl2, wh + OW_CLS2, wl + OW_CLS2, cls_b2,
        out, nullptr, nullptr, ROWS, NE, KPAD, NE, NE);
}

// round 9
// speedup vs baseline: 4.3032x; 1.0496x over previous
#include <cuda_runtime.h>
#include <cuda_bf16.h>
#include <math.h>
#include <cstdint>

// ----------------------------------------------------------------------------
// Problem constants
// ----------------------------------------------------------------------------
#define BB   16
#define MM   128
#define LL   32
#define SS   512
#define DD   768
#define HH   12
#define HD   64
#define DFF  3072
#define NL   4
#define NE   50000
#define ROWS (BB*MM)          // 2048
#define KPAD 112              // padded K for classifier stage 2

typedef unsigned long long ull;
typedef unsigned int u32;
typedef __nv_bfloat16 bf16;

// weight scratch offsets (elements)
#define OW_QKV  0ULL
#define OW_OUT  7077888ULL
#define OW_FF1  9437184ULL
#define OW_FF2  18874368ULL
#define OW_CLS1 28311552ULL
#define OW_CLS2 28388352ULL
#define NW_TOT  (28388352ULL + 50000ULL*KPAD)

// ----------------------------------------------------------------------------
// Device scratch (static allocation — no cudaMalloc allowed)
// ----------------------------------------------------------------------------
__device__ float g_hl[BB*LL];
__device__ float g_x [ROWS*DD];
__device__ float g_tmp[ROWS*DFF];
__device__ __align__(256) bf16 g_wh[NW_TOT];
__device__ __align__(256) bf16 g_wl[NW_TOT];
__device__ __align__(256) bf16 g_ah[ROWS*DFF];
__device__ __align__(256) bf16 g_al[ROWS*DFF];
__device__ __align__(256) bf16 g_bh[ROWS*DFF];
__device__ __align__(256) bf16 g_bl[ROWS*DFF];

// ----------------------------------------------------------------------------
// PTX helpers
// ----------------------------------------------------------------------------
__device__ __forceinline__ u32 smem_u32(const void* p)
{
    u32 a;
    asm("{ .reg .u64 t; cvta.to.shared.u64 t, %1; cvt.u32.u64 %0, t; }"
        : "=r"(a) : "l"(p));
    return a;
}

__device__ __forceinline__ void cp_async16(u32 dst, const void* src, int sz)
{
    asm volatile("cp.async.cg.shared.global [%0], [%1], 16, %2;"
        :: "r"(dst), "l"(src), "r"(sz));
}
#define CP_COMMIT() asm volatile("cp.async.commit_group;" ::: "memory")
#define CP_WAIT1()  asm volatile("cp.async.wait_group 1;" ::: "memory")
#define CP_WAIT0()  asm volatile("cp.async.wait_group 0;" ::: "memory")

__device__ __forceinline__ void ldsm4(u32 addr, u32& r0, u32& r1, u32& r2, u32& r3)
{
    asm volatile("ldmatrix.sync.aligned.m8n8.x4.shared.b16 {%0,%1,%2,%3}, [%4];"
        : "=r"(r0), "=r"(r1), "=r"(r2), "=r"(r3) : "r"(addr));
}
__device__ __forceinline__ void ldsm4t(u32 addr, u32& r0, u32& r1, u32& r2, u32& r3)
{
    asm volatile("ldmatrix.sync.aligned.m8n8.x4.trans.shared.b16 {%0,%1,%2,%3}, [%4];"
        : "=r"(r0), "=r"(r1), "=r"(r2), "=r"(r3) : "r"(addr));
}

__device__ __forceinline__ void mma_bf16(float* d, const u32* a, u32 b0, u32 b1)
{
    asm volatile(
        "mma.sync.aligned.m16n8k16.row.col.f32.bf16.bf16.f32 "
        "{%0,%1,%2,%3},{%4,%5,%6,%7},{%8,%9},{%0,%1,%2,%3};"
        : "+f"(d[0]), "+f"(d[1]), "+f"(d[2]), "+f"(d[3])
        : "r"(a[0]), "r"(a[1]), "r"(a[2]), "r"(a[3]), "r"(b0), "r"(b1));
}

// pack two fp32 into bf16x2 word: lo at lower halfword
__device__ __forceinline__ u32 pack_bf(float lo, float hi)
{
    u32 r;
    asm("cvt.rn.bf16x2.f32 %0, %1, %2;" : "=r"(r) : "f"(hi), "f"(lo));
    return r;
}

__device__ __forceinline__ float bf_round(float v)
{
    return __bfloat162float(__float2bfloat16(v));
}

__device__ __forceinline__ void split_write(bf16* h, bf16* l, size_t idx, float v)
{
    bf16 hh = __float2bfloat16(v);
    h[idx] = hh;
    l[idx] = __float2bfloat16(v - __bfloat162float(hh));
}

// packed pair store (idx even, arrays 4B-aligned)
__device__ __forceinline__ void split_store2(bf16* h, bf16* l, size_t idx,
                                             float v0, float v1)
{
    float h0 = bf_round(v0), h1 = bf_round(v1);
    *(u32*)(h + idx) = pack_bf(h0, h1);
    *(u32*)(l + idx) = pack_bf(v0 - h0, v1 - h1);
}

// ----------------------------------------------------------------------------
// Fused weight conversion: 5 contiguous destination segments in wh/wl.
// One 8-element unit per thread-iter.
// ----------------------------------------------------------------------------
__global__ void cvt_all_kernel(const float* __restrict__ s0,
                               const float* __restrict__ s1,
                               const float* __restrict__ s2,
                               const float* __restrict__ s3,
                               const float* __restrict__ s4,
                               bf16* __restrict__ h, bf16* __restrict__ l)
{
    // boundaries in 8-element units
    const long long Bn0 = 884736, Bn1 = 1179648, Bn2 = 2359296,
                    Bn3 = 3538944, Bn4 = 3548544;
    for (long long i = (long long)blockIdx.x * 256 + threadIdx.x; i < Bn4;
         i += (long long)gridDim.x * 256) {
        const float* src;
        long long basei;
        if (i < Bn0)      { src = s0; basei = 0; }
        else if (i < Bn1) { src = s1; basei = Bn0; }
        else if (i < Bn2) { src = s2; basei = Bn1; }
        else if (i < Bn3) { src = s3; basei = Bn2; }
        else              { src = s4; basei = Bn3; }
        const float4* xp = (const float4*)src + 2 * (i - basei);
        float4 a = xp[0], b = xp[1];
        float h0 = bf_round(a.x), h1 = bf_round(a.y),
              h2 = bf_round(a.z), h3 = bf_round(a.w),
              h4 = bf_round(b.x), h5 = bf_round(b.y),
              h6 = bf_round(b.z), h7 = bf_round(b.w);
        uint4 H, L;
        H.x = pack_bf(h0, h1); H.y = pack_bf(h2, h3);
        H.z = pack_bf(h4, h5); H.w = pack_bf(h6, h7);
        L.x = pack_bf(a.x - h0, a.y - h1); L.y = pack_bf(a.z - h2, a.w - h3);
        L.z = pack_bf(b.x - h4, b.y - h5); L.w = pack_bf(b.z - h6, b.w - h7);
        ((uint4*)h)[i] = H;
        ((uint4*)l)[i] = L;
    }
}

// cls_w2: [NE,100] -> [NE,112] zero-padded split (4 cols/thread/iter)
__global__ void cvt_pad_kernel(const float* __restrict__ x,
                               bf16* __restrict__ h, bf16* __restrict__ l)
{
    int total = NE * 28;
    for (int i = blockIdx.x * 256 + threadIdx.x; i < total; i += gridDim.x * 256) {
        int r = i / 28, c4 = (i - r * 28) * 4;
        u32 ha = 0, hb = 0, la = 0, lb = 0;
        if (c4 < 100) {
            float4 v = *(const float4*)(x + (size_t)r * 100 + c4);
            float h0 = bf_round(v.x), h1 = bf_round(v.y),
                  h2 = bf_round(v.z), h3 = bf_round(v.w);
            ha = pack_bf(h0, h1); hb = pack_bf(h2, h3);
            la = pack_bf(v.x - h0, v.y - h1); lb = pack_bf(v.z - h2, v.w - h3);
        }
        size_t o = (size_t)r * KPAD + c4;
        *(uint2*)(h + o) = make_uint2(ha, hb);
        *(uint2*)(l + o) = make_uint2(la, lb);
    }
}

// ----------------------------------------------------------------------------
// hl[b,l] = dot(hidden[b,l,:], attn_w)
// ----------------------------------------------------------------------------
__global__ void hl_kernel(const float* __restrict__ lhs,
                          const float* __restrict__ aw,
                          float* __restrict__ hl)
{
    int blk = blockIdx.x;
    int b = blk >> 5, l = blk & 31;
    const float* row = lhs + ((size_t)b * SS + l) * DD;
    int t = threadIdx.x;
    float p = 0.f;
    for (int i = t; i < DD; i += 256) p += row[i] * aw[i];
    #pragma unroll
    for (int o = 16; o; o >>= 1) p += __shfl_xor_sync(~0u, p, o);
    __shared__ float red[8];
    if ((t & 31) == 0) red[t >> 5] = p;
    __syncthreads();
    if (t == 0) {
        float s = 0.f;
        #pragma unroll
        for (int i = 0; i < 8; i++) s += red[i];
        hl[b * LL + l] = s;
    }
}

// ----------------------------------------------------------------------------
// Mention pooling (pos/mask int32). Writes x fp32 + bf16 split.
// ----------------------------------------------------------------------------
__global__ void pool_kernel(const float* __restrict__ lhs,
                            const int* __restrict__ pos,
                            const int* __restrict__ mask,
                            const float* __restrict__ hl,
                            float* __restrict__ x,
                            bf16* __restrict__ xh, bf16* __restrict__ xl)
{
    int bm = blockIdx.x;
    int b = bm >> 7;
    int t = threadIdx.x;
    __shared__ float ws[LL];
    __shared__ int s_nv;
    if (t < 32) {
        int p = pos[(size_t)bm * LL + t];
        unsigned bits = __ballot_sync(0xffffffffu, p != -1);
        int nv;
        if (mask[bm] == 0) nv = 0;
        else if (~bits == 0u) nv = 32;
        else nv = __ffs(~bits) - 1;
        float logit = (t < nv) ? hl[b * LL + t] : 0.f;
        float mx = logit;
        #pragma unroll
        for (int o = 16; o; o >>= 1) mx = fmaxf(mx, __shfl_xor_sync(~0u, mx, o));
        float e = expf(logit - mx);
        float s = e;
        #pragma unroll
        for (int o = 16; o; o >>= 1) s += __shfl_xor_sync(~0u, s, o);
        ws[t] = e / s;
        if (t == 0) s_nv = nv;
    }
    __syncthreads();
    int nv = s_nv;
    for (int d = t; d < DD; d += 256) {
        float acc = 0.f;
        for (int l = 0; l < nv; l++)
            acc += ws[l] * lhs[((size_t)b * SS + l) * DD + d];
        size_t idx = (size_t)bm * DD + d;
        x[idx] = acc;
        split_write(xh, xl, idx, acc);
    }
}

// ----------------------------------------------------------------------------
// Tensor-core split-bf16 NT GEMM: mma.sync + ldmatrix + 3-stage cp.async ring.
// 2 CTAs/SM. CTA tile TM x TN (TM in {64,128}, TN in {64,128}).
// 8 warps: 4m x 2n, warp tile (TM/4) x (TN/2). M%TM==0; N,K guarded; N even.
// SPLIT=0 -> fp32 C; SPLIT=1 -> bf16 hi/lo, cols [N,padN) zero-filled.
// ----------------------------------------------------------------------------
template<int TM, int TN, int RELU, int SPLIT>
__global__ __launch_bounds__(256, 2)
void gemm_tc(const bf16* __restrict__ Ah, const bf16* __restrict__ Al,
             const bf16* __restrict__ Bh, const bf16* __restrict__ Bl,
             const float* __restrict__ bias,
             float* __restrict__ C, bf16* __restrict__ Ch, bf16* __restrict__ Cl,
             int M, int N, int K, int ldout, int padN)
{
    constexpr int MI  = TM / 64;        // m16 frags per warp
    constexpr int NJW = TN / 16;        // n8 frags per warp
    constexpr int ASZ = TM * 64;        // bytes per A split slab
    constexpr int BSZ = TN * 64;
    constexpr int BUF = 2 * ASZ + 2 * BSZ;

    extern __shared__ char smem[];
    const u32 base = smem_u32(smem);
    const int t = threadIdx.x, lane = t & 31, warp = t >> 5;
    const int mBase = blockIdx.y * TM, nBase = blockIdx.x * TN;
    const int wm = (warp >> 1) * (TM / 4), wn = (warp & 1) * (TN / 2);
    const int ar0 = wm + (lane & 15);
    const int ahi = lane >> 4;
    const int br0 = wn + (lane & 7) + ((lane >> 4) << 3);
    const int bhi = (lane >> 3) & 1;

    float acc[MI][NJW][4];
    #pragma unroll
    for (int mi = 0; mi < MI; mi++)
        #pragma unroll
        for (int nj = 0; nj < NJW; nj++)
            #pragma unroll
            for (int r = 0; r < 4; r++) acc[mi][nj][r] = 0.f;

    const int S = (K + 31) / 32;

    auto loadSlab = [&](int s) {
        const int k0 = s * 32;
        const u32 bb = base + (s % 3) * BUF;
        #pragma unroll
        for (int p = 0; p < TM / 64; p++) {
            int c = p * 256 + t, row = c >> 2, ch = c & 3;
            int kk = k0 + ch * 8;
            int avail = K - kk;
            int sz = (avail >= 8) ? 16 : (avail > 0 ? avail * 2 : 0);
            u32 off = row * 64 + ((u32)(ch ^ ((row >> 1) & 3)) << 4);
            cp_async16(bb + off, Ah + (size_t)(mBase + row) * K + kk, sz);
            cp_async16(bb + ASZ + off, Al + (size_t)(mBase + row) * K + kk, sz);
        }
        #pragma unroll
        for (int p = 0; p < TN / 64; p++) {
            int c = p * 256 + t, row = c >> 2, ch = c & 3;
            int kk = k0 + ch * 8;
            int avail = K - kk;
            int sz = (avail >= 8) ? 16 : (avail > 0 ? avail * 2 : 0);
            if (nBase + row >= N) sz = 0;
            u32 off = row * 64 + ((u32)(ch ^ ((row >> 1) & 3)) << 4);
            cp_async16(bb + 2 * ASZ + off, Bh + (size_t)(nBase + row) * K + kk, sz);
            cp_async16(bb + 2 * ASZ + BSZ + off, Bl + (size_t)(nBase + row) * K + kk, sz);
        }
    };

    loadSlab(0);
    CP_COMMIT();
    if (S > 1) loadSlab(1);
    CP_COMMIT();

    for (int s = 0; s < S; s++) {
        CP_WAIT1();
        __syncthreads();
        if (s + 2 < S) loadSlab(s + 2);
        CP_COMMIT();

        const u32 bb = base + (s % 3) * BUF;
        const u32 aB0 = bb, aB1 = bb + ASZ;
        const u32 bB0 = bb + 2 * ASZ, bB1 = bb + 2 * ASZ + BSZ;

        #pragma unroll
        for (int ks = 0; ks < 2; ks++) {
            u32 ahf[MI][4], alf[MI][4];
            #pragma unroll
            for (int mi = 0; mi < MI; mi++) {
                int row = ar0 + mi * 16;
                u32 off = row * 64 + ((u32)((ks * 2 + ahi) ^ ((row >> 1) & 3)) << 4);
                ldsm4(aB0 + off, ahf[mi][0], ahf[mi][1], ahf[mi][2], ahf[mi][3]);
                ldsm4(aB1 + off, alf[mi][0], alf[mi][1], alf[mi][2], alf[mi][3]);
            }
            #pragma unroll
            for (int j = 0; j < NJW / 2; j++) {
                int row = br0 + j * 16;
                u32 off = row * 64 + ((u32)((ks * 2 + bhi) ^ ((row >> 1) & 3)) << 4);
                u32 b0, b1, b2, b3, l0, l1, l2, l3;
                ldsm4(bB0 + off, b0, b1, b2, b3);
                ldsm4(bB1 + off, l0, l1, l2, l3);
                #pragma unroll
                for (int mi = 0; mi < MI; mi++) {
                    mma_bf16(acc[mi][2 * j],     ahf[mi], b0, b1);
                    mma_bf16(acc[mi][2 * j],     ahf[mi], l0, l1);
                    mma_bf16(acc[mi][2 * j],     alf[mi], b0, b1);
                    mma_bf16(acc[mi][2 * j + 1], ahf[mi], b2, b3);
                    mma_bf16(acc[mi][2 * j + 1], ahf[mi], l2, l3);
                    mma_bf16(acc[mi][2 * j + 1], alf[mi], b2, b3);
                }
            }
        }
    }

    // epilogue (packed pair stores; all N/padN even)
    const int g = lane >> 2, tg = lane & 3;
    #pragma unroll
    for (int mi = 0; mi < MI; mi++) {
        int row0 = mBase + wm + mi * 16 + g;
        #pragma unroll
        for (int nj = 0; nj < NJW; nj++) {
            int col0 = nBase + wn + nj * 8 + 2 * tg;
            if (col0 < padN) {
                #pragma unroll
                for (int rr = 0; rr < 2; rr++) {
                    int row = row0 + rr * 8;
                    float v0 = 0.f, v1 = 0.f;
                    if (col0 < N) {
                        v0 = acc[mi][nj][rr * 2 + 0] + (bias ? bias[col0] : 0.f);
                        v1 = acc[mi][nj][rr * 2 + 1] + (bias ? bias[col0 + 1] : 0.f);
                        if (RELU) { v0 = fmaxf(v0, 0.f); v1 = fmaxf(v1, 0.f); }
                    }
                    if (SPLIT)
                        split_store2(Ch, Cl, (size_t)row * ldout + col0, v0, v1);
                    else
                        *(float2*)(C + (size_t)row * ldout + col0) = make_float2(v0, v1);
                }
            }
        }
    }
}

// ----------------------------------------------------------------------------
// Fused attention: one CTA per (b,h), 8 warps x 16 Q-rows.
// ----------------------------------------------------------------------------
__global__ __launch_bounds__(256)
void attn_fused(const bf16* __restrict__ qkvh, const bf16* __restrict__ qkvl,
                bf16* __restrict__ aoh, bf16* __restrict__ aol)
{
    extern __shared__ char smem[];
    const u32 base = smem_u32(smem);
    const int t = threadIdx.x, lane = t & 31, warp = t >> 5;
    const int bh = blockIdx.x, b = bh / HH, h = bh % HH;
    const size_t rowBase = (size_t)b * MM;
    const int g = lane >> 2, tg = lane & 3;

    #pragma unroll
    for (int m = 0; m < 6; m++) {
        const bf16* src = (m & 1) ? qkvl : qkvh;
        int colOff = (m >> 1) * DD + h * HD;
        u32 dst = base + m * 16384;
        #pragma unroll
        for (int p = 0; p < 4; p++) {
            int c = p * 256 + t;
            int row = c >> 3, ch = c & 7;
            u32 off = row * 128 + ((u32)(ch ^ (row & 7)) << 4);
            cp_async16(dst + off,
                       src + (rowBase + row) * (3 * DD) + colOff + ch * 8, 16);
        }
    }
    CP_COMMIT(); CP_WAIT0();
    __syncthreads();

    const u32 sQh = base, sQl = base + 16384;
    const u32 sKh = base + 32768, sKl = base + 49152;
    const u32 sVh = base + 65536, sVl = base + 81920;
    const int m0 = warp * 16;

    float acc[16][4];
    #pragma unroll
    for (int nj = 0; nj < 16; nj++)
        #pragma unroll
        for (int r = 0; r < 4; r++) acc[nj][r] = 0.f;

    const int tile = lane >> 3, wr = lane & 7;
    #pragma unroll
    for (int kk = 0; kk < 4; kk++) {
        u32 qh4[4], ql4[4];
        {
            int row = m0 + wr + (tile & 1) * 8;
            int ch = kk * 2 + (tile >> 1);
            u32 off = row * 128 + ((u32)(ch ^ (row & 7)) << 4);
            ldsm4(sQh + off, qh4[0], qh4[1], qh4[2], qh4[3]);
            ldsm4(sQl + off, ql4[0], ql4[1], ql4[2], ql4[3]);
        }
        #pragma unroll
        for (int nj2 = 0; nj2 < 8; nj2++) {
            int row = nj2 * 16 + wr + (tile >> 1) * 8;
            int ch = kk * 2 + (tile & 1);
            u32 off = row * 128 + ((u32)(ch ^ (row & 7)) << 4);
            u32 b0, b1, b2, b3, l0, l1, l2, l3;
            ldsm4(sKh + off, b0, b1, b2, b3);
            ldsm4(sKl + off, l0, l1, l2, l3);
            mma_bf16(acc[2 * nj2],     qh4, b0, b1);
            mma_bf16(acc[2 * nj2],     qh4, l0, l1);
            mma_bf16(acc[2 * nj2],     ql4, b0, b1);
            mma_bf16(acc[2 * nj2 + 1], qh4, b2, b3);
            mma_bf16(acc[2 * nj2 + 1], qh4, l2, l3);
            mma_bf16(acc[2 * nj2 + 1], ql4, b2, b3);
        }
    }

    {
        float mx0 = -1e30f, mx1 = -1e30f;
        #pragma unroll
        for (int nj = 0; nj < 16; nj++) {
            acc[nj][0] *= 0.125f; acc[nj][1] *= 0.125f;
            acc[nj][2] *= 0.125f; acc[nj][3] *= 0.125f;
            mx0 = fmaxf(mx0, fmaxf(acc[nj][0], acc[nj][1]));
            mx1 = fmaxf(mx1, fmaxf(acc[nj][2], acc[nj][3]));
        }
        mx0 = fmaxf(mx0, __shfl_xor_sync(~0u, mx0, 1));
        mx0 = fmaxf(mx0, __shfl_xor_sync(~0u, mx0, 2));
        mx1 = fmaxf(mx1, __shfl_xor_sync(~0u, mx1, 1));
        mx1 = fmaxf(mx1, __shfl_xor_sync(~0u, mx1, 2));
        float s0 = 0.f, s1 = 0.f;
        #pragma unroll
        for (int nj = 0; nj < 16; nj++) {
            acc[nj][0] = expf(acc[nj][0] - mx0);
            acc[nj][1] = expf(acc[nj][1] - mx0);
            acc[nj][2] = expf(acc[nj][2] - mx1);
            acc[nj][3] = expf(acc[nj][3] - mx1);
            s0 += acc[nj][0] + acc[nj][1];
            s1 += acc[nj][2] + acc[nj][3];
        }
        s0 += __shfl_xor_sync(~0u, s0, 1);
        s0 += __shfl_xor_sync(~0u, s0, 2);
        s1 += __shfl_xor_sync(~0u, s1, 1);
        s1 += __shfl_xor_sync(~0u, s1, 2);
        float i0 = 1.f / s0, i1 = 1.f / s1;
        #pragma unroll
        for (int nj = 0; nj < 16; nj++) {
            acc[nj][0] *= i0; acc[nj][1] *= i0;
            acc[nj][2] *= i1; acc[nj][3] *= i1;
        }
    }

    float o[8][4];
    #pragma unroll
    for (int nj = 0; nj < 8; nj++)
        #pragma unroll
        for (int r = 0; r < 4; r++) o[nj][r] = 0.f;

    #pragma unroll
    for (int j = 0; j < 8; j++) {
        u32 pa_h[4], pa_l[4];
        #pragma unroll
        for (int q = 0; q < 2; q++) {
            float p0 = acc[2 * j + q][0], p1 = acc[2 * j + q][1];
            float p2 = acc[2 * j + q][2], p3 = acc[2 * j + q][3];
            float h0 = bf_round(p0), h1 = bf_round(p1);
            float h2 = bf_round(p2), h3 = bf_round(p3);
            pa_h[0 + 2 * q] = pack_bf(h0, h1);
            pa_h[1 + 2 * q] = pack_bf(h2, h3);
            pa_l[0 + 2 * q] = pack_bf(p0 - h0, p1 - h1);
            pa_l[1 + 2 * q] = pack_bf(p2 - h2, p3 - h3);
        }
        #pragma unroll
        for (int c2 = 0; c2 < 4; c2++) {
            int row = j * 16 + wr + (tile & 1) * 8;
            int ch = 2 * c2 + (tile >> 1);
            u32 off = row * 128 + ((u32)(ch ^ (row & 7)) << 4);
            u32 v0, v1, v2, v3, w0, w1, w2, w3;
            ldsm4t(sVh + off, v0, v1, v2, v3);
            ldsm4t(sVl + off, w0, w1, w2, w3);
            mma_bf16(o[2 * c2],     pa_h, v0, v1);
            mma_bf16(o[2 * c2],     pa_h, w0, w1);
            mma_bf16(o[2 * c2],     pa_l, v0, v1);
            mma_bf16(o[2 * c2 + 1], pa_h, v2, v3);
            mma_bf16(o[2 * c2 + 1], pa_h, w2, w3);
            mma_bf16(o[2 * c2 + 1], pa_l, v2, v3);
        }
    }

    {
        size_t gr = rowBase + m0 + g;
        #pragma unroll
        for (int nj = 0; nj < 8; nj++) {
            int col = h * HD + nj * 8 + 2 * tg;
            split_store2(aoh, aol, gr * DD + col, o[nj][0], o[nj][1]);
            split_store2(aoh, aol, (gr + 8) * DD + col, o[nj][2], o[nj][3]);
        }
    }
}

// ----------------------------------------------------------------------------
// x = LayerNorm(x + delta) * w + b; also writes bf16 split of x
// ----------------------------------------------------------------------------
__global__ __launch_bounds__(256)
void add_ln_kernel(float* __restrict__ x, const float* __restrict__ d,
                   const float* __restrict__ w, const float* __restrict__ b,
                   bf16* __restrict__ xh, bf16* __restrict__ xl)
{
    int row = blockIdx.x, t = threadIdx.x;
    float* xp = x + (size_t)row * DD;
    const float* dp = d + (size_t)row * DD;
    float v0 = xp[t]       + dp[t];
    float v1 = xp[t + 256] + dp[t + 256];
    float v2 = xp[t + 512] + dp[t + 512];
    float s = v0 + v1 + v2;
    __shared__ float red[8];
    #pragma unroll
    for (int o = 16; o; o >>= 1) s += __shfl_xor_sync(~0u, s, o);
    if ((t & 31) == 0) red[t >> 5] = s;
    __syncthreads();
    float tot = red[0] + red[1] + red[2] + red[3] + red[4] + red[5] + red[6] + red[7];
    float mu = tot * (1.f / 768.f);
    float d0 = v0 - mu, d1 = v1 - mu, d2 = v2 - mu;
    float q = d0 * d0 + d1 * d1 + d2 * d2;
    #pragma unroll
    for (int o = 16; o; o >>= 1) q += __shfl_xor_sync(~0u, q, o);
    __syncthreads();
    if ((t & 31) == 0) red[t >> 5] = q;
    __syncthreads();
    float qt = red[0] + red[1] + red[2] + red[3] + red[4] + red[5] + red[6] + red[7];
    float inv = rsqrtf(qt * (1.f / 768.f) + 1e-5f);
    float o0 = d0 * inv * w[t]       + b[t];
    float o1 = d1 * inv * w[t + 256] + b[t + 256];
    float o2 = d2 * inv * w[t + 512] + b[t + 512];
    size_t rb = (size_t)row * DD;
    xp[t] = o0;       split_write(xh, xl, rb + t,       o0);
    xp[t + 256] = o1; split_write(xh, xl, rb + t + 256, o1);
    xp[t + 512] = o2; split_write(xh, xl, rb + t + 512, o2);
}

// ----------------------------------------------------------------------------
// Host-side launch
// ----------------------------------------------------------------------------
template<typename T>
static T* sym(const void* s)
{
    void* p = nullptr;
    cudaGetSymbolAddress(&p, s);
    return (T*)p;
}

#define SMEM_TM_TN(TM, TN) (3 * (2 * (TM) * 64 + 2 * (TN) * 64))
#define SMEM12828 SMEM_TM_TN(128, 128)   // 98304
#define SMEM12864 SMEM_TM_TN(128, 64)    // 73728
#define SMEM6464  SMEM_TM_TN(64, 64)     // 49152
#define SMEMATT   (6 * 16384)            // 98304

extern "C" void kernel_launch(void* const* d_in, const int* in_sizes, int n_in,
                              void* d_out, int out_size)
{
    static const long long want[20] = {
        6291456LL, 65536LL, 2048LL, 768LL, 1LL,
        7077888LL, 9216LL, 2359296LL, 3072LL, 3072LL, 3072LL,
        9437184LL, 12288LL, 9437184LL, 3072LL, 3072LL, 3072LL,
        76800LL, 5000000LL, 50000LL
    };
    const void* slot[20];
    bool used[64];
    for (int i = 0; i < 20; i++) slot[i] = nullptr;
    for (int i = 0; i < n_in && i < 64; i++) used[i] = false;
    for (int w = 0; w < 20; w++) {
        for (int i = 0; i < n_in && i < 64; i++) {
            if (!used[i] && (long long)in_sizes[i] == want[w]) {
                slot[w] = d_in[i];
                used[i] = true;
                break;
            }
        }
    }
    if (!slot[0]) {
        for (int w = 0; w < 20 && w < n_in; w++) slot[w] = d_in[w];
    }

    const float* lhs    = (const float*)slot[0];
    const int*   pos    = (const int*)slot[1];
    const int*   mask   = (const int*)slot[2];
    const float* attn_w = (const float*)slot[3];
    const float* qkv_w  = (const float*)slot[5];
    const float* qkv_b  = (const float*)slot[6];
    const float* out_w  = (const float*)slot[7];
    const float* out_b  = (const float*)slot[8];
    const float* ln1_w  = (const float*)slot[9];
    const float* ln1_b  = (const float*)slot[10];
    const float* ff1_w  = (const float*)slot[11];
    const float* ff1_b  = (const float*)slot[12];
    const float* ff2_w  = (const float*)slot[13];
    const float* ff2_b  = (const float*)slot[14];
    const float* ln2_w  = (const float*)slot[15];
    const float* ln2_b  = (const float*)slot[16];
    const float* cls_w1 = (const float*)slot[17];
    const float* cls_w2 = (const float*)slot[18];
    const float* cls_b2 = (const float*)slot[19];
    float* out = (float*)d_out;

    float* hl  = sym<float>(g_hl);
    float* x   = sym<float>(g_x);
    float* tmp = sym<float>(g_tmp);
    bf16*  wh  = sym<bf16>(g_wh);
    bf16*  wl  = sym<bf16>(g_wl);
    bf16*  ah  = sym<bf16>(g_ah);
    bf16*  al  = sym<bf16>(g_al);
    bf16*  bh2 = sym<bf16>(g_bh);
    bf16*  bl2 = sym<bf16>(g_bl);

    cudaFuncSetAttribute(gemm_tc<128, 128, 0, 1>, cudaFuncAttributeMaxDynamicSharedMemorySize, SMEM12828);
    cudaFuncSetAttribute(gemm_tc<128, 128, 0, 0>, cudaFuncAttributeMaxDynamicSharedMemorySize, SMEM12828);
    cudaFuncSetAttribute(gemm_tc<128, 64, 1, 1>,  cudaFuncAttributeMaxDynamicSharedMemorySize, SMEM12864);
    cudaFuncSetAttribute(gemm_tc<128, 64, 0, 1>,  cudaFuncAttributeMaxDynamicSharedMemorySize, SMEM12864);
    cudaFuncSetAttribute(gemm_tc<64, 64, 0, 0>,   cudaFuncAttributeMaxDynamicSharedMemorySize, SMEM6464);
    cudaFuncSetAttribute(attn_fused, cudaFuncAttributeMaxDynamicSharedMemorySize, SMEMATT);

    // --- weight conversion: 1 fused launch + cls2 pad ---
    cvt_all_kernel<<<6934, 256>>>(qkv_w, out_w, ff1_w, ff2_w, cls_w1, wh, wl);
    cvt_pad_kernel<<<2736, 256>>>(cls_w2, wh + OW_CLS2, wl + OW_CLS2);

    // --- mention pooling (writes x + split) ---
    hl_kernel<<<BB * LL, 256>>>(lhs, attn_w, hl);
    pool_kernel<<<ROWS, 256>>>(lhs, pos, mask, hl, x, ah, al);

    // --- transformer layers ---
    for (int i = 0; i < NL; i++) {
        gemm_tc<128, 128, 0, 1><<<dim3(3 * DD / 128, ROWS / 128), 256, SMEM12828>>>(
            ah, al, wh + OW_QKV + (size_t)i * 3 * DD * DD,
            wl + OW_QKV + (size_t)i * 3 * DD * DD,
            qkv_b + (size_t)i * 3 * DD, nullptr, bh2, bl2,
            ROWS, 3 * DD, DD, 3 * DD, 3 * DD);
        attn_fused<<<BB * HH, 256, SMEMATT>>>(bh2, bl2, ah, al);
        gemm_tc<64, 64, 0, 0><<<dim3(DD / 64, ROWS / 64), 256, SMEM6464>>>(
            ah, al, wh + OW_OUT + (size_t)i * DD * DD,
            wl + OW_OUT + (size_t)i * DD * DD,
            out_b + (size_t)i * DD, tmp, nullptr, nullptr,
            ROWS, DD, DD, DD, DD);
        add_ln_kernel<<<ROWS, 256>>>(x, tmp, ln1_w + (size_t)i * DD,
                                     ln1_b + (size_t)i * DD, ah, al);
        gemm_tc<128, 64, 1, 1><<<dim3(DFF / 64, ROWS / 128), 256, SMEM12864>>>(
            ah, al, wh + OW_FF1 + (size_t)i * DFF * DD,
            wl + OW_FF1 + (size_t)i * DFF * DD,
            ff1_b + (size_t)i * DFF, nullptr, bh2, bl2,
            ROWS, DFF, DD, DFF, DFF);
        gemm_tc<64, 64, 0, 0><<<dim3(DD / 64, ROWS / 64), 256, SMEM6464>>>(
            bh2, bl2, wh + OW_FF2 + (size_t)i * DD * DFF,
            wl + OW_FF2 + (size_t)i * DD * DFF,
            ff2_b + (size_t)i * DD, tmp, nullptr, nullptr,
            ROWS, DD, DFF, DD, DD);
        add_ln_kernel<<<ROWS, 256>>>(x, tmp, ln2_w + (size_t)i * DD,
                                     ln2_b + (size_t)i * DD, ah, al);
    }

    // --- classifier head ---
    gemm_tc<128, 64, 0, 1><<<dim3(2, ROWS / 128), 256, SMEM12864>>>(
        ah, al, wh + OW_CLS1, wl + OW_CLS1, nullptr,
        nullptr, bh2, bl2, ROWS, 100, DD, KPAD, KPAD);
    gemm_tc<128, 128, 0, 0><<<dim3((NE + 127) / 128, ROWS / 128), 256, SMEM12828>>>(
        bh2, bl2, wh + OW_CLS2, wl + OW_CLS2, cls_b2,
        out, nullptr, nullptr, ROWS, NE, KPAD, NE, NE);
}

// round 10
// speedup vs baseline: 4.3883x; 1.0198x over previous
#include <cuda_runtime.h>
#include <cuda_bf16.h>
#include <cuda_fp16.h>
#include <math.h>
#include <cstdint>

// ----------------------------------------------------------------------------
// Problem constants
// ----------------------------------------------------------------------------
#define BB   16
#define MM   128
#define LL   32
#define SS   512
#define DD   768
#define HH   12
#define HD   64
#define DFF  3072
#define NL   4
#define NE   50000
#define ROWS (BB*MM)          // 2048
#define KPAD 112              // padded K for classifier stage 2

typedef unsigned long long ull;
typedef unsigned int u32;
typedef __nv_bfloat16 bf16;

// weight scratch offsets (elements)
#define OW_QKV  0ULL
#define OW_OUT  7077888ULL
#define OW_FF1  9437184ULL
#define OW_FF2  18874368ULL
#define OW_CLS1 28311552ULL
#define OW_CLS2 28388352ULL
#define NW_TOT  (28388352ULL + 50000ULL*KPAD)

// ----------------------------------------------------------------------------
// Device scratch (static allocation — no cudaMalloc allowed)
// ----------------------------------------------------------------------------
__device__ float g_x [ROWS*DD];
__device__ float g_tmp[ROWS*DFF];            // split-K partials (2 x ROWS*DD)
__device__ __align__(256) bf16 g_wh[NW_TOT];
__device__ __align__(256) bf16 g_wl[NW_TOT];
__device__ __align__(256) bf16 g_ah[ROWS*DFF];
__device__ __align__(256) bf16 g_al[ROWS*DFF];
__device__ __align__(256) bf16 g_bh[ROWS*DFF];
__device__ __align__(256) bf16 g_bl[ROWS*DFF];

// ----------------------------------------------------------------------------
// PTX helpers
// ----------------------------------------------------------------------------
__device__ __forceinline__ u32 smem_u32(const void* p)
{
    u32 a;
    asm("{ .reg .u64 t; cvta.to.shared.u64 t, %1; cvt.u32.u64 %0, t; }"
        : "=r"(a) : "l"(p));
    return a;
}

__device__ __forceinline__ void cp_async16(u32 dst, const void* src, int sz)
{
    asm volatile("cp.async.cg.shared.global [%0], [%1], 16, %2;"
        :: "r"(dst), "l"(src), "r"(sz));
}
#define CP_COMMIT() asm volatile("cp.async.commit_group;" ::: "memory")
#define CP_WAIT1()  asm volatile("cp.async.wait_group 1;" ::: "memory")
#define CP_WAIT0()  asm volatile("cp.async.wait_group 0;" ::: "memory")

__device__ __forceinline__ void ldsm4(u32 addr, u32& r0, u32& r1, u32& r2, u32& r3)
{
    asm volatile("ldmatrix.sync.aligned.m8n8.x4.shared.b16 {%0,%1,%2,%3}, [%4];"
        : "=r"(r0), "=r"(r1), "=r"(r2), "=r"(r3) : "r"(addr));
}
__device__ __forceinline__ void ldsm4t(u32 addr, u32& r0, u32& r1, u32& r2, u32& r3)
{
    asm volatile("ldmatrix.sync.aligned.m8n8.x4.trans.shared.b16 {%0,%1,%2,%3}, [%4];"
        : "=r"(r0), "=r"(r1), "=r"(r2), "=r"(r3) : "r"(addr));
}

__device__ __forceinline__ void mma_bf16(float* d, const u32* a, u32 b0, u32 b1)
{
    asm volatile(
        "mma.sync.aligned.m16n8k16.row.col.f32.bf16.bf16.f32 "
        "{%0,%1,%2,%3},{%4,%5,%6,%7},{%8,%9},{%0,%1,%2,%3};"
        : "+f"(d[0]), "+f"(d[1]), "+f"(d[2]), "+f"(d[3])
        : "r"(a[0]), "r"(a[1]), "r"(a[2]), "r"(a[3]), "r"(b0), "r"(b1));
}
__device__ __forceinline__ void mma_f16(float* d, const u32* a, u32 b0, u32 b1)
{
    asm volatile(
        "mma.sync.aligned.m16n8k16.row.col.f32.f16.f16.f32 "
        "{%0,%1,%2,%3},{%4,%5,%6,%7},{%8,%9},{%0,%1,%2,%3};"
        : "+f"(d[0]), "+f"(d[1]), "+f"(d[2]), "+f"(d[3])
        : "r"(a[0]), "r"(a[1]), "r"(a[2]), "r"(a[3]), "r"(b0), "r"(b1));
}

// pack two fp32 into bf16x2 word: first arg -> lower halfword
__device__ __forceinline__ u32 pack_bf(float lo, float hi)
{
    u32 r;
    asm("cvt.rn.bf16x2.f32 %0, %1, %2;" : "=r"(r) : "f"(hi), "f"(lo));
    return r;
}
__device__ __forceinline__ u32 pack_h2(float lo, float hi)
{
    __half2 h = __floats2half2_rn(lo, hi);
    return *(u32*)&h;
}

__device__ __forceinline__ float bf_round(float v)
{
    return __bfloat162float(__float2bfloat16(v));
}

__device__ __forceinline__ void split_write(bf16* h, bf16* l, size_t idx, float v)
{
    bf16 hh = __float2bfloat16(v);
    h[idx] = hh;
    l[idx] = __float2bfloat16(v - __bfloat162float(hh));
}

__device__ __forceinline__ void split_store2(bf16* h, bf16* l, size_t idx,
                                             float v0, float v1)
{
    float h0 = bf_round(v0), h1 = bf_round(v1);
    *(u32*)(h + idx) = pack_bf(h0, h1);
    *(u32*)(l + idx) = pack_bf(v0 - h0, v1 - h1);
}

// ----------------------------------------------------------------------------
// Fused weight conversion (bf16 splits): 5 contiguous segments in wh/wl.
// ----------------------------------------------------------------------------
__global__ void cvt_all_kernel(const float* __restrict__ s0,
                               const float* __restrict__ s1,
                               const float* __restrict__ s2,
                               const float* __restrict__ s3,
                               const float* __restrict__ s4,
                               bf16* __restrict__ h, bf16* __restrict__ l)
{
    const long long Bn0 = 884736, Bn1 = 1179648, Bn2 = 2359296,
                    Bn3 = 3538944, Bn4 = 3548544;
    for (long long i = (long long)blockIdx.x * 256 + threadIdx.x; i < Bn4;
         i += (long long)gridDim.x * 256) {
        const float* src;
        long long basei;
        if (i < Bn0)      { src = s0; basei = 0; }
        else if (i < Bn1) { src = s1; basei = Bn0; }
        else if (i < Bn2) { src = s2; basei = Bn1; }
        else if (i < Bn3) { src = s3; basei = Bn2; }
        else              { src = s4; basei = Bn3; }
        const float4* xp = (const float4*)src + 2 * (i - basei);
        float4 a = xp[0], b = xp[1];
        float h0 = bf_round(a.x), h1 = bf_round(a.y),
              h2 = bf_round(a.z), h3 = bf_round(a.w),
              h4 = bf_round(b.x), h5 = bf_round(b.y),
              h6 = bf_round(b.z), h7 = bf_round(b.w);
        uint4 H, L;
        H.x = pack_bf(h0, h1); H.y = pack_bf(h2, h3);
        H.z = pack_bf(h4, h5); H.w = pack_bf(h6, h7);
        L.x = pack_bf(a.x - h0, a.y - h1); L.y = pack_bf(a.z - h2, a.w - h3);
        L.z = pack_bf(b.x - h4, b.y - h5); L.w = pack_bf(b.z - h6, b.w - h7);
        ((uint4*)h)[i] = H;
        ((uint4*)l)[i] = L;
    }
}

// cls_w2: [NE,100] -> [NE,112] zero-padded FP16 hi/lo split
__global__ void cvt_pad_kernel(const float* __restrict__ x,
                               bf16* __restrict__ h, bf16* __restrict__ l)
{
    int total = NE * 28;
    for (int i = blockIdx.x * 256 + threadIdx.x; i < total; i += gridDim.x * 256) {
        int r = i / 28, c4 = (i - r * 28) * 4;
        u32 ha = 0, hb = 0, la = 0, lb = 0;
        if (c4 < 100) {
            float4 v = *(const float4*)(x + (size_t)r * 100 + c4);
            float h0 = __half2float(__float2half_rn(v.x));
            float h1 = __half2float(__float2half_rn(v.y));
            float h2 = __half2float(__float2half_rn(v.z));
            float h3 = __half2float(__float2half_rn(v.w));
            ha = pack_h2(h0, h1); hb = pack_h2(h2, h3);
            la = pack_h2(v.x - h0, v.y - h1); lb = pack_h2(v.z - h2, v.w - h3);
        }
        size_t o = (size_t)r * KPAD + c4;
        *(uint2*)(h + o) = make_uint2(ha, hb);
        *(uint2*)(l + o) = make_uint2(la, lb);
    }
}

// ----------------------------------------------------------------------------
// Mention pooling (pos/mask int32), inline attention logits.
// ----------------------------------------------------------------------------
__global__ __launch_bounds__(256)
void pool_kernel(const float* __restrict__ lhs,
                 const int* __restrict__ pos,
                 const int* __restrict__ mask,
                 const float* __restrict__ aw,
                 float* __restrict__ x,
                 bf16* __restrict__ xh, bf16* __restrict__ xl)
{
    int bm = blockIdx.x;
    int b = bm >> 7;
    int t = threadIdx.x;
    __shared__ float dots[LL];
    __shared__ float ws[LL];
    __shared__ int s_nv;

    // logits: 8 threads per mention slot
    {
        int l = t >> 3, sub = t & 7;
        const float* row = lhs + ((size_t)b * SS + l) * DD;
        float p = 0.f;
        for (int j = sub; j < DD; j += 8) p += row[j] * aw[j];
        #pragma unroll
        for (int o = 4; o; o >>= 1) p += __shfl_xor_sync(~0u, p, o);
        if (sub == 0) dots[l] = p;
    }
    __syncthreads();

    if (t < 32) {
        int p = pos[(size_t)bm * LL + t];
        unsigned bits = __ballot_sync(0xffffffffu, p != -1);
        int nv;
        if (mask[bm] == 0) nv = 0;
        else if (~bits == 0u) nv = 32;
        else nv = __ffs(~bits) - 1;
        float logit = (t < nv) ? dots[t] : 0.f;
        float mx = logit;
        #pragma unroll
        for (int o = 16; o; o >>= 1) mx = fmaxf(mx, __shfl_xor_sync(~0u, mx, o));
        float e = expf(logit - mx);
        float s = e;
        #pragma unroll
        for (int o = 16; o; o >>= 1) s += __shfl_xor_sync(~0u, s, o);
        ws[t] = e / s;
        if (t == 0) s_nv = nv;
    }
    __syncthreads();
    int nv = s_nv;
    for (int d = t; d < DD; d += 256) {
        float acc = 0.f;
        for (int l = 0; l < nv; l++)
            acc += ws[l] * lhs[((size_t)b * SS + l) * DD + d];
        size_t idx = (size_t)bm * DD + d;
        x[idx] = acc;
        split_write(xh, xl, idx, acc);
    }
}

// ----------------------------------------------------------------------------
// Tensor-core split NT GEMM: mma.sync + ldmatrix + 3-stage cp.async ring.
// 2 CTAs/SM. CTA tile TM x TN. 8 warps: 4m x 2n.
// PREC=0: bf16 A(hi,lo) x B(hi,lo), 3 mmas (AhBh+AhBl+AlBh).
// PREC=1: fp16 A(hi only) x B(hi,lo), 2 mmas (AhBh+AhBl).
// SPLIT=0 -> fp32 C (+ blockIdx.z * M*ldout for split-K partials);
// SPLIT=1 -> bf16 hi/lo; SPLIT=2 -> fp16 single (Ch). cols [N,padN) zeroed.
// lda/ldb row strides; Klen = K length per z-slice (blockIdx.z*Klen offset).
// ----------------------------------------------------------------------------
template<int TM, int TN, int RELU, int SPLIT, int PREC>
__global__ __launch_bounds__(256, 2)
void gemm_tc(const bf16* __restrict__ Ah, const bf16* __restrict__ Al,
             const bf16* __restrict__ Bh, const bf16* __restrict__ Bl,
             const float* __restrict__ bias,
             float* __restrict__ C, bf16* __restrict__ Ch, bf16* __restrict__ Cl,
             int M, int N, int lda, int ldb, int Klen, int ldout, int padN)
{
    constexpr int MI  = TM / 64;
    constexpr int NJW = TN / 16;
    constexpr int NA  = (PREC == 0) ? 2 : 1;
    constexpr int ASZ = TM * 64;
    constexpr int BSZ = TN * 64;
    constexpr int BUF = NA * ASZ + 2 * BSZ;

    extern __shared__ char smem[];
    const u32 base = smem_u32(smem);
    const int t = threadIdx.x, lane = t & 31, warp = t >> 5;
    const int mBase = blockIdx.y * TM, nBase = blockIdx.x * TN;
    const int kOff = blockIdx.z * Klen;
    const int wm = (warp >> 1) * (TM / 4), wn = (warp & 1) * (TN / 2);
    const int ar0 = wm + (lane & 15);
    const int ahi = lane >> 4;
    const int br0 = wn + (lane & 7) + ((lane >> 4) << 3);
    const int bhi = (lane >> 3) & 1;

    float acc[MI][NJW][4];
    #pragma unroll
    for (int mi = 0; mi < MI; mi++)
        #pragma unroll
        for (int nj = 0; nj < NJW; nj++)
            #pragma unroll
            for (int r = 0; r < 4; r++) acc[mi][nj][r] = 0.f;

    const int S = (Klen + 31) / 32;

    auto loadSlab = [&](int s) {
        const int k0 = s * 32;
        const u32 bb = base + (s % 3) * BUF;
        #pragma unroll
        for (int p = 0; p < TM / 64; p++) {
            int c = p * 256 + t, row = c >> 2, ch = c & 3;
            int kk = k0 + ch * 8;
            int avail = Klen - kk;
            int sz = (avail >= 8) ? 16 : (avail > 0 ? avail * 2 : 0);
            u32 off = row * 64 + ((u32)(ch ^ ((row >> 1) & 3)) << 4);
            cp_async16(bb + off, Ah + (size_t)(mBase + row) * lda + kOff + kk, sz);
            if (PREC == 0)
                cp_async16(bb + ASZ + off, Al + (size_t)(mBase + row) * lda + kOff + kk, sz);
        }
        #pragma unroll
        for (int p = 0; p < TN / 64; p++) {
            int c = p * 256 + t, row = c >> 2, ch = c & 3;
            int kk = k0 + ch * 8;
            int avail = Klen - kk;
            int sz = (avail >= 8) ? 16 : (avail > 0 ? avail * 2 : 0);
            if (nBase + row >= N) sz = 0;
            u32 off = row * 64 + ((u32)(ch ^ ((row >> 1) & 3)) << 4);
            cp_async16(bb + NA * ASZ + off, Bh + (size_t)(nBase + row) * ldb + kOff + kk, sz);
            cp_async16(bb + NA * ASZ + BSZ + off, Bl + (size_t)(nBase + row) * ldb + kOff + kk, sz);
        }
    };

    loadSlab(0);
    CP_COMMIT();
    if (S > 1) loadSlab(1);
    CP_COMMIT();

    for (int s = 0; s < S; s++) {
        CP_WAIT1();
        __syncthreads();
        if (s + 2 < S) loadSlab(s + 2);
        CP_COMMIT();

        const u32 bb = base + (s % 3) * BUF;
        const u32 aB0 = bb, aB1 = bb + ASZ;
        const u32 bB0 = bb + NA * ASZ, bB1 = bb + NA * ASZ + BSZ;

        #pragma unroll
        for (int ks = 0; ks < 2; ks++) {
            u32 ahf[MI][4], alf[MI][4];
            #pragma unroll
            for (int mi = 0; mi < MI; mi++) {
                int row = ar0 + mi * 16;
                u32 off = row * 64 + ((u32)((ks * 2 + ahi) ^ ((row >> 1) & 3)) << 4);
                ldsm4(aB0 + off, ahf[mi][0], ahf[mi][1], ahf[mi][2], ahf[mi][3]);
                if (PREC == 0)
                    ldsm4(aB1 + off, alf[mi][0], alf[mi][1], alf[mi][2], alf[mi][3]);
            }
            #pragma unroll
            for (int j = 0; j < NJW / 2; j++) {
                int row = br0 + j * 16;
                u32 off = row * 64 + ((u32)((ks * 2 + bhi) ^ ((row >> 1) & 3)) << 4);
                u32 b0, b1, b2, b3, l0, l1, l2, l3;
                ldsm4(bB0 + off, b0, b1, b2, b3);
                ldsm4(bB1 + off, l0, l1, l2, l3);
                #pragma unroll
                for (int mi = 0; mi < MI; mi++) {
                    if (PREC == 0) {
                        mma_bf16(acc[mi][2 * j],     ahf[mi], b0, b1);
                        mma_bf16(acc[mi][2 * j],     ahf[mi], l0, l1);
                        mma_bf16(acc[mi][2 * j],     alf[mi], b0, b1);
                        mma_bf16(acc[mi][2 * j + 1], ahf[mi], b2, b3);
                        mma_bf16(acc[mi][2 * j + 1], ahf[mi], l2, l3);
                        mma_bf16(acc[mi][2 * j + 1], alf[mi], b2, b3);
                    } else {
                        mma_f16(acc[mi][2 * j],     ahf[mi], b0, b1);
                        mma_f16(acc[mi][2 * j],     ahf[mi], l0, l1);
                        mma_f16(acc[mi][2 * j + 1], ahf[mi], b2, b3);
                        mma_f16(acc[mi][2 * j + 1], ahf[mi], l2, l3);
                    }
                }
            }
        }
    }

    // epilogue
    float* Cz = C + (size_t)blockIdx.z * M * ldout;
    const int g = lane >> 2, tg = lane & 3;
    #pragma unroll
    for (int mi = 0; mi < MI; mi++) {
        int row0 = mBase + wm + mi * 16 + g;
        #pragma unroll
        for (int nj = 0; nj < NJW; nj++) {
            int col0 = nBase + wn + nj * 8 + 2 * tg;
            if (col0 < padN) {
                #pragma unroll
                for (int rr = 0; rr < 2; rr++) {
                    int row = row0 + rr * 8;
                    float v0 = 0.f, v1 = 0.f;
                    if (col0 < N) {
                        v0 = acc[mi][nj][rr * 2 + 0] + (bias ? bias[col0] : 0.f);
                        v1 = acc[mi][nj][rr * 2 + 1] + (bias ? bias[col0 + 1] : 0.f);
                        if (RELU) { v0 = fmaxf(v0, 0.f); v1 = fmaxf(v1, 0.f); }
                    }
                    size_t idx = (size_t)row * ldout + col0;
                    if (SPLIT == 1)      split_store2(Ch, Cl, idx, v0, v1);
                    else if (SPLIT == 2) *(u32*)(Ch + idx) = pack_h2(v0, v1);
                    else                 *(float2*)(Cz + idx) = make_float2(v0, v1);
                }
            }
        }
    }
}

// ----------------------------------------------------------------------------
// Fused attention: one CTA per (b,h), 8 warps x 16 Q-rows. 2 CTAs/SM.
// ----------------------------------------------------------------------------
__global__ __launch_bounds__(256, 2)
void attn_fused(const bf16* __restrict__ qkvh, const bf16* __restrict__ qkvl,
                bf16* __restrict__ aoh, bf16* __restrict__ aol)
{
    extern __shared__ char smem[];
    const u32 base = smem_u32(smem);
    const int t = threadIdx.x, lane = t & 31, warp = t >> 5;
    const int bh = blockIdx.x, b = bh / HH, h = bh % HH;
    const size_t rowBase = (size_t)b * MM;
    const int g = lane >> 2, tg = lane & 3;

    #pragma unroll
    for (int m = 0; m < 6; m++) {
        const bf16* src = (m & 1) ? qkvl : qkvh;
        int colOff = (m >> 1) * DD + h * HD;
        u32 dst = base + m * 16384;
        #pragma unroll
        for (int p = 0; p < 4; p++) {
            int c = p * 256 + t;
            int row = c >> 3, ch = c & 7;
            u32 off = row * 128 + ((u32)(ch ^ (row & 7)) << 4);
            cp_async16(dst + off,
                       src + (rowBase + row) * (3 * DD) + colOff + ch * 8, 16);
        }
    }
    CP_COMMIT(); CP_WAIT0();
    __syncthreads();

    const u32 sQh = base, sQl = base + 16384;
    const u32 sKh = base + 32768, sKl = base + 49152;
    const u32 sVh = base + 65536, sVl = base + 81920;
    const int m0 = warp * 16;

    float acc[16][4];
    #pragma unroll
    for (int nj = 0; nj < 16; nj++)
        #pragma unroll
        for (int r = 0; r < 4; r++) acc[nj][r] = 0.f;

    const int tile = lane >> 3, wr = lane & 7;
    #pragma unroll
    for (int kk = 0; kk < 4; kk++) {
        u32 qh4[4], ql4[4];
        {
            int row = m0 + wr + (tile & 1) * 8;
            int ch = kk * 2 + (tile >> 1);
            u32 off = row * 128 + ((u32)(ch ^ (row & 7)) << 4);
            ldsm4(sQh + off, qh4[0], qh4[1], qh4[2], qh4[3]);
            ldsm4(sQl + off, ql4[0], ql4[1], ql4[2], ql4[3]);
        }
        #pragma unroll
        for (int nj2 = 0; nj2 < 8; nj2++) {
            int row = nj2 * 16 + wr + (tile >> 1) * 8;
            int ch = kk * 2 + (tile & 1);
            u32 off = row * 128 + ((u32)(ch ^ (row & 7)) << 4);
            u32 b0, b1, b2, b3, l0, l1, l2, l3;
            ldsm4(sKh + off, b0, b1, b2, b3);
            ldsm4(sKl + off, l0, l1, l2, l3);
            mma_bf16(acc[2 * nj2],     qh4, b0, b1);
            mma_bf16(acc[2 * nj2],     qh4, l0, l1);
            mma_bf16(acc[2 * nj2],     ql4, b0, b1);
            mma_bf16(acc[2 * nj2 + 1], qh4, b2, b3);
            mma_bf16(acc[2 * nj2 + 1], qh4, l2, l3);
            mma_bf16(acc[2 * nj2 + 1], ql4, b2, b3);
        }
    }

    {
        float mx0 = -1e30f, mx1 = -1e30f;
        #pragma unroll
        for (int nj = 0; nj < 16; nj++) {
            acc[nj][0] *= 0.125f; acc[nj][1] *= 0.125f;
            acc[nj][2] *= 0.125f; acc[nj][3] *= 0.125f;
            mx0 = fmaxf(mx0, fmaxf(acc[nj][0], acc[nj][1]));
            mx1 = fmaxf(mx1, fmaxf(acc[nj][2], acc[nj][3]));
        }
        mx0 = fmaxf(mx0, __shfl_xor_sync(~0u, mx0, 1));
        mx0 = fmaxf(mx0, __shfl_xor_sync(~0u, mx0, 2));
        mx1 = fmaxf(mx1, __shfl_xor_sync(~0u, mx1, 1));
        mx1 = fmaxf(mx1, __shfl_xor_sync(~0u, mx1, 2));
        float s0 = 0.f, s1 = 0.f;
        #pragma unroll
        for (int nj = 0; nj < 16; nj++) {
            acc[nj][0] = expf(acc[nj][0] - mx0);
            acc[nj][1] = expf(acc[nj][1] - mx0);
            acc[nj][2] = expf(acc[nj][2] - mx1);
            acc[nj][3] = expf(acc[nj][3] - mx1);
            s0 += acc[nj][0] + acc[nj][1];
            s1 += acc[nj][2] + acc[nj][3];
        }
        s0 += __shfl_xor_sync(~0u, s0, 1);
        s0 += __shfl_xor_sync(~0u, s0, 2);
        s1 += __shfl_xor_sync(~0u, s1, 1);
        s1 += __shfl_xor_sync(~0u, s1, 2);
        float i0 = 1.f / s0, i1 = 1.f / s1;
        #pragma unroll
        for (int nj = 0; nj < 16; nj++) {
            acc[nj][0] *= i0; acc[nj][1] *= i0;
            acc[nj][2] *= i1; acc[nj][3] *= i1;
        }
    }

    float o[8][4];
    #pragma unroll
    for (int nj = 0; nj < 8; nj++)
        #pragma unroll
        for (int r = 0; r < 4; r++) o[nj][r] = 0.f;

    #pragma unroll
    for (int j = 0; j < 8; j++) {
        u32 pa_h[4], pa_l[4];
        #pragma unroll
        for (int q = 0; q < 2; q++) {
            float p0 = acc[2 * j + q][0], p1 = acc[2 * j + q][1];
            float p2 = acc[2 * j + q][2], p3 = acc[2 * j + q][3];
            float h0 = bf_round(p0), h1 = bf_round(p1);
            float h2 = bf_round(p2), h3 = bf_round(p3);
            pa_h[0 + 2 * q] = pack_bf(h0, h1);
            pa_h[1 + 2 * q] = pack_bf(h2, h3);
            pa_l[0 + 2 * q] = pack_bf(p0 - h0, p1 - h1);
            pa_l[1 + 2 * q] = pack_bf(p2 - h2, p3 - h3);
        }
        #pragma unroll
        for (int c2 = 0; c2 < 4; c2++) {
            int row = j * 16 + wr + (tile & 1) * 8;
            int ch = 2 * c2 + (tile >> 1);
            u32 off = row * 128 + ((u32)(ch ^ (row & 7)) << 4);
            u32 v0, v1, v2, v3, w0, w1, w2, w3;
            ldsm4t(sVh + off, v0, v1, v2, v3);
            ldsm4t(sVl + off, w0, w1, w2, w3);
            mma_bf16(o[2 * c2],     pa_h, v0, v1);
            mma_bf16(o[2 * c2],     pa_h, w0, w1);
            mma_bf16(o[2 * c2],     pa_l, v0, v1);
            mma_bf16(o[2 * c2 + 1], pa_h, v2, v3);
            mma_bf16(o[2 * c2 + 1], pa_h, w2, w3);
            mma_bf16(o[2 * c2 + 1], pa_l, v2, v3);
        }
    }

    {
        size_t gr = rowBase + m0 + g;
        #pragma unroll
        for (int nj = 0; nj < 8; nj++) {
            int col = h * HD + nj * 8 + 2 * tg;
            split_store2(aoh, aol, gr * DD + col, o[nj][0], o[nj][1]);
            split_store2(aoh, aol, (gr + 8) * DD + col, o[nj][2], o[nj][3]);
        }
    }
}

// ----------------------------------------------------------------------------
// x = LayerNorm(x + d0 + d1 + bias) * w + b; writes bf16 split of x
// ----------------------------------------------------------------------------
__global__ __launch_bounds__(256)
void add_ln_kernel(float* __restrict__ x,
                   const float* __restrict__ d0p, const float* __restrict__ d1p,
                   const float* __restrict__ bias,
                   const float* __restrict__ w, const float* __restrict__ b,
                   bf16* __restrict__ xh, bf16* __restrict__ xl)
{
    int row = blockIdx.x, t = threadIdx.x;
    float* xp = x + (size_t)row * DD;
    const float* a0 = d0p + (size_t)row * DD;
    const float* a1 = d1p + (size_t)row * DD;
    float v0 = xp[t]       + a0[t]       + a1[t]       + bias[t];
    float v1 = xp[t + 256] + a0[t + 256] + a1[t + 256] + bias[t + 256];
    float v2 = xp[t + 512] + a0[t + 512] + a1[t + 512] + bias[t + 512];
    float s = v0 + v1 + v2;
    __shared__ float red[8];
    #pragma unroll
    for (int o = 16; o; o >>= 1) s += __shfl_xor_sync(~0u, s, o);
    if ((t & 31) == 0) red[t >> 5] = s;
    __syncthreads();
    float tot = red[0] + red[1] + red[2] + red[3] + red[4] + red[5] + red[6] + red[7];
    float mu = tot * (1.f / 768.f);
    float d0 = v0 - mu, d1 = v1 - mu, d2 = v2 - mu;
    float q = d0 * d0 + d1 * d1 + d2 * d2;
    #pragma unroll
    for (int o = 16; o; o >>= 1) q += __shfl_xor_sync(~0u, q, o);
    __syncthreads();
    if ((t & 31) == 0) red[t >> 5] = q;
    __syncthreads();
    float qt = red[0] + red[1] + red[2] + red[3] + red[4] + red[5] + red[6] + red[7];
    float inv = rsqrtf(qt * (1.f / 768.f) + 1e-5f);
    float o0 = d0 * inv * w[t]       + b[t];
    float o1 = d1 * inv * w[t + 256] + b[t + 256];
    float o2 = d2 * inv * w[t + 512] + b[t + 512];
    size_t rb = (size_t)row * DD;
    xp[t] = o0;       split_write(xh, xl, rb + t,       o0);
    xp[t + 256] = o1; split_write(xh, xl, rb + t + 256, o1);
    xp[t + 512] = o2; split_write(xh, xl, rb + t + 512, o2);
}

// ----------------------------------------------------------------------------
// Host-side launch
// ----------------------------------------------------------------------------
template<typename T>
static T* sym(const void* s)
{
    void* p = nullptr;
    cudaGetSymbolAddress(&p, s);
    return (T*)p;
}

#define SMEM_G(TM, TN, NA) (3 * ((NA) * (TM) * 64 + 2 * (TN) * 64))
#define SMEMATT (6 * 16384)

extern "C" void kernel_launch(void* const* d_in, const int* in_sizes, int n_in,
                              void* d_out, int out_size)
{
    static const long long want[20] = {
        6291456LL, 65536LL, 2048LL, 768LL, 1LL,
        7077888LL, 9216LL, 2359296LL, 3072LL, 3072LL, 3072LL,
        9437184LL, 12288LL, 9437184LL, 3072LL, 3072LL, 3072LL,
        76800LL, 5000000LL, 50000LL
    };
    const void* slot[20];
    bool used[64];
    for (int i = 0; i < 20; i++) slot[i] = nullptr;
    for (int i = 0; i < n_in && i < 64; i++) used[i] = false;
    for (int w = 0; w < 20; w++) {
        for (int i = 0; i < n_in && i < 64; i++) {
            if (!used[i] && (long long)in_sizes[i] == want[w]) {
                slot[w] = d_in[i];
                used[i] = true;
                break;
            }
        }
    }
    if (!slot[0]) {
        for (int w = 0; w < 20 && w < n_in; w++) slot[w] = d_in[w];
    }

    const float* lhs    = (const float*)slot[0];
    const int*   pos    = (const int*)slot[1];
    const int*   mask   = (const int*)slot[2];
    const float* attn_w = (const float*)slot[3];
    const float* qkv_w  = (const float*)slot[5];
    const float* qkv_b  = (const float*)slot[6];
    const float* out_w  = (const float*)slot[7];
    const float* out_b  = (const float*)slot[8];
    const float* ln1_w  = (const float*)slot[9];
    const float* ln1_b  = (const float*)slot[10];
    const float* ff1_w  = (const float*)slot[11];
    const float* ff1_b  = (const float*)slot[12];
    const float* ff2_w  = (const float*)slot[13];
    const float* ff2_b  = (const float*)slot[14];
    const float* ln2_w  = (const float*)slot[15];
    const float* ln2_b  = (const float*)slot[16];
    const float* cls_w1 = (const float*)slot[17];
    const float* cls_w2 = (const float*)slot[18];
    const float* cls_b2 = (const float*)slot[19];
    float* out = (float*)d_out;

    float* x   = sym<float>(g_x);
    float* tmp = sym<float>(g_tmp);
    bf16*  wh  = sym<bf16>(g_wh);
    bf16*  wl  = sym<bf16>(g_wl);
    bf16*  ah  = sym<bf16>(g_ah);
    bf16*  al  = sym<bf16>(g_al);
    bf16*  bh2 = sym<bf16>(g_bh);
    bf16*  bl2 = sym<bf16>(g_bl);

    cudaFuncSetAttribute(gemm_tc<128, 128, 0, 1, 0>, cudaFuncAttributeMaxDynamicSharedMemorySize, SMEM_G(128, 128, 2));
    cudaFuncSetAttribute(gemm_tc<64, 64, 0, 0, 0>,   cudaFuncAttributeMaxDynamicSharedMemorySize, SMEM_G(64, 64, 2));
    cudaFuncSetAttribute(gemm_tc<128, 64, 1, 1, 0>,  cudaFuncAttributeMaxDynamicSharedMemorySize, SMEM_G(128, 64, 2));
    cudaFuncSetAttribute(gemm_tc<128, 64, 0, 2, 0>,  cudaFuncAttributeMaxDynamicSharedMemorySize, SMEM_G(128, 64, 2));
    cudaFuncSetAttribute(gemm_tc<128, 128, 0, 0, 1>, cudaFuncAttributeMaxDynamicSharedMemorySize, SMEM_G(128, 128, 1));
    cudaFuncSetAttribute(attn_fused, cudaFuncAttributeMaxDynamicSharedMemorySize, SMEMATT);

    // --- weight conversion ---
    cvt_all_kernel<<<6934, 256>>>(qkv_w, out_w, ff1_w, ff2_w, cls_w1, wh, wl);
    cvt_pad_kernel<<<2736, 256>>>(cls_w2, wh + OW_CLS2, wl + OW_CLS2);

    // --- mention pooling (inline logits; writes x + split) ---
    pool_kernel<<<ROWS, 256>>>(lhs, pos, mask, attn_w, x, ah, al);

    // --- transformer layers ---
    for (int i = 0; i < NL; i++) {
        gemm_tc<128, 128, 0, 1, 0><<<dim3(18, 16, 1), 256, SMEM_G(128, 128, 2)>>>(
            ah, al, wh + OW_QKV + (size_t)i * 3 * DD * DD,
            wl + OW_QKV + (size_t)i * 3 * DD * DD,
            qkv_b + (size_t)i * 3 * DD, nullptr, bh2, bl2,
            ROWS, 3 * DD, DD, DD, DD, 3 * DD, 3 * DD);
        attn_fused<<<BB * HH, 256, SMEMATT>>>(bh2, bl2, ah, al);
        // out-proj: split-K 2, partials to tmp[0], tmp[1]
        gemm_tc<64, 64, 0, 0, 0><<<dim3(12, 32, 2), 256, SMEM_G(64, 64, 2)>>>(
            ah, al, wh + OW_OUT + (size_t)i * DD * DD,
            wl + OW_OUT + (size_t)i * DD * DD,
            nullptr, tmp, nullptr, nullptr,
            ROWS, DD, DD, DD, DD / 2, DD, DD);
        add_ln_kernel<<<ROWS, 256>>>(x, tmp, tmp + (size_t)ROWS * DD,
                                     out_b + (size_t)i * DD,
                                     ln1_w + (size_t)i * DD, ln1_b + (size_t)i * DD,
                                     ah, al);
        gemm_tc<128, 64, 1, 1, 0><<<dim3(48, 16, 1), 256, SMEM_G(128, 64, 2)>>>(
            ah, al, wh + OW_FF1 + (size_t)i * DFF * DD,
            wl + OW_FF1 + (size_t)i * DFF * DD,
            ff1_b + (size_t)i * DFF, nullptr, bh2, bl2,
            ROWS, DFF, DD, DD, DD, DFF, DFF);
        // ff2: split-K 2
        gemm_tc<64, 64, 0, 0, 0><<<dim3(12, 32, 2), 256, SMEM_G(64, 64, 2)>>>(
            bh2, bl2, wh + OW_FF2 + (size_t)i * DD * DFF,
            wl + OW_FF2 + (size_t)i * DD * DFF,
            nullptr, tmp, nullptr, nullptr,
            ROWS, DD, DFF, DFF, DFF / 2, DD, DD);
        add_ln_kernel<<<ROWS, 256>>>(x, tmp, tmp + (size_t)ROWS * DD,
                                     ff2_b + (size_t)i * DD,
                                     ln2_w + (size_t)i * DD, ln2_b + (size_t)i * DD,
                                     ah, al);
    }

    // --- classifier head ---
    // cls1: bf16 3-term, output y as fp16 single into bh2 ([ROWS, KPAD])
    gemm_tc<128, 64, 0, 2, 0><<<dim3(2, 16, 1), 256, SMEM_G(128, 64, 2)>>>(
        ah, al, wh + OW_CLS1, wl + OW_CLS1, nullptr,
        nullptr, bh2, nullptr, ROWS, 100, DD, DD, DD, KPAD, KPAD);
    // cls2: fp16 2-term (A = y fp16 single, B = cls_w2 fp16 hi/lo)
    gemm_tc<128, 128, 0, 0, 1><<<dim3((NE + 127) / 128, 16, 1), 256, SMEM_G(128, 128, 1)>>>(
        bh2, nullptr, wh + OW_CLS2, wl + OW_CLS2, cls_b2,
        out, nullptr, nullptr, ROWS, NE, KPAD, KPAD, KPAD, NE, NE);
}

// round 11
// speedup vs baseline: 4.4198x; 1.0072x over previous
#include <cuda_runtime.h>
#include <cuda_bf16.h>
#include <cuda_fp16.h>
#include <math.h>
#include <cstdint>

// ----------------------------------------------------------------------------
// Problem constants
// ----------------------------------------------------------------------------
#define BB   16
#define MM   128
#define LL   32
#define SS   512
#define DD   768
#define HH   12
#define HD   64
#define DFF  3072
#define NL   4
#define NE   50000
#define ROWS (BB*MM)          // 2048
#define KPAD 112              // padded K for classifier stage 2

typedef unsigned long long ull;
typedef unsigned int u32;
typedef __nv_bfloat16 bf16;

// weight scratch offsets (elements)
#define OW_QKV  0ULL
#define OW_OUT  7077888ULL
#define OW_FF1  9437184ULL
#define OW_FF2  18874368ULL
#define OW_CLS1 28311552ULL
#define OW_CLS2 28388352ULL
#define NW_TOT  (28388352ULL + 50000ULL*KPAD)

// ----------------------------------------------------------------------------
// Device scratch (static allocation — no cudaMalloc allowed)
// ----------------------------------------------------------------------------
__device__ float g_x [ROWS*DD];
__device__ float g_tmp[ROWS*DFF];            // split-K partials (2 x ROWS*DD)
__device__ __align__(256) bf16 g_wh[NW_TOT];
__device__ __align__(256) bf16 g_wl[NW_TOT];
__device__ __align__(256) bf16 g_ah[ROWS*DFF];
__device__ __align__(256) bf16 g_al[ROWS*DFF];
__device__ __align__(256) bf16 g_bh[ROWS*DFF];
__device__ __align__(256) bf16 g_bl[ROWS*DFF];

// ----------------------------------------------------------------------------
// PTX helpers
// ----------------------------------------------------------------------------
__device__ __forceinline__ u32 smem_u32(const void* p)
{
    u32 a;
    asm("{ .reg .u64 t; cvta.to.shared.u64 t, %1; cvt.u32.u64 %0, t; }"
        : "=r"(a) : "l"(p));
    return a;
}

__device__ __forceinline__ void cp_async16(u32 dst, const void* src, int sz)
{
    asm volatile("cp.async.cg.shared.global [%0], [%1], 16, %2;"
        :: "r"(dst), "l"(src), "r"(sz));
}
#define CP_COMMIT() asm volatile("cp.async.commit_group;" ::: "memory")
#define CP_WAIT1()  asm volatile("cp.async.wait_group 1;" ::: "memory")
#define CP_WAIT0()  asm volatile("cp.async.wait_group 0;" ::: "memory")

__device__ __forceinline__ void ldsm4(u32 addr, u32& r0, u32& r1, u32& r2, u32& r3)
{
    asm volatile("ldmatrix.sync.aligned.m8n8.x4.shared.b16 {%0,%1,%2,%3}, [%4];"
        : "=r"(r0), "=r"(r1), "=r"(r2), "=r"(r3) : "r"(addr));
}
__device__ __forceinline__ void ldsm4t(u32 addr, u32& r0, u32& r1, u32& r2, u32& r3)
{
    asm volatile("ldmatrix.sync.aligned.m8n8.x4.trans.shared.b16 {%0,%1,%2,%3}, [%4];"
        : "=r"(r0), "=r"(r1), "=r"(r2), "=r"(r3) : "r"(addr));
}

__device__ __forceinline__ void mma_bf16(float* d, const u32* a, u32 b0, u32 b1)
{
    asm volatile(
        "mma.sync.aligned.m16n8k16.row.col.f32.bf16.bf16.f32 "
        "{%0,%1,%2,%3},{%4,%5,%6,%7},{%8,%9},{%0,%1,%2,%3};"
        : "+f"(d[0]), "+f"(d[1]), "+f"(d[2]), "+f"(d[3])
        : "r"(a[0]), "r"(a[1]), "r"(a[2]), "r"(a[3]), "r"(b0), "r"(b1));
}
__device__ __forceinline__ void mma_f16(float* d, const u32* a, u32 b0, u32 b1)
{
    asm volatile(
        "mma.sync.aligned.m16n8k16.row.col.f32.f16.f16.f32 "
        "{%0,%1,%2,%3},{%4,%5,%6,%7},{%8,%9},{%0,%1,%2,%3};"
        : "+f"(d[0]), "+f"(d[1]), "+f"(d[2]), "+f"(d[3])
        : "r"(a[0]), "r"(a[1]), "r"(a[2]), "r"(a[3]), "r"(b0), "r"(b1));
}

// pack two fp32 into bf16x2 word: first arg -> lower halfword
__device__ __forceinline__ u32 pack_bf(float lo, float hi)
{
    u32 r;
    asm("cvt.rn.bf16x2.f32 %0, %1, %2;" : "=r"(r) : "f"(hi), "f"(lo));
    return r;
}
__device__ __forceinline__ u32 pack_h2(float lo, float hi)
{
    __half2 h = __floats2half2_rn(lo, hi);
    return *(u32*)&h;
}

__device__ __forceinline__ float bf_round(float v)
{
    return __bfloat162float(__float2bfloat16(v));
}

__device__ __forceinline__ void split_write(bf16* h, bf16* l, size_t idx, float v)
{
    bf16 hh = __float2bfloat16(v);
    h[idx] = hh;
    l[idx] = __float2bfloat16(v - __bfloat162float(hh));
}

__device__ __forceinline__ void split_store2(bf16* h, bf16* l, size_t idx,
                                             float v0, float v1)
{
    float h0 = bf_round(v0), h1 = bf_round(v1);
    *(u32*)(h + idx) = pack_bf(h0, h1);
    *(u32*)(l + idx) = pack_bf(v0 - h0, v1 - h1);
}

// ----------------------------------------------------------------------------
// Fused weight conversion (bf16 splits): 5 contiguous segments in wh/wl.
// ----------------------------------------------------------------------------
__global__ void cvt_all_kernel(const float* __restrict__ s0,
                               const float* __restrict__ s1,
                               const float* __restrict__ s2,
                               const float* __restrict__ s3,
                               const float* __restrict__ s4,
                               bf16* __restrict__ h, bf16* __restrict__ l)
{
    const long long Bn0 = 884736, Bn1 = 1179648, Bn2 = 2359296,
                    Bn3 = 3538944, Bn4 = 3548544;
    for (long long i = (long long)blockIdx.x * 256 + threadIdx.x; i < Bn4;
         i += (long long)gridDim.x * 256) {
        const float* src;
        long long basei;
        if (i < Bn0)      { src = s0; basei = 0; }
        else if (i < Bn1) { src = s1; basei = Bn0; }
        else if (i < Bn2) { src = s2; basei = Bn1; }
        else if (i < Bn3) { src = s3; basei = Bn2; }
        else              { src = s4; basei = Bn3; }
        const float4* xp = (const float4*)src + 2 * (i - basei);
        float4 a = xp[0], b = xp[1];
        float h0 = bf_round(a.x), h1 = bf_round(a.y),
              h2 = bf_round(a.z), h3 = bf_round(a.w),
              h4 = bf_round(b.x), h5 = bf_round(b.y),
              h6 = bf_round(b.z), h7 = bf_round(b.w);
        uint4 H, L;
        H.x = pack_bf(h0, h1); H.y = pack_bf(h2, h3);
        H.z = pack_bf(h4, h5); H.w = pack_bf(h6, h7);
        L.x = pack_bf(a.x - h0, a.y - h1); L.y = pack_bf(a.z - h2, a.w - h3);
        L.z = pack_bf(b.x - h4, b.y - h5); L.w = pack_bf(b.z - h6, b.w - h7);
        ((uint4*)h)[i] = H;
        ((uint4*)l)[i] = L;
    }
}

// cls_w2: [NE,100] -> [NE,112] zero-padded FP16 hi/lo split
__global__ void cvt_pad_kernel(const float* __restrict__ x,
                               bf16* __restrict__ h, bf16* __restrict__ l)
{
    int total = NE * 28;
    for (int i = blockIdx.x * 256 + threadIdx.x; i < total; i += gridDim.x * 256) {
        int r = i / 28, c4 = (i - r * 28) * 4;
        u32 ha = 0, hb = 0, la = 0, lb = 0;
        if (c4 < 100) {
            float4 v = *(const float4*)(x + (size_t)r * 100 + c4);
            float h0 = __half2float(__float2half_rn(v.x));
            float h1 = __half2float(__float2half_rn(v.y));
            float h2 = __half2float(__float2half_rn(v.z));
            float h3 = __half2float(__float2half_rn(v.w));
            ha = pack_h2(h0, h1); hb = pack_h2(h2, h3);
            la = pack_h2(v.x - h0, v.y - h1); lb = pack_h2(v.z - h2, v.w - h3);
        }
        size_t o = (size_t)r * KPAD + c4;
        *(uint2*)(h + o) = make_uint2(ha, hb);
        *(uint2*)(l + o) = make_uint2(la, lb);
    }
}

// ----------------------------------------------------------------------------
// Mention pooling (pos/mask int32), inline attention logits.
// ----------------------------------------------------------------------------
__global__ __launch_bounds__(256)
void pool_kernel(const float* __restrict__ lhs,
                 const int* __restrict__ pos,
                 const int* __restrict__ mask,
                 const float* __restrict__ aw,
                 float* __restrict__ x,
                 bf16* __restrict__ xh, bf16* __restrict__ xl)
{
    int bm = blockIdx.x;
    int b = bm >> 7;
    int t = threadIdx.x;
    __shared__ float dots[LL];
    __shared__ float ws[LL];
    __shared__ int s_nv;

    {
        int l = t >> 3, sub = t & 7;
        const float* row = lhs + ((size_t)b * SS + l) * DD;
        float p = 0.f;
        for (int j = sub; j < DD; j += 8) p += row[j] * aw[j];
        #pragma unroll
        for (int o = 4; o; o >>= 1) p += __shfl_xor_sync(~0u, p, o);
        if (sub == 0) dots[l] = p;
    }
    __syncthreads();

    if (t < 32) {
        int p = pos[(size_t)bm * LL + t];
        unsigned bits = __ballot_sync(0xffffffffu, p != -1);
        int nv;
        if (mask[bm] == 0) nv = 0;
        else if (~bits == 0u) nv = 32;
        else nv = __ffs(~bits) - 1;
        float logit = (t < nv) ? dots[t] : 0.f;
        float mx = logit;
        #pragma unroll
        for (int o = 16; o; o >>= 1) mx = fmaxf(mx, __shfl_xor_sync(~0u, mx, o));
        float e = expf(logit - mx);
        float s = e;
        #pragma unroll
        for (int o = 16; o; o >>= 1) s += __shfl_xor_sync(~0u, s, o);
        ws[t] = e / s;
        if (t == 0) s_nv = nv;
    }
    __syncthreads();
    int nv = s_nv;
    for (int d = t; d < DD; d += 256) {
        float acc = 0.f;
        for (int l = 0; l < nv; l++)
            acc += ws[l] * lhs[((size_t)b * SS + l) * DD + d];
        size_t idx = (size_t)bm * DD + d;
        x[idx] = acc;
        split_write(xh, xl, idx, acc);
    }
}

// ----------------------------------------------------------------------------
// Tensor-core split NT GEMM: mma.sync + ldmatrix + 3-stage cp.async ring.
// OCC CTAs/SM (template). CTA tile TM x TN. 8 warps: 4m x 2n.
// PREC=0: bf16 A(hi,lo) x B(hi,lo), 3 mmas. PREC=1: fp16 A(hi) x B(hi,lo), 2 mmas.
// SPLIT=0 -> fp32 C (+ blockIdx.z * M*ldout); SPLIT=1 -> bf16 hi/lo;
// SPLIT=2 -> fp16 single (Ch). cols [N,padN) zeroed.
// lda/ldb row strides; Klen = K per z-slice (blockIdx.z*Klen offset).
// ----------------------------------------------------------------------------
template<int TM, int TN, int RELU, int SPLIT, int PREC, int OCC>
__global__ __launch_bounds__(256, OCC)
void gemm_tc(const bf16* __restrict__ Ah, const bf16* __restrict__ Al,
             const bf16* __restrict__ Bh, const bf16* __restrict__ Bl,
             const float* __restrict__ bias,
             float* __restrict__ C, bf16* __restrict__ Ch, bf16* __restrict__ Cl,
             int M, int N, int lda, int ldb, int Klen, int ldout, int padN)
{
    constexpr int MI  = TM / 64;
    constexpr int NJW = TN / 16;
    constexpr int NA  = (PREC == 0) ? 2 : 1;
    constexpr int ASZ = TM * 64;
    constexpr int BSZ = TN * 64;
    constexpr int BUF = NA * ASZ + 2 * BSZ;

    extern __shared__ char smem[];
    const u32 base = smem_u32(smem);
    const int t = threadIdx.x, lane = t & 31, warp = t >> 5;
    const int mBase = blockIdx.y * TM, nBase = blockIdx.x * TN;
    const int kOff = blockIdx.z * Klen;
    const int wm = (warp >> 1) * (TM / 4), wn = (warp & 1) * (TN / 2);
    const int ar0 = wm + (lane & 15);
    const int ahi = lane >> 4;
    const int br0 = wn + (lane & 7) + ((lane >> 4) << 3);
    const int bhi = (lane >> 3) & 1;

    float acc[MI][NJW][4];
    #pragma unroll
    for (int mi = 0; mi < MI; mi++)
        #pragma unroll
        for (int nj = 0; nj < NJW; nj++)
            #pragma unroll
            for (int r = 0; r < 4; r++) acc[mi][nj][r] = 0.f;

    const int S = (Klen + 31) / 32;

    auto loadSlab = [&](int s) {
        const int k0 = s * 32;
        const u32 bb = base + (s % 3) * BUF;
        #pragma unroll
        for (int p = 0; p < TM / 64; p++) {
            int c = p * 256 + t, row = c >> 2, ch = c & 3;
            int kk = k0 + ch * 8;
            int avail = Klen - kk;
            int sz = (avail >= 8) ? 16 : (avail > 0 ? avail * 2 : 0);
            u32 off = row * 64 + ((u32)(ch ^ ((row >> 1) & 3)) << 4);
            cp_async16(bb + off, Ah + (size_t)(mBase + row) * lda + kOff + kk, sz);
            if (PREC == 0)
                cp_async16(bb + ASZ + off, Al + (size_t)(mBase + row) * lda + kOff + kk, sz);
        }
        #pragma unroll
        for (int p = 0; p < TN / 64; p++) {
            int c = p * 256 + t, row = c >> 2, ch = c & 3;
            int kk = k0 + ch * 8;
            int avail = Klen - kk;
            int sz = (avail >= 8) ? 16 : (avail > 0 ? avail * 2 : 0);
            if (nBase + row >= N) sz = 0;
            u32 off = row * 64 + ((u32)(ch ^ ((row >> 1) & 3)) << 4);
            cp_async16(bb + NA * ASZ + off, Bh + (size_t)(nBase + row) * ldb + kOff + kk, sz);
            cp_async16(bb + NA * ASZ + BSZ + off, Bl + (size_t)(nBase + row) * ldb + kOff + kk, sz);
        }
    };

    loadSlab(0);
    CP_COMMIT();
    if (S > 1) loadSlab(1);
    CP_COMMIT();

    for (int s = 0; s < S; s++) {
        CP_WAIT1();
        __syncthreads();
        if (s + 2 < S) loadSlab(s + 2);
        CP_COMMIT();

        const u32 bb = base + (s % 3) * BUF;
        const u32 aB0 = bb, aB1 = bb + ASZ;
        const u32 bB0 = bb + NA * ASZ, bB1 = bb + NA * ASZ + BSZ;

        #pragma unroll
        for (int ks = 0; ks < 2; ks++) {
            u32 ahf[MI][4], alf[MI][4];
            #pragma unroll
            for (int mi = 0; mi < MI; mi++) {
                int row = ar0 + mi * 16;
                u32 off = row * 64 + ((u32)((ks * 2 + ahi) ^ ((row >> 1) & 3)) << 4);
                ldsm4(aB0 + off, ahf[mi][0], ahf[mi][1], ahf[mi][2], ahf[mi][3]);
                if (PREC == 0)
                    ldsm4(aB1 + off, alf[mi][0], alf[mi][1], alf[mi][2], alf[mi][3]);
            }
            #pragma unroll
            for (int j = 0; j < NJW / 2; j++) {
                int row = br0 + j * 16;
                u32 off = row * 64 + ((u32)((ks * 2 + bhi) ^ ((row >> 1) & 3)) << 4);
                u32 b0, b1, b2, b3, l0, l1, l2, l3;
                ldsm4(bB0 + off, b0, b1, b2, b3);
                ldsm4(bB1 + off, l0, l1, l2, l3);
                #pragma unroll
                for (int mi = 0; mi < MI; mi++) {
                    if (PREC == 0) {
                        mma_bf16(acc[mi][2 * j],     ahf[mi], b0, b1);
                        mma_bf16(acc[mi][2 * j],     ahf[mi], l0, l1);
                        mma_bf16(acc[mi][2 * j],     alf[mi], b0, b1);
                        mma_bf16(acc[mi][2 * j + 1], ahf[mi], b2, b3);
                        mma_bf16(acc[mi][2 * j + 1], ahf[mi], l2, l3);
                        mma_bf16(acc[mi][2 * j + 1], alf[mi], b2, b3);
                    } else {
                        mma_f16(acc[mi][2 * j],     ahf[mi], b0, b1);
                        mma_f16(acc[mi][2 * j],     ahf[mi], l0, l1);
                        mma_f16(acc[mi][2 * j + 1], ahf[mi], b2, b3);
                        mma_f16(acc[mi][2 * j + 1], ahf[mi], l2, l3);
                    }
                }
            }
        }
    }

    // epilogue
    float* Cz = C + (size_t)blockIdx.z * M * ldout;
    const int g = lane >> 2, tg = lane & 3;
    #pragma unroll
    for (int mi = 0; mi < MI; mi++) {
        int row0 = mBase + wm + mi * 16 + g;
        #pragma unroll
        for (int nj = 0; nj < NJW; nj++) {
            int col0 = nBase + wn + nj * 8 + 2 * tg;
            if (col0 < padN) {
                #pragma unroll
                for (int rr = 0; rr < 2; rr++) {
                    int row = row0 + rr * 8;
                    float v0 = 0.f, v1 = 0.f;
                    if (col0 < N) {
                        v0 = acc[mi][nj][rr * 2 + 0] + (bias ? bias[col0] : 0.f);
                        v1 = acc[mi][nj][rr * 2 + 1] + (bias ? bias[col0 + 1] : 0.f);
                        if (RELU) { v0 = fmaxf(v0, 0.f); v1 = fmaxf(v1, 0.f); }
                    }
                    size_t idx = (size_t)row * ldout + col0;
                    if (SPLIT == 1)      split_store2(Ch, Cl, idx, v0, v1);
                    else if (SPLIT == 2) *(u32*)(Ch + idx) = pack_h2(v0, v1);
                    else                 *(float2*)(Cz + idx) = make_float2(v0, v1);
                }
            }
        }
    }
}

// ----------------------------------------------------------------------------
// Fused attention: one CTA per (b,h), 8 warps x 16 Q-rows. 2 CTAs/SM.
// ----------------------------------------------------------------------------
__global__ __launch_bounds__(256, 2)
void attn_fused(const bf16* __restrict__ qkvh, const bf16* __restrict__ qkvl,
                bf16* __restrict__ aoh, bf16* __restrict__ aol)
{
    extern __shared__ char smem[];
    const u32 base = smem_u32(smem);
    const int t = threadIdx.x, lane = t & 31, warp = t >> 5;
    const int bh = blockIdx.x, b = bh / HH, h = bh % HH;
    const size_t rowBase = (size_t)b * MM;
    const int g = lane >> 2, tg = lane & 3;

    #pragma unroll
    for (int m = 0; m < 6; m++) {
        const bf16* src = (m & 1) ? qkvl : qkvh;
        int colOff = (m >> 1) * DD + h * HD;
        u32 dst = base + m * 16384;
        #pragma unroll
        for (int p = 0; p < 4; p++) {
            int c = p * 256 + t;
            int row = c >> 3, ch = c & 7;
            u32 off = row * 128 + ((u32)(ch ^ (row & 7)) << 4);
            cp_async16(dst + off,
                       src + (rowBase + row) * (3 * DD) + colOff + ch * 8, 16);
        }
    }
    CP_COMMIT(); CP_WAIT0();
    __syncthreads();

    const u32 sQh = base, sQl = base + 16384;
    const u32 sKh = base + 32768, sKl = base + 49152;
    const u32 sVh = base + 65536, sVl = base + 81920;
    const int m0 = warp * 16;

    float acc[16][4];
    #pragma unroll
    for (int nj = 0; nj < 16; nj++)
        #pragma unroll
        for (int r = 0; r < 4; r++) acc[nj][r] = 0.f;

    const int tile = lane >> 3, wr = lane & 7;
    #pragma unroll
    for (int kk = 0; kk < 4; kk++) {
        u32 qh4[4], ql4[4];
        {
            int row = m0 + wr + (tile & 1) * 8;
            int ch = kk * 2 + (tile >> 1);
            u32 off = row * 128 + ((u32)(ch ^ (row & 7)) << 4);
            ldsm4(sQh + off, qh4[0], qh4[1], qh4[2], qh4[3]);
            ldsm4(sQl + off, ql4[0], ql4[1], ql4[2], ql4[3]);
        }
        #pragma unroll
        for (int nj2 = 0; nj2 < 8; nj2++) {
            int row = nj2 * 16 + wr + (tile >> 1) * 8;
            int ch = kk * 2 + (tile & 1);
            u32 off = row * 128 + ((u32)(ch ^ (row & 7)) << 4);
            u32 b0, b1, b2, b3, l0, l1, l2, l3;
            ldsm4(sKh + off, b0, b1, b2, b3);
            ldsm4(sKl + off, l0, l1, l2, l3);
            mma_bf16(acc[2 * nj2],     qh4, b0, b1);
            mma_bf16(acc[2 * nj2],     qh4, l0, l1);
            mma_bf16(acc[2 * nj2],     ql4, b0, b1);
            mma_bf16(acc[2 * nj2 + 1], qh4, b2, b3);
            mma_bf16(acc[2 * nj2 + 1], qh4, l2, l3);
            mma_bf16(acc[2 * nj2 + 1], ql4, b2, b3);
        }
    }

    {
        float mx0 = -1e30f, mx1 = -1e30f;
        #pragma unroll
        for (int nj = 0; nj < 16; nj++) {
            acc[nj][0] *= 0.125f; acc[nj][1] *= 0.125f;
            acc[nj][2] *= 0.125f; acc[nj][3] *= 0.125f;
            mx0 = fmaxf(mx0, fmaxf(acc[nj][0], acc[nj][1]));
            mx1 = fmaxf(mx1, fmaxf(acc[nj][2], acc[nj][3]));
        }
        mx0 = fmaxf(mx0, __shfl_xor_sync(~0u, mx0, 1));
        mx0 = fmaxf(mx0, __shfl_xor_sync(~0u, mx0, 2));
        mx1 = fmaxf(mx1, __shfl_xor_sync(~0u, mx1, 1));
        mx1 = fmaxf(mx1, __shfl_xor_sync(~0u, mx1, 2));
        float s0 = 0.f, s1 = 0.f;
        #pragma unroll
        for (int nj = 0; nj < 16; nj++) {
            acc[nj][0] = expf(acc[nj][0] - mx0);
            acc[nj][1] = expf(acc[nj][1] - mx0);
            acc[nj][2] = expf(acc[nj][2] - mx1);
            acc[nj][3] = expf(acc[nj][3] - mx1);
            s0 += acc[nj][0] + acc[nj][1];
            s1 += acc[nj][2] + acc[nj][3];
        }
        s0 += __shfl_xor_sync(~0u, s0, 1);
        s0 += __shfl_xor_sync(~0u, s0, 2);
        s1 += __shfl_xor_sync(~0u, s1, 1);
        s1 += __shfl_xor_sync(~0u, s1, 2);
        float i0 = 1.f / s0, i1 = 1.f / s1;
        #pragma unroll
        for (int nj = 0; nj < 16; nj++) {
            acc[nj][0] *= i0; acc[nj][1] *= i0;
            acc[nj][2] *= i1; acc[nj][3] *= i1;
        }
    }

    float o[8][4];
    #pragma unroll
    for (int nj = 0; nj < 8; nj++)
        #pragma unroll
        for (int r = 0; r < 4; r++) o[nj][r] = 0.f;

    #pragma unroll
    for (int j = 0; j < 8; j++) {
        u32 pa_h[4], pa_l[4];
        #pragma unroll
        for (int q = 0; q < 2; q++) {
            float p0 = acc[2 * j + q][0], p1 = acc[2 * j + q][1];
            float p2 = acc[2 * j + q][2], p3 = acc[2 * j + q][3];
            float h0 = bf_round(p0), h1 = bf_round(p1);
            float h2 = bf_round(p2), h3 = bf_round(p3);
            pa_h[0 + 2 * q] = pack_bf(h0, h1);
            pa_h[1 + 2 * q] = pack_bf(h2, h3);
            pa_l[0 + 2 * q] = pack_bf(p0 - h0, p1 - h1);
            pa_l[1 + 2 * q] = pack_bf(p2 - h2, p3 - h3);
        }
        #pragma unroll
        for (int c2 = 0; c2 < 4; c2++) {
            int row = j * 16 + wr + (tile & 1) * 8;
            int ch = 2 * c2 + (tile >> 1);
            u32 off = row * 128 + ((u32)(ch ^ (row & 7)) << 4);
            u32 v0, v1, v2, v3, w0, w1, w2, w3;
            ldsm4t(sVh + off, v0, v1, v2, v3);
            ldsm4t(sVl + off, w0, w1, w2, w3);
            mma_bf16(o[2 * c2],     pa_h, v0, v1);
            mma_bf16(o[2 * c2],     pa_h, w0, w1);
            mma_bf16(o[2 * c2],     pa_l, v0, v1);
            mma_bf16(o[2 * c2 + 1], pa_h, v2, v3);
            mma_bf16(o[2 * c2 + 1], pa_h, w2, w3);
            mma_bf16(o[2 * c2 + 1], pa_l, v2, v3);
        }
    }

    {
        size_t gr = rowBase + m0 + g;
        #pragma unroll
        for (int nj = 0; nj < 8; nj++) {
            int col = h * HD + nj * 8 + 2 * tg;
            split_store2(aoh, aol, gr * DD + col, o[nj][0], o[nj][1]);
            split_store2(aoh, aol, (gr + 8) * DD + col, o[nj][2], o[nj][3]);
        }
    }
}

// ----------------------------------------------------------------------------
// x = LayerNorm(x + d0 + d1 + bias) * w + b; writes bf16 split of x
// ----------------------------------------------------------------------------
__global__ __launch_bounds__(256)
void add_ln_kernel(float* __restrict__ x,
                   const float* __restrict__ d0p, const float* __restrict__ d1p,
                   const float* __restrict__ bias,
                   const float* __restrict__ w, const float* __restrict__ b,
                   bf16* __restrict__ xh, bf16* __restrict__ xl)
{
    int row = blockIdx.x, t = threadIdx.x;
    float* xp = x + (size_t)row * DD;
    const float* a0 = d0p + (size_t)row * DD;
    const float* a1 = d1p + (size_t)row * DD;
    float v0 = xp[t]       + a0[t]       + a1[t]       + bias[t];
    float v1 = xp[t + 256] + a0[t + 256] + a1[t + 256] + bias[t + 256];
    float v2 = xp[t + 512] + a0[t + 512] + a1[t + 512] + bias[t + 512];
    float s = v0 + v1 + v2;
    __shared__ float red[8];
    #pragma unroll
    for (int o = 16; o; o >>= 1) s += __shfl_xor_sync(~0u, s, o);
    if ((t & 31) == 0) red[t >> 5] = s;
    __syncthreads();
    float tot = red[0] + red[1] + red[2] + red[3] + red[4] + red[5] + red[6] + red[7];
    float mu = tot * (1.f / 768.f);
    float d0 = v0 - mu, d1 = v1 - mu, d2 = v2 - mu;
    float q = d0 * d0 + d1 * d1 + d2 * d2;
    #pragma unroll
    for (int o = 16; o; o >>= 1) q += __shfl_xor_sync(~0u, q, o);
    __syncthreads();
    if ((t & 31) == 0) red[t >> 5] = q;
    __syncthreads();
    float qt = red[0] + red[1] + red[2] + red[3] + red[4] + red[5] + red[6] + red[7];
    float inv = rsqrtf(qt * (1.f / 768.f) + 1e-5f);
    float o0 = d0 * inv * w[t]       + b[t];
    float o1 = d1 * inv * w[t + 256] + b[t + 256];
    float o2 = d2 * inv * w[t + 512] + b[t + 512];
    size_t rb = (size_t)row * DD;
    xp[t] = o0;       split_write(xh, xl, rb + t,       o0);
    xp[t + 256] = o1; split_write(xh, xl, rb + t + 256, o1);
    xp[t + 512] = o2; split_write(xh, xl, rb + t + 512, o2);
}

// ----------------------------------------------------------------------------
// Host-side launch
// ----------------------------------------------------------------------------
template<typename T>
static T* sym(const void* s)
{
    void* p = nullptr;
    cudaGetSymbolAddress(&p, s);
    return (T*)p;
}

#define SMEM_G(TM, TN, NA) (3 * ((NA) * (TM) * 64 + 2 * (TN) * 64))
#define SMEMATT (6 * 16384)

extern "C" void kernel_launch(void* const* d_in, const int* in_sizes, int n_in,
                              void* d_out, int out_size)
{
    static const long long want[20] = {
        6291456LL, 65536LL, 2048LL, 768LL, 1LL,
        7077888LL, 9216LL, 2359296LL, 3072LL, 3072LL, 3072LL,
        9437184LL, 12288LL, 9437184LL, 3072LL, 3072LL, 3072LL,
        76800LL, 5000000LL, 50000LL
    };
    const void* slot[20];
    bool used[64];
    for (int i = 0; i < 20; i++) slot[i] = nullptr;
    for (int i = 0; i < n_in && i < 64; i++) used[i] = false;
    for (int w = 0; w < 20; w++) {
        for (int i = 0; i < n_in && i < 64; i++) {
            if (!used[i] && (long long)in_sizes[i] == want[w]) {
                slot[w] = d_in[i];
                used[i] = true;
                break;
            }
        }
    }
    if (!slot[0]) {
        for (int w = 0; w < 20 && w < n_in; w++) slot[w] = d_in[w];
    }

    const float* lhs    = (const float*)slot[0];
    const int*   pos    = (const int*)slot[1];
    const int*   mask   = (const int*)slot[2];
    const float* attn_w = (const float*)slot[3];
    const float* qkv_w  = (const float*)slot[5];
    const float* qkv_b  = (const float*)slot[6];
    const float* out_w  = (const float*)slot[7];
    const float* out_b  = (const float*)slot[8];
    const float* ln1_w  = (const float*)slot[9];
    const float* ln1_b  = (const float*)slot[10];
    const float* ff1_w  = (const float*)slot[11];
    const float* ff1_b  = (const float*)slot[12];
    const float* ff2_w  = (const float*)slot[13];
    const float* ff2_b  = (const float*)slot[14];
    const float* ln2_w  = (const float*)slot[15];
    const float* ln2_b  = (const float*)slot[16];
    const float* cls_w1 = (const float*)slot[17];
    const float* cls_w2 = (const float*)slot[18];
    const float* cls_b2 = (const float*)slot[19];
    float* out = (float*)d_out;

    float* x   = sym<float>(g_x);
    float* tmp = sym<float>(g_tmp);
    bf16*  wh  = sym<bf16>(g_wh);
    bf16*  wl  = sym<bf16>(g_wl);
    bf16*  ah  = sym<bf16>(g_ah);
    bf16*  al  = sym<bf16>(g_al);
    bf16*  bh2 = sym<bf16>(g_bh);
    bf16*  bl2 = sym<bf16>(g_bl);

    cudaFuncSetAttribute(gemm_tc<128, 64, 0, 1, 0, 3>, cudaFuncAttributeMaxDynamicSharedMemorySize, SMEM_G(128, 64, 2));
    cudaFuncSetAttribute(gemm_tc<128, 64, 0, 0, 0, 3>, cudaFuncAttributeMaxDynamicSharedMemorySize, SMEM_G(128, 64, 2));
    cudaFuncSetAttribute(gemm_tc<128, 64, 1, 1, 0, 3>, cudaFuncAttributeMaxDynamicSharedMemorySize, SMEM_G(128, 64, 2));
    cudaFuncSetAttribute(gemm_tc<128, 64, 0, 2, 0, 3>, cudaFuncAttributeMaxDynamicSharedMemorySize, SMEM_G(128, 64, 2));
    cudaFuncSetAttribute(gemm_tc<128, 128, 0, 0, 1, 2>, cudaFuncAttributeMaxDynamicSharedMemorySize, SMEM_G(128, 128, 1));
    cudaFuncSetAttribute(attn_fused, cudaFuncAttributeMaxDynamicSharedMemorySize, SMEMATT);

    // --- weight conversion ---
    cvt_all_kernel<<<6934, 256>>>(qkv_w, out_w, ff1_w, ff2_w, cls_w1, wh, wl);
    cvt_pad_kernel<<<2736, 256>>>(cls_w2, wh + OW_CLS2, wl + OW_CLS2);

    // --- mention pooling (inline logits; writes x + split) ---
    pool_kernel<<<ROWS, 256>>>(lhs, pos, mask, attn_w, x, ah, al);

    // --- transformer layers ---
    for (int i = 0; i < NL; i++) {
        gemm_tc<128, 64, 0, 1, 0, 3><<<dim3(36, 16, 1), 256, SMEM_G(128, 64, 2)>>>(
            ah, al, wh + OW_QKV + (size_t)i * 3 * DD * DD,
            wl + OW_QKV + (size_t)i * 3 * DD * DD,
            qkv_b + (size_t)i * 3 * DD, nullptr, bh2, bl2,
            ROWS, 3 * DD, DD, DD, DD, 3 * DD, 3 * DD);
        attn_fused<<<BB * HH, 256, SMEMATT>>>(bh2, bl2, ah, al);
        // out-proj: split-K 2, partials to tmp[0], tmp[1]
        gemm_tc<128, 64, 0, 0, 0, 3><<<dim3(12, 16, 2), 256, SMEM_G(128, 64, 2)>>>(
            ah, al, wh + OW_OUT + (size_t)i * DD * DD,
            wl + OW_OUT + (size_t)i * DD * DD,
            nullptr, tmp, nullptr, nullptr,
            ROWS, DD, DD, DD, DD / 2, DD, DD);
        add_ln_kernel<<<ROWS, 256>>>(x, tmp, tmp + (size_t)ROWS * DD,
                                     out_b + (size_t)i * DD,
                                     ln1_w + (size_t)i * DD, ln1_b + (size_t)i * DD,
                                     ah, al);
        gemm_tc<128, 64, 1, 1, 0, 3><<<dim3(48, 16, 1), 256, SMEM_G(128, 64, 2)>>>(
            ah, al, wh + OW_FF1 + (size_t)i * DFF * DD,
            wl + OW_FF1 + (size_t)i * DFF * DD,
            ff1_b + (size_t)i * DFF, nullptr, bh2, bl2,
            ROWS, DFF, DD, DD, DD, DFF, DFF);
        // ff2: split-K 2
        gemm_tc<128, 64, 0, 0, 0, 3><<<dim3(12, 16, 2), 256, SMEM_G(128, 64, 2)>>>(
            bh2, bl2, wh + OW_FF2 + (size_t)i * DD * DFF,
            wl + OW_FF2 + (size_t)i * DD * DFF,
            nullptr, tmp, nullptr, nullptr,
            ROWS, DD, DFF, DFF, DFF / 2, DD, DD);
        add_ln_kernel<<<ROWS, 256>>>(x, tmp, tmp + (size_t)ROWS * DD,
                                     ff2_b + (size_t)i * DD,
                                     ln2_w + (size_t)i * DD, ln2_b + (size_t)i * DD,
                                     ah, al);
    }

    // --- classifier head ---
    // cls1: bf16 3-term, output y as fp16 single into bh2 ([ROWS, KPAD])
    gemm_tc<128, 64, 0, 2, 0, 3><<<dim3(2, 16, 1), 256, SMEM_G(128, 64, 2)>>>(
        ah, al, wh + OW_CLS1, wl + OW_CLS1, nullptr,
        nullptr, bh2, nullptr, ROWS, 100, DD, DD, DD, KPAD, KPAD);
    // cls2: fp16 2-term (A = y fp16 single, B = cls_w2 fp16 hi/lo)
    gemm_tc<128, 128, 0, 0, 1, 2><<<dim3((NE + 127) / 128, 16, 1), 256, SMEM_G(128, 128, 1)>>>(
        bh2, nullptr, wh + OW_CLS2, wl + OW_CLS2, cls_b2,
        out, nullptr, nullptr, ROWS, NE, KPAD, KPAD, KPAD, NE, NE);
}

// round 12
// speedup vs baseline: 4.6013x; 1.0411x over previous
#include <cuda_runtime.h>
#include <cuda_bf16.h>
#include <cuda_fp16.h>
#include <math.h>
#include <cstdint>

// ----------------------------------------------------------------------------
// Problem constants
// ----------------------------------------------------------------------------
#define BB   16
#define MM   128
#define LL   32
#define SS   512
#define DD   768
#define HH   12
#define HD   64
#define DFF  3072
#define NL   4
#define NE   50000
#define ROWS (BB*MM)          // 2048
#define KPAD 112              // padded K for classifier stage 2

typedef unsigned long long ull;
typedef unsigned int u32;
typedef __nv_bfloat16 bf16;

// weight scratch offsets (elements)
#define OW_QKV  0ULL
#define OW_OUT  7077888ULL
#define OW_FF1  9437184ULL
#define OW_FF2  18874368ULL
#define OW_CLS1 28311552ULL
#define OW_CLS2 28388352ULL
#define NW_TOT  (28388352ULL + 50000ULL*KPAD)

// ----------------------------------------------------------------------------
// Device scratch (static allocation — no cudaMalloc allowed)
// ----------------------------------------------------------------------------
__device__ float g_x [ROWS*DD];
__device__ float g_tmp[ROWS*DFF];            // split-K partials (2 x ROWS*DD)
__device__ __align__(256) bf16 g_wh[NW_TOT];
__device__ __align__(256) bf16 g_wl[NW_TOT];
__device__ __align__(256) bf16 g_ah[ROWS*DFF];
__device__ __align__(256) bf16 g_al[ROWS*DFF];
__device__ __align__(256) bf16 g_bh[ROWS*DFF];
__device__ __align__(256) bf16 g_bl[ROWS*DFF];

// ----------------------------------------------------------------------------
// PTX helpers
// ----------------------------------------------------------------------------
__device__ __forceinline__ u32 smem_u32(const void* p)
{
    u32 a;
    asm("{ .reg .u64 t; cvta.to.shared.u64 t, %1; cvt.u32.u64 %0, t; }"
        : "=r"(a) : "l"(p));
    return a;
}

__device__ __forceinline__ void cp_async16(u32 dst, const void* src, int sz)
{
    asm volatile("cp.async.cg.shared.global [%0], [%1], 16, %2;"
        :: "r"(dst), "l"(src), "r"(sz));
}
#define CP_COMMIT() asm volatile("cp.async.commit_group;" ::: "memory")
#define CP_WAIT1()  asm volatile("cp.async.wait_group 1;" ::: "memory")
#define CP_WAIT0()  asm volatile("cp.async.wait_group 0;" ::: "memory")

__device__ __forceinline__ void ldsm4(u32 addr, u32& r0, u32& r1, u32& r2, u32& r3)
{
    asm volatile("ldmatrix.sync.aligned.m8n8.x4.shared.b16 {%0,%1,%2,%3}, [%4];"
        : "=r"(r0), "=r"(r1), "=r"(r2), "=r"(r3) : "r"(addr));
}
__device__ __forceinline__ void ldsm4t(u32 addr, u32& r0, u32& r1, u32& r2, u32& r3)
{
    asm volatile("ldmatrix.sync.aligned.m8n8.x4.trans.shared.b16 {%0,%1,%2,%3}, [%4];"
        : "=r"(r0), "=r"(r1), "=r"(r2), "=r"(r3) : "r"(addr));
}

__device__ __forceinline__ void mma_bf16(float* d, const u32* a, u32 b0, u32 b1)
{
    asm volatile(
        "mma.sync.aligned.m16n8k16.row.col.f32.bf16.bf16.f32 "
        "{%0,%1,%2,%3},{%4,%5,%6,%7},{%8,%9},{%0,%1,%2,%3};"
        : "+f"(d[0]), "+f"(d[1]), "+f"(d[2]), "+f"(d[3])
        : "r"(a[0]), "r"(a[1]), "r"(a[2]), "r"(a[3]), "r"(b0), "r"(b1));
}
__device__ __forceinline__ void mma_f16(float* d, const u32* a, u32 b0, u32 b1)
{
    asm volatile(
        "mma.sync.aligned.m16n8k16.row.col.f32.f16.f16.f32 "
        "{%0,%1,%2,%3},{%4,%5,%6,%7},{%8,%9},{%0,%1,%2,%3};"
        : "+f"(d[0]), "+f"(d[1]), "+f"(d[2]), "+f"(d[3])
        : "r"(a[0]), "r"(a[1]), "r"(a[2]), "r"(a[3]), "r"(b0), "r"(b1));
}

// pack two fp32 into bf16x2 word: first arg -> lower halfword
__device__ __forceinline__ u32 pack_bf(float lo, float hi)
{
    u32 r;
    asm("cvt.rn.bf16x2.f32 %0, %1, %2;" : "=r"(r) : "f"(hi), "f"(lo));
    return r;
}
__device__ __forceinline__ u32 pack_h2(float lo, float hi)
{
    __half2 h = __floats2half2_rn(lo, hi);
    return *(u32*)&h;
}

__device__ __forceinline__ float bf_round(float v)
{
    return __bfloat162float(__float2bfloat16(v));
}

__device__ __forceinline__ void split_write(bf16* h, bf16* l, size_t idx, float v)
{
    bf16 hh = __float2bfloat16(v);
    h[idx] = hh;
    l[idx] = __float2bfloat16(v - __bfloat162float(hh));
}

__device__ __forceinline__ void split_store2(bf16* h, bf16* l, size_t idx,
                                             float v0, float v1)
{
    float h0 = bf_round(v0), h1 = bf_round(v1);
    *(u32*)(h + idx) = pack_bf(h0, h1);
    *(u32*)(l + idx) = pack_bf(v0 - h0, v1 - h1);
}

// ----------------------------------------------------------------------------
// Fused weight conversion (bf16 splits): 5 contiguous segments in wh/wl.
// ----------------------------------------------------------------------------
__global__ void cvt_all_kernel(const float* __restrict__ s0,
                               const float* __restrict__ s1,
                               const float* __restrict__ s2,
                               const float* __restrict__ s3,
                               const float* __restrict__ s4,
                               bf16* __restrict__ h, bf16* __restrict__ l)
{
    const long long Bn0 = 884736, Bn1 = 1179648, Bn2 = 2359296,
                    Bn3 = 3538944, Bn4 = 3548544;
    for (long long i = (long long)blockIdx.x * 256 + threadIdx.x; i < Bn4;
         i += (long long)gridDim.x * 256) {
        const float* src;
        long long basei;
        if (i < Bn0)      { src = s0; basei = 0; }
        else if (i < Bn1) { src = s1; basei = Bn0; }
        else if (i < Bn2) { src = s2; basei = Bn1; }
        else if (i < Bn3) { src = s3; basei = Bn2; }
        else              { src = s4; basei = Bn3; }
        const float4* xp = (const float4*)src + 2 * (i - basei);
        float4 a = xp[0], b = xp[1];
        float h0 = bf_round(a.x), h1 = bf_round(a.y),
              h2 = bf_round(a.z), h3 = bf_round(a.w),
              h4 = bf_round(b.x), h5 = bf_round(b.y),
              h6 = bf_round(b.z), h7 = bf_round(b.w);
        uint4 H, L;
        H.x = pack_bf(h0, h1); H.y = pack_bf(h2, h3);
        H.z = pack_bf(h4, h5); H.w = pack_bf(h6, h7);
        L.x = pack_bf(a.x - h0, a.y - h1); L.y = pack_bf(a.z - h2, a.w - h3);
        L.z = pack_bf(b.x - h4, b.y - h5); L.w = pack_bf(b.z - h6, b.w - h7);
        ((uint4*)h)[i] = H;
        ((uint4*)l)[i] = L;
    }
}

// cls_w2: [NE,100] -> [NE,112] zero-padded FP16 single (hi only; 1-term cls2)
__global__ void cvt_pad_kernel(const float* __restrict__ x,
                               bf16* __restrict__ h)
{
    int total = NE * 28;
    for (int i = blockIdx.x * 256 + threadIdx.x; i < total; i += gridDim.x * 256) {
        int r = i / 28, c4 = (i - r * 28) * 4;
        u32 ha = 0, hb = 0;
        if (c4 < 100) {
            float4 v = *(const float4*)(x + (size_t)r * 100 + c4);
            ha = pack_h2(v.x, v.y); hb = pack_h2(v.z, v.w);
        }
        size_t o = (size_t)r * KPAD + c4;
        *(uint2*)(h + o) = make_uint2(ha, hb);
    }
}

// ----------------------------------------------------------------------------
// Mention pooling (pos/mask int32), inline attention logits.
// ----------------------------------------------------------------------------
__global__ __launch_bounds__(256)
void pool_kernel(const float* __restrict__ lhs,
                 const int* __restrict__ pos,
                 const int* __restrict__ mask,
                 const float* __restrict__ aw,
                 float* __restrict__ x,
                 bf16* __restrict__ xh, bf16* __restrict__ xl)
{
    int bm = blockIdx.x;
    int b = bm >> 7;
    int t = threadIdx.x;
    __shared__ float dots[LL];
    __shared__ float ws[LL];
    __shared__ int s_nv;

    {
        int l = t >> 3, sub = t & 7;
        const float* row = lhs + ((size_t)b * SS + l) * DD;
        float p = 0.f;
        for (int j = sub; j < DD; j += 8) p += row[j] * aw[j];
        #pragma unroll
        for (int o = 4; o; o >>= 1) p += __shfl_xor_sync(~0u, p, o);
        if (sub == 0) dots[l] = p;
    }
    __syncthreads();

    if (t < 32) {
        int p = pos[(size_t)bm * LL + t];
        unsigned bits = __ballot_sync(0xffffffffu, p != -1);
        int nv;
        if (mask[bm] == 0) nv = 0;
        else if (~bits == 0u) nv = 32;
        else nv = __ffs(~bits) - 1;
        float logit = (t < nv) ? dots[t] : 0.f;
        float mx = logit;
        #pragma unroll
        for (int o = 16; o; o >>= 1) mx = fmaxf(mx, __shfl_xor_sync(~0u, mx, o));
        float e = expf(logit - mx);
        float s = e;
        #pragma unroll
        for (int o = 16; o; o >>= 1) s += __shfl_xor_sync(~0u, s, o);
        ws[t] = e / s;
        if (t == 0) s_nv = nv;
    }
    __syncthreads();
    int nv = s_nv;
    for (int d = t; d < DD; d += 256) {
        float acc = 0.f;
        for (int l = 0; l < nv; l++)
            acc += ws[l] * lhs[((size_t)b * SS + l) * DD + d];
        size_t idx = (size_t)bm * DD + d;
        x[idx] = acc;
        split_write(xh, xl, idx, acc);
    }
}

// ----------------------------------------------------------------------------
// Tensor-core split NT GEMM: mma.sync + ldmatrix + 3-stage cp.async ring.
// OCC CTAs/SM (template). CTA tile TM x TN. 8 warps: 4m x 2n.
// PREC=0: bf16 A(hi,lo) x B(hi,lo), 3 mmas.
// PREC=1: fp16 A(hi) x B(hi,lo), 2 mmas.
// PREC=2: fp16 A(hi) x B(hi), 1 mma.
// SPLIT=0 -> fp32 C (+ blockIdx.z * M*ldout); SPLIT=1 -> bf16 hi/lo;
// SPLIT=2 -> fp16 single (Ch). cols [N,padN) zeroed.
// lda/ldb row strides; Klen = K per z-slice (blockIdx.z*Klen offset).
// ----------------------------------------------------------------------------
template<int TM, int TN, int RELU, int SPLIT, int PREC, int OCC>
__global__ __launch_bounds__(256, OCC)
void gemm_tc(const bf16* __restrict__ Ah, const bf16* __restrict__ Al,
             const bf16* __restrict__ Bh, const bf16* __restrict__ Bl,
             const float* __restrict__ bias,
             float* __restrict__ C, bf16* __restrict__ Ch, bf16* __restrict__ Cl,
             int M, int N, int lda, int ldb, int Klen, int ldout, int padN)
{
    constexpr int MI  = TM / 64;
    constexpr int NJW = TN / 16;
    constexpr int NA  = (PREC == 0) ? 2 : 1;
    constexpr int NB  = (PREC == 2) ? 1 : 2;
    constexpr int ASZ = TM * 64;
    constexpr int BSZ = TN * 64;
    constexpr int BUF = NA * ASZ + NB * BSZ;

    extern __shared__ char smem[];
    const u32 base = smem_u32(smem);
    const int t = threadIdx.x, lane = t & 31, warp = t >> 5;
    const int mBase = blockIdx.y * TM, nBase = blockIdx.x * TN;
    const int kOff = blockIdx.z * Klen;
    const int wm = (warp >> 1) * (TM / 4), wn = (warp & 1) * (TN / 2);
    const int ar0 = wm + (lane & 15);
    const int ahi = lane >> 4;
    const int br0 = wn + (lane & 7) + ((lane >> 4) << 3);
    const int bhi = (lane >> 3) & 1;

    float acc[MI][NJW][4];
    #pragma unroll
    for (int mi = 0; mi < MI; mi++)
        #pragma unroll
        for (int nj = 0; nj < NJW; nj++)
            #pragma unroll
            for (int r = 0; r < 4; r++) acc[mi][nj][r] = 0.f;

    const int S = (Klen + 31) / 32;

    auto loadSlab = [&](int s) {
        const int k0 = s * 32;
        const u32 bb = base + (s % 3) * BUF;
        #pragma unroll
        for (int p = 0; p < TM / 64; p++) {
            int c = p * 256 + t, row = c >> 2, ch = c & 3;
            int kk = k0 + ch * 8;
            int avail = Klen - kk;
            int sz = (avail >= 8) ? 16 : (avail > 0 ? avail * 2 : 0);
            u32 off = row * 64 + ((u32)(ch ^ ((row >> 1) & 3)) << 4);
            cp_async16(bb + off, Ah + (size_t)(mBase + row) * lda + kOff + kk, sz);
            if (PREC == 0)
                cp_async16(bb + ASZ + off, Al + (size_t)(mBase + row) * lda + kOff + kk, sz);
        }
        #pragma unroll
        for (int p = 0; p < TN / 64; p++) {
            int c = p * 256 + t, row = c >> 2, ch = c & 3;
            int kk = k0 + ch * 8;
            int avail = Klen - kk;
            int sz = (avail >= 8) ? 16 : (avail > 0 ? avail * 2 : 0);
            if (nBase + row >= N) sz = 0;
            u32 off = row * 64 + ((u32)(ch ^ ((row >> 1) & 3)) << 4);
            cp_async16(bb + NA * ASZ + off, Bh + (size_t)(nBase + row) * ldb + kOff + kk, sz);
            if (PREC < 2)
                cp_async16(bb + NA * ASZ + BSZ + off, Bl + (size_t)(nBase + row) * ldb + kOff + kk, sz);
        }
    };

    loadSlab(0);
    CP_COMMIT();
    if (S > 1) loadSlab(1);
    CP_COMMIT();

    for (int s = 0; s < S; s++) {
        CP_WAIT1();
        __syncthreads();
        if (s + 2 < S) loadSlab(s + 2);
        CP_COMMIT();

        const u32 bb = base + (s % 3) * BUF;
        const u32 aB0 = bb, aB1 = bb + ASZ;
        const u32 bB0 = bb + NA * ASZ, bB1 = bb + NA * ASZ + BSZ;

        #pragma unroll
        for (int ks = 0; ks < 2; ks++) {
            u32 ahf[MI][4], alf[MI][4];
            #pragma unroll
            for (int mi = 0; mi < MI; mi++) {
                int row = ar0 + mi * 16;
                u32 off = row * 64 + ((u32)((ks * 2 + ahi) ^ ((row >> 1) & 3)) << 4);
                ldsm4(aB0 + off, ahf[mi][0], ahf[mi][1], ahf[mi][2], ahf[mi][3]);
                if (PREC == 0)
                    ldsm4(aB1 + off, alf[mi][0], alf[mi][1], alf[mi][2], alf[mi][3]);
            }
            #pragma unroll
            for (int j = 0; j < NJW / 2; j++) {
                int row = br0 + j * 16;
                u32 off = row * 64 + ((u32)((ks * 2 + bhi) ^ ((row >> 1) & 3)) << 4);
                u32 b0, b1, b2, b3, l0, l1, l2, l3;
                ldsm4(bB0 + off, b0, b1, b2, b3);
                if (PREC < 2) ldsm4(bB1 + off, l0, l1, l2, l3);
                #pragma unroll
                for (int mi = 0; mi < MI; mi++) {
                    if (PREC == 0) {
                        mma_bf16(acc[mi][2 * j],     ahf[mi], b0, b1);
                        mma_bf16(acc[mi][2 * j],     ahf[mi], l0, l1);
                        mma_bf16(acc[mi][2 * j],     alf[mi], b0, b1);
                        mma_bf16(acc[mi][2 * j + 1], ahf[mi], b2, b3);
                        mma_bf16(acc[mi][2 * j + 1], ahf[mi], l2, l3);
                        mma_bf16(acc[mi][2 * j + 1], alf[mi], b2, b3);
                    } else if (PREC == 1) {
                        mma_f16(acc[mi][2 * j],     ahf[mi], b0, b1);
                        mma_f16(acc[mi][2 * j],     ahf[mi], l0, l1);
                        mma_f16(acc[mi][2 * j + 1], ahf[mi], b2, b3);
                        mma_f16(acc[mi][2 * j + 1], ahf[mi], l2, l3);
                    } else {
                        mma_f16(acc[mi][2 * j],     ahf[mi], b0, b1);
                        mma_f16(acc[mi][2 * j + 1], ahf[mi], b2, b3);
                    }
                }
            }
        }
    }

    // epilogue
    float* Cz = C + (size_t)blockIdx.z * M * ldout;
    const int g = lane >> 2, tg = lane & 3;
    #pragma unroll
    for (int mi = 0; mi < MI; mi++) {
        int row0 = mBase + wm + mi * 16 + g;
        #pragma unroll
        for (int nj = 0; nj < NJW; nj++) {
            int col0 = nBase + wn + nj * 8 + 2 * tg;
            if (col0 < padN) {
                #pragma unroll
                for (int rr = 0; rr < 2; rr++) {
                    int row = row0 + rr * 8;
                    float v0 = 0.f, v1 = 0.f;
                    if (col0 < N) {
                        v0 = acc[mi][nj][rr * 2 + 0] + (bias ? bias[col0] : 0.f);
                        v1 = acc[mi][nj][rr * 2 + 1] + (bias ? bias[col0 + 1] : 0.f);
                        if (RELU) { v0 = fmaxf(v0, 0.f); v1 = fmaxf(v1, 0.f); }
                    }
                    size_t idx = (size_t)row * ldout + col0;
                    if (SPLIT == 1)      split_store2(Ch, Cl, idx, v0, v1);
                    else if (SPLIT == 2) *(u32*)(Ch + idx) = pack_h2(v0, v1);
                    else                 *(float2*)(Cz + idx) = make_float2(v0, v1);
                }
            }
        }
    }
}

// ----------------------------------------------------------------------------
// Fused attention: one CTA per (b,h), 8 warps x 16 Q-rows. 2 CTAs/SM.
// ----------------------------------------------------------------------------
__global__ __launch_bounds__(256, 2)
void attn_fused(const bf16* __restrict__ qkvh, const bf16* __restrict__ qkvl,
                bf16* __restrict__ aoh, bf16* __restrict__ aol)
{
    extern __shared__ char smem[];
    const u32 base = smem_u32(smem);
    const int t = threadIdx.x, lane = t & 31, warp = t >> 5;
    const int bh = blockIdx.x, b = bh / HH, h = bh % HH;
    const size_t rowBase = (size_t)b * MM;
    const int g = lane >> 2, tg = lane & 3;

    #pragma unroll
    for (int m = 0; m < 6; m++) {
        const bf16* src = (m & 1) ? qkvl : qkvh;
        int colOff = (m >> 1) * DD + h * HD;
        u32 dst = base + m * 16384;
        #pragma unroll
        for (int p = 0; p < 4; p++) {
            int c = p * 256 + t;
            int row = c >> 3, ch = c & 7;
            u32 off = row * 128 + ((u32)(ch ^ (row & 7)) << 4);
            cp_async16(dst + off,
                       src + (rowBase + row) * (3 * DD) + colOff + ch * 8, 16);
        }
    }
    CP_COMMIT(); CP_WAIT0();
    __syncthreads();

    const u32 sQh = base, sQl = base + 16384;
    const u32 sKh = base + 32768, sKl = base + 49152;
    const u32 sVh = base + 65536, sVl = base + 81920;
    const int m0 = warp * 16;

    float acc[16][4];
    #pragma unroll
    for (int nj = 0; nj < 16; nj++)
        #pragma unroll
        for (int r = 0; r < 4; r++) acc[nj][r] = 0.f;

    const int tile = lane >> 3, wr = lane & 7;
    #pragma unroll
    for (int kk = 0; kk < 4; kk++) {
        u32 qh4[4], ql4[4];
        {
            int row = m0 + wr + (tile & 1) * 8;
            int ch = kk * 2 + (tile >> 1);
            u32 off = row * 128 + ((u32)(ch ^ (row & 7)) << 4);
            ldsm4(sQh + off, qh4[0], qh4[1], qh4[2], qh4[3]);
            ldsm4(sQl + off, ql4[0], ql4[1], ql4[2], ql4[3]);
        }
        #pragma unroll
        for (int nj2 = 0; nj2 < 8; nj2++) {
            int row = nj2 * 16 + wr + (tile >> 1) * 8;
            int ch = kk * 2 + (tile & 1);
            u32 off = row * 128 + ((u32)(ch ^ (row & 7)) << 4);
            u32 b0, b1, b2, b3, l0, l1, l2, l3;
            ldsm4(sKh + off, b0, b1, b2, b3);
            ldsm4(sKl + off, l0, l1, l2, l3);
            mma_bf16(acc[2 * nj2],     qh4, b0, b1);
            mma_bf16(acc[2 * nj2],     qh4, l0, l1);
            mma_bf16(acc[2 * nj2],     ql4, b0, b1);
            mma_bf16(acc[2 * nj2 + 1], qh4, b2, b3);
            mma_bf16(acc[2 * nj2 + 1], qh4, l2, l3);
            mma_bf16(acc[2 * nj2 + 1], ql4, b2, b3);
        }
    }

    {
        float mx0 = -1e30f, mx1 = -1e30f;
        #pragma unroll
        for (int nj = 0; nj < 16; nj++) {
            acc[nj][0] *= 0.125f; acc[nj][1] *= 0.125f;
            acc[nj][2] *= 0.125f; acc[nj][3] *= 0.125f;
            mx0 = fmaxf(mx0, fmaxf(acc[nj][0], acc[nj][1]));
            mx1 = fmaxf(mx1, fmaxf(acc[nj][2], acc[nj][3]));
        }
        mx0 = fmaxf(mx0, __shfl_xor_sync(~0u, mx0, 1));
        mx0 = fmaxf(mx0, __shfl_xor_sync(~0u, mx0, 2));
        mx1 = fmaxf(mx1, __shfl_xor_sync(~0u, mx1, 1));
        mx1 = fmaxf(mx1, __shfl_xor_sync(~0u, mx1, 2));
        float s0 = 0.f, s1 = 0.f;
        #pragma unroll
        for (int nj = 0; nj < 16; nj++) {
            acc[nj][0] = expf(acc[nj][0] - mx0);
            acc[nj][1] = expf(acc[nj][1] - mx0);
            acc[nj][2] = expf(acc[nj][2] - mx1);
            acc[nj][3] = expf(acc[nj][3] - mx1);
            s0 += acc[nj][0] + acc[nj][1];
            s1 += acc[nj][2] + acc[nj][3];
        }
        s0 += __shfl_xor_sync(~0u, s0, 1);
        s0 += __shfl_xor_sync(~0u, s0, 2);
        s1 += __shfl_xor_sync(~0u, s1, 1);
        s1 += __shfl_xor_sync(~0u, s1, 2);
        float i0 = 1.f / s0, i1 = 1.f / s1;
        #pragma unroll
        for (int nj = 0; nj < 16; nj++) {
            acc[nj][0] *= i0; acc[nj][1] *= i0;
            acc[nj][2] *= i1; acc[nj][3] *= i1;
        }
    }

    float o[8][4];
    #pragma unroll
    for (int nj = 0; nj < 8; nj++)
        #pragma unroll
        for (int r = 0; r < 4; r++) o[nj][r] = 0.f;

    #pragma unroll
    for (int j = 0; j < 8; j++) {
        u32 pa_h[4], pa_l[4];
        #pragma unroll
        for (int q = 0; q < 2; q++) {
            float p0 = acc[2 * j + q][0], p1 = acc[2 * j + q][1];
            float p2 = acc[2 * j + q][2], p3 = acc[2 * j + q][3];
            float h0 = bf_round(p0), h1 = bf_round(p1);
            float h2 = bf_round(p2), h3 = bf_round(p3);
            pa_h[0 + 2 * q] = pack_bf(h0, h1);
            pa_h[1 + 2 * q] = pack_bf(h2, h3);
            pa_l[0 + 2 * q] = pack_bf(p0 - h0, p1 - h1);
            pa_l[1 + 2 * q] = pack_bf(p2 - h2, p3 - h3);
        }
        #pragma unroll
        for (int c2 = 0; c2 < 4; c2++) {
            int row = j * 16 + wr + (tile & 1) * 8;
            int ch = 2 * c2 + (tile >> 1);
            u32 off = row * 128 + ((u32)(ch ^ (row & 7)) << 4);
            u32 v0, v1, v2, v3, w0, w1, w2, w3;
            ldsm4t(sVh + off, v0, v1, v2, v3);
            ldsm4t(sVl + off, w0, w1, w2, w3);
            mma_bf16(o[2 * c2],     pa_h, v0, v1);
            mma_bf16(o[2 * c2],     pa_h, w0, w1);
            mma_bf16(o[2 * c2],     pa_l, v0, v1);
            mma_bf16(o[2 * c2 + 1], pa_h, v2, v3);
            mma_bf16(o[2 * c2 + 1], pa_h, w2, w3);
            mma_bf16(o[2 * c2 + 1], pa_l, v2, v3);
        }
    }

    {
        size_t gr = rowBase + m0 + g;
        #pragma unroll
        for (int nj = 0; nj < 8; nj++) {
            int col = h * HD + nj * 8 + 2 * tg;
            split_store2(aoh, aol, gr * DD + col, o[nj][0], o[nj][1]);
            split_store2(aoh, aol, (gr + 8) * DD + col, o[nj][2], o[nj][3]);
        }
    }
}

// ----------------------------------------------------------------------------
// x = LayerNorm(x + d0 + d1 + bias) * w + b; writes bf16 split of x
// ----------------------------------------------------------------------------
__global__ __launch_bounds__(256)
void add_ln_kernel(float* __restrict__ x,
                   const float* __restrict__ d0p, const float* __restrict__ d1p,
                   const float* __restrict__ bias,
                   const float* __restrict__ w, const float* __restrict__ b,
                   bf16* __restrict__ xh, bf16* __restrict__ xl)
{
    int row = blockIdx.x, t = threadIdx.x;
    float* xp = x + (size_t)row * DD;
    const float* a0 = d0p + (size_t)row * DD;
    const float* a1 = d1p + (size_t)row * DD;
    float v0 = xp[t]       + a0[t]       + a1[t]       + bias[t];
    float v1 = xp[t + 256] + a0[t + 256] + a1[t + 256] + bias[t + 256];
    float v2 = xp[t + 512] + a0[t + 512] + a1[t + 512] + bias[t + 512];
    float s = v0 + v1 + v2;
    __shared__ float red[8];
    #pragma unroll
    for (int o = 16; o; o >>= 1) s += __shfl_xor_sync(~0u, s, o);
    if ((t & 31) == 0) red[t >> 5] = s;
    __syncthreads();
    float tot = red[0] + red[1] + red[2] + red[3] + red[4] + red[5] + red[6] + red[7];
    float mu = tot * (1.f / 768.f);
    float d0 = v0 - mu, d1 = v1 - mu, d2 = v2 - mu;
    float q = d0 * d0 + d1 * d1 + d2 * d2;
    #pragma unroll
    for (int o = 16; o; o >>= 1) q += __shfl_xor_sync(~0u, q, o);
    __syncthreads();
    if ((t & 31) == 0) red[t >> 5] = q;
    __syncthreads();
    float qt = red[0] + red[1] + red[2] + red[3] + red[4] + red[5] + red[6] + red[7];
    float inv = rsqrtf(qt * (1.f / 768.f) + 1e-5f);
    float o0 = d0 * inv * w[t]       + b[t];
    float o1 = d1 * inv * w[t + 256] + b[t + 256];
    float o2 = d2 * inv * w[t + 512] + b[t + 512];
    size_t rb = (size_t)row * DD;
    xp[t] = o0;       split_write(xh, xl, rb + t,       o0);
    xp[t + 256] = o1; split_write(xh, xl, rb + t + 256, o1);
    xp[t + 512] = o2; split_write(xh, xl, rb + t + 512, o2);
}

// ----------------------------------------------------------------------------
// Host-side launch
// ----------------------------------------------------------------------------
template<typename T>
static T* sym(const void* s)
{
    void* p = nullptr;
    cudaGetSymbolAddress(&p, s);
    return (T*)p;
}

#define SMEM_G(TM, TN, NA, NB) (3 * ((NA) * (TM) * 64 + (NB) * (TN) * 64))
#define SMEMATT (6 * 16384)

extern "C" void kernel_launch(void* const* d_in, const int* in_sizes, int n_in,
                              void* d_out, int out_size)
{
    static const long long want[20] = {
        6291456LL, 65536LL, 2048LL, 768LL, 1LL,
        7077888LL, 9216LL, 2359296LL, 3072LL, 3072LL, 3072LL,
        9437184LL, 12288LL, 9437184LL, 3072LL, 3072LL, 3072LL,
        76800LL, 5000000LL, 50000LL
    };
    const void* slot[20];
    bool used[64];
    for (int i = 0; i < 20; i++) slot[i] = nullptr;
    for (int i = 0; i < n_in && i < 64; i++) used[i] = false;
    for (int w = 0; w < 20; w++) {
        for (int i = 0; i < n_in && i < 64; i++) {
            if (!used[i] && (long long)in_sizes[i] == want[w]) {
                slot[w] = d_in[i];
                used[i] = true;
                break;
            }
        }
    }
    if (!slot[0]) {
        for (int w = 0; w < 20 && w < n_in; w++) slot[w] = d_in[w];
    }

    const float* lhs    = (const float*)slot[0];
    const int*   pos    = (const int*)slot[1];
    const int*   mask   = (const int*)slot[2];
    const float* attn_w = (const float*)slot[3];
    const float* qkv_w  = (const float*)slot[5];
    const float* qkv_b  = (const float*)slot[6];
    const float* out_w  = (const float*)slot[7];
    const float* out_b  = (const float*)slot[8];
    const float* ln1_w  = (const float*)slot[9];
    const float* ln1_b  = (const float*)slot[10];
    const float* ff1_w  = (const float*)slot[11];
    const float* ff1_b  = (const float*)slot[12];
    const float* ff2_w  = (const float*)slot[13];
    const float* ff2_b  = (const float*)slot[14];
    const float* ln2_w  = (const float*)slot[15];
    const float* ln2_b  = (const float*)slot[16];
    const float* cls_w1 = (const float*)slot[17];
    const float* cls_w2 = (const float*)slot[18];
    const float* cls_b2 = (const float*)slot[19];
    float* out = (float*)d_out;

    float* x   = sym<float>(g_x);
    float* tmp = sym<float>(g_tmp);
    bf16*  wh  = sym<bf16>(g_wh);
    bf16*  wl  = sym<bf16>(g_wl);
    bf16*  ah  = sym<bf16>(g_ah);
    bf16*  al  = sym<bf16>(g_al);
    bf16*  bh2 = sym<bf16>(g_bh);
    bf16*  bl2 = sym<bf16>(g_bl);

    cudaFuncSetAttribute(gemm_tc<128, 128, 0, 1, 0, 2>, cudaFuncAttributeMaxDynamicSharedMemorySize, SMEM_G(128, 128, 2, 2));
    cudaFuncSetAttribute(gemm_tc<128, 64, 0, 0, 0, 3>,  cudaFuncAttributeMaxDynamicSharedMemorySize, SMEM_G(128, 64, 2, 2));
    cudaFuncSetAttribute(gemm_tc<128, 64, 1, 1, 0, 3>,  cudaFuncAttributeMaxDynamicSharedMemorySize, SMEM_G(128, 64, 2, 2));
    cudaFuncSetAttribute(gemm_tc<128, 64, 0, 2, 0, 3>,  cudaFuncAttributeMaxDynamicSharedMemorySize, SMEM_G(128, 64, 2, 2));
    cudaFuncSetAttribute(gemm_tc<128, 128, 0, 0, 2, 2>, cudaFuncAttributeMaxDynamicSharedMemorySize, SMEM_G(128, 128, 1, 1));
    cudaFuncSetAttribute(attn_fused, cudaFuncAttributeMaxDynamicSharedMemorySize, SMEMATT);

    // --- weight conversion ---
    cvt_all_kernel<<<6934, 256>>>(qkv_w, out_w, ff1_w, ff2_w, cls_w1, wh, wl);
    cvt_pad_kernel<<<2736, 256>>>(cls_w2, wh + OW_CLS2);

    // --- mention pooling (inline logits; writes x + split) ---
    pool_kernel<<<ROWS, 256>>>(lhs, pos, mask, attn_w, x, ah, al);

    // --- transformer layers ---
    for (int i = 0; i < NL; i++) {
        // qkv: TN=128/OCC=2 -> 288 CTAs = 0.97 wave
        gemm_tc<128, 128, 0, 1, 0, 2><<<dim3(18, 16, 1), 256, SMEM_G(128, 128, 2, 2)>>>(
            ah, al, wh + OW_QKV + (size_t)i * 3 * DD * DD,
            wl + OW_QKV + (size_t)i * 3 * DD * DD,
            qkv_b + (size_t)i * 3 * DD, nullptr, bh2, bl2,
            ROWS, 3 * DD, DD, DD, DD, 3 * DD, 3 * DD);
        attn_fused<<<BB * HH, 256, SMEMATT>>>(bh2, bl2, ah, al);
        // out-proj: split-K 2, partials to tmp[0], tmp[1]
        gemm_tc<128, 64, 0, 0, 0, 3><<<dim3(12, 16, 2), 256, SMEM_G(128, 64, 2, 2)>>>(
            ah, al, wh + OW_OUT + (size_t)i * DD * DD,
            wl + OW_OUT + (size_t)i * DD * DD,
            nullptr, tmp, nullptr, nullptr,
            ROWS, DD, DD, DD, DD / 2, DD, DD);
        add_ln_kernel<<<ROWS, 256>>>(x, tmp, tmp + (size_t)ROWS * DD,
                                     out_b + (size_t)i * DD,
                                     ln1_w + (size_t)i * DD, ln1_b + (size_t)i * DD,
                                     ah, al);
        gemm_tc<128, 64, 1, 1, 0, 3><<<dim3(48, 16, 1), 256, SMEM_G(128, 64, 2, 2)>>>(
            ah, al, wh + OW_FF1 + (size_t)i * DFF * DD,
            wl + OW_FF1 + (size_t)i * DFF * DD,
            ff1_b + (size_t)i * DFF, nullptr, bh2, bl2,
            ROWS, DFF, DD, DD, DD, DFF, DFF);
        // ff2: split-K 2
        gemm_tc<128, 64, 0, 0, 0, 3><<<dim3(12, 16, 2), 256, SMEM_G(128, 64, 2, 2)>>>(
            bh2, bl2, wh + OW_FF2 + (size_t)i * DD * DFF,
            wl + OW_FF2 + (size_t)i * DD * DFF,
            nullptr, tmp, nullptr, nullptr,
            ROWS, DD, DFF, DFF, DFF / 2, DD, DD);
        add_ln_kernel<<<ROWS, 256>>>(x, tmp, tmp + (size_t)ROWS * DD,
                                     ff2_b + (size_t)i * DD,
                                     ln2_w + (size_t)i * DD, ln2_b + (size_t)i * DD,
                                     ah, al);
    }

    // --- classifier head ---
    // cls1: bf16 3-term, output y as fp16 single into bh2 ([ROWS, KPAD])
    gemm_tc<128, 64, 0, 2, 0, 3><<<dim3(2, 16, 1), 256, SMEM_G(128, 64, 2, 2)>>>(
        ah, al, wh + OW_CLS1, wl + OW_CLS1, nullptr,
        nullptr, bh2, nullptr, ROWS, 100, DD, DD, DD, KPAD, KPAD);
    // cls2: fp16 1-term (A = y fp16 single, B = cls_w2 fp16 single)
    gemm_tc<128, 128, 0, 0, 2, 2><<<dim3((NE + 127) / 128, 16, 1), 256, SMEM_G(128, 128, 1, 1)>>>(
        bh2, nullptr, wh + OW_CLS2, nullptr, cls_b2,
        out, nullptr, nullptr, ROWS, NE, KPAD, KPAD, KPAD, NE, NE);
}

// round 13
// speedup vs baseline: 4.6776x; 1.0166x over previous
#include <cuda_runtime.h>
#include <cuda_bf16.h>
#include <cuda_fp16.h>
#include <math.h>
#include <cstdint>

// ----------------------------------------------------------------------------
// Problem constants
// ----------------------------------------------------------------------------
#define BB   16
#define MM   128
#define LL   32
#define SS   512
#define DD   768
#define HH   12
#define HD   64
#define DFF  3072
#define NL   4
#define NE   50000
#define ROWS (BB*MM)          // 2048
#define KPAD 112              // padded K for classifier stage 2

typedef unsigned long long ull;
typedef unsigned int u32;
typedef __nv_bfloat16 bf16;

// weight scratch offsets (elements)
#define OW_QKV  0ULL
#define OW_OUT  7077888ULL
#define OW_FF1  9437184ULL
#define OW_FF2  18874368ULL
#define OW_CLS1 28311552ULL
#define OW_CLS2 28388352ULL
#define NW_TOT  (28388352ULL + 50000ULL*KPAD)

// ----------------------------------------------------------------------------
// Device scratch (static allocation — no cudaMalloc allowed)
// ----------------------------------------------------------------------------
__device__ float g_x [ROWS*DD];
__device__ float g_tmp[ROWS*DFF];            // split-K partials (2 x ROWS*DD)
__device__ __align__(256) bf16 g_wh[NW_TOT];
__device__ __align__(256) bf16 g_wl[NW_TOT];
__device__ __align__(256) bf16 g_ah[ROWS*DFF];
__device__ __align__(256) bf16 g_al[ROWS*DFF];
__device__ __align__(256) bf16 g_bh[ROWS*DFF];
__device__ __align__(256) bf16 g_bl[ROWS*DFF];

// ----------------------------------------------------------------------------
// PTX helpers
// ----------------------------------------------------------------------------
__device__ __forceinline__ u32 smem_u32(const void* p)
{
    u32 a;
    asm("{ .reg .u64 t; cvta.to.shared.u64 t, %1; cvt.u32.u64 %0, t; }"
        : "=r"(a) : "l"(p));
    return a;
}

__device__ __forceinline__ void cp_async16(u32 dst, const void* src, int sz)
{
    asm volatile("cp.async.cg.shared.global [%0], [%1], 16, %2;"
        :: "r"(dst), "l"(src), "r"(sz));
}
#define CP_COMMIT() asm volatile("cp.async.commit_group;" ::: "memory")
#define CP_WAIT1()  asm volatile("cp.async.wait_group 1;" ::: "memory")
#define CP_WAIT0()  asm volatile("cp.async.wait_group 0;" ::: "memory")

__device__ __forceinline__ void ldsm4(u32 addr, u32& r0, u32& r1, u32& r2, u32& r3)
{
    asm volatile("ldmatrix.sync.aligned.m8n8.x4.shared.b16 {%0,%1,%2,%3}, [%4];"
        : "=r"(r0), "=r"(r1), "=r"(r2), "=r"(r3) : "r"(addr));
}
__device__ __forceinline__ void ldsm4t(u32 addr, u32& r0, u32& r1, u32& r2, u32& r3)
{
    asm volatile("ldmatrix.sync.aligned.m8n8.x4.trans.shared.b16 {%0,%1,%2,%3}, [%4];"
        : "=r"(r0), "=r"(r1), "=r"(r2), "=r"(r3) : "r"(addr));
}

__device__ __forceinline__ void mma_bf16(float* d, const u32* a, u32 b0, u32 b1)
{
    asm volatile(
        "mma.sync.aligned.m16n8k16.row.col.f32.bf16.bf16.f32 "
        "{%0,%1,%2,%3},{%4,%5,%6,%7},{%8,%9},{%0,%1,%2,%3};"
        : "+f"(d[0]), "+f"(d[1]), "+f"(d[2]), "+f"(d[3])
        : "r"(a[0]), "r"(a[1]), "r"(a[2]), "r"(a[3]), "r"(b0), "r"(b1));
}
__device__ __forceinline__ void mma_f16(float* d, const u32* a, u32 b0, u32 b1)
{
    asm volatile(
        "mma.sync.aligned.m16n8k16.row.col.f32.f16.f16.f32 "
        "{%0,%1,%2,%3},{%4,%5,%6,%7},{%8,%9},{%0,%1,%2,%3};"
        : "+f"(d[0]), "+f"(d[1]), "+f"(d[2]), "+f"(d[3])
        : "r"(a[0]), "r"(a[1]), "r"(a[2]), "r"(a[3]), "r"(b0), "r"(b1));
}

// pack two fp32 into bf16x2 word: first arg -> lower halfword
__device__ __forceinline__ u32 pack_bf(float lo, float hi)
{
    u32 r;
    asm("cvt.rn.bf16x2.f32 %0, %1, %2;" : "=r"(r) : "f"(hi), "f"(lo));
    return r;
}
__device__ __forceinline__ u32 pack_h2(float lo, float hi)
{
    __half2 h = __floats2half2_rn(lo, hi);
    return *(u32*)&h;
}

__device__ __forceinline__ float bf_round(float v)
{
    return __bfloat162float(__float2bfloat16(v));
}

__device__ __forceinline__ void split_write(bf16* h, bf16* l, size_t idx, float v)
{
    bf16 hh = __float2bfloat16(v);
    h[idx] = hh;
    l[idx] = __float2bfloat16(v - __bfloat162float(hh));
}

__device__ __forceinline__ void split_store2(bf16* h, bf16* l, size_t idx,
                                             float v0, float v1)
{
    float h0 = bf_round(v0), h1 = bf_round(v1);
    *(u32*)(h + idx) = pack_bf(h0, h1);
    *(u32*)(l + idx) = pack_bf(v0 - h0, v1 - h1);
}

// ----------------------------------------------------------------------------
// Fused weight conversion (bf16 splits): 5 contiguous segments in wh/wl.
// ----------------------------------------------------------------------------
__global__ void cvt_all_kernel(const float* __restrict__ s0,
                               const float* __restrict__ s1,
                               const float* __restrict__ s2,
                               const float* __restrict__ s3,
                               const float* __restrict__ s4,
                               bf16* __restrict__ h, bf16* __restrict__ l)
{
    const long long Bn0 = 884736, Bn1 = 1179648, Bn2 = 2359296,
                    Bn3 = 3538944, Bn4 = 3548544;
    for (long long i = (long long)blockIdx.x * 256 + threadIdx.x; i < Bn4;
         i += (long long)gridDim.x * 256) {
        const float* src;
        long long basei;
        if (i < Bn0)      { src = s0; basei = 0; }
        else if (i < Bn1) { src = s1; basei = Bn0; }
        else if (i < Bn2) { src = s2; basei = Bn1; }
        else if (i < Bn3) { src = s3; basei = Bn2; }
        else              { src = s4; basei = Bn3; }
        const float4* xp = (const float4*)src + 2 * (i - basei);
        float4 a = xp[0], b = xp[1];
        float h0 = bf_round(a.x), h1 = bf_round(a.y),
              h2 = bf_round(a.z), h3 = bf_round(a.w),
              h4 = bf_round(b.x), h5 = bf_round(b.y),
              h6 = bf_round(b.z), h7 = bf_round(b.w);
        uint4 H, L;
        H.x = pack_bf(h0, h1); H.y = pack_bf(h2, h3);
        H.z = pack_bf(h4, h5); H.w = pack_bf(h6, h7);
        L.x = pack_bf(a.x - h0, a.y - h1); L.y = pack_bf(a.z - h2, a.w - h3);
        L.z = pack_bf(b.x - h4, b.y - h5); L.w = pack_bf(b.z - h6, b.w - h7);
        ((uint4*)h)[i] = H;
        ((uint4*)l)[i] = L;
    }
}

// cls_w2: [NE,100] -> [NE,112] zero-padded FP16 single (hi only; 1-term cls2)
__global__ void cvt_pad_kernel(const float* __restrict__ x,
                               bf16* __restrict__ h)
{
    int total = NE * 28;
    for (int i = blockIdx.x * 256 + threadIdx.x; i < total; i += gridDim.x * 256) {
        int r = i / 28, c4 = (i - r * 28) * 4;
        u32 ha = 0, hb = 0;
        if (c4 < 100) {
            float4 v = *(const float4*)(x + (size_t)r * 100 + c4);
            ha = pack_h2(v.x, v.y); hb = pack_h2(v.z, v.w);
        }
        size_t o = (size_t)r * KPAD + c4;
        *(uint2*)(h + o) = make_uint2(ha, hb);
    }
}

// ----------------------------------------------------------------------------
// Mention pooling (pos/mask int32), inline attention logits.
// ----------------------------------------------------------------------------
__global__ __launch_bounds__(256)
void pool_kernel(const float* __restrict__ lhs,
                 const int* __restrict__ pos,
                 const int* __restrict__ mask,
                 const float* __restrict__ aw,
                 float* __restrict__ x,
                 bf16* __restrict__ xh, bf16* __restrict__ xl)
{
    int bm = blockIdx.x;
    int b = bm >> 7;
    int t = threadIdx.x;
    __shared__ float dots[LL];
    __shared__ float ws[LL];
    __shared__ int s_nv;

    {
        int l = t >> 3, sub = t & 7;
        const float* row = lhs + ((size_t)b * SS + l) * DD;
        float p = 0.f;
        for (int j = sub; j < DD; j += 8) p += row[j] * aw[j];
        #pragma unroll
        for (int o = 4; o; o >>= 1) p += __shfl_xor_sync(~0u, p, o);
        if (sub == 0) dots[l] = p;
    }
    __syncthreads();

    if (t < 32) {
        int p = pos[(size_t)bm * LL + t];
        unsigned bits = __ballot_sync(0xffffffffu, p != -1);
        int nv;
        if (mask[bm] == 0) nv = 0;
        else if (~bits == 0u) nv = 32;
        else nv = __ffs(~bits) - 1;
        float logit = (t < nv) ? dots[t] : 0.f;
        float mx = logit;
        #pragma unroll
        for (int o = 16; o; o >>= 1) mx = fmaxf(mx, __shfl_xor_sync(~0u, mx, o));
        float e = expf(logit - mx);
        float s = e;
        #pragma unroll
        for (int o = 16; o; o >>= 1) s += __shfl_xor_sync(~0u, s, o);
        ws[t] = e / s;
        if (t == 0) s_nv = nv;
    }
    __syncthreads();
    int nv = s_nv;
    for (int d = t; d < DD; d += 256) {
        float acc = 0.f;
        for (int l = 0; l < nv; l++)
            acc += ws[l] * lhs[((size_t)b * SS + l) * DD + d];
        size_t idx = (size_t)bm * DD + d;
        x[idx] = acc;
        split_write(xh, xl, idx, acc);
    }
}

// ----------------------------------------------------------------------------
// Tensor-core split NT GEMM: mma.sync + ldmatrix + 3-stage cp.async ring.
// OCC CTAs/SM (template). CTA tile TM x TN. 8 warps: 4m x 2n.
// PREC=0: bf16 A(hi,lo) x B(hi,lo), 3 mmas (term-major interleave).
// PREC=1: fp16 A(hi) x B(hi,lo), 2 mmas.
// PREC=2: fp16 A(hi) x B(hi), 1 mma.
// SPLIT=0 -> fp32 C (+ blockIdx.z * M*ldout); SPLIT=1 -> bf16 hi/lo;
// SPLIT=2 -> fp16 single (Ch). cols [N,padN) zeroed.
// lda/ldb row strides; Klen = K per z-slice (blockIdx.z*Klen offset).
// ----------------------------------------------------------------------------
template<int TM, int TN, int RELU, int SPLIT, int PREC, int OCC>
__global__ __launch_bounds__(256, OCC)
void gemm_tc(const bf16* __restrict__ Ah, const bf16* __restrict__ Al,
             const bf16* __restrict__ Bh, const bf16* __restrict__ Bl,
             const float* __restrict__ bias,
             float* __restrict__ C, bf16* __restrict__ Ch, bf16* __restrict__ Cl,
             int M, int N, int lda, int ldb, int Klen, int ldout, int padN)
{
    constexpr int MI  = TM / 64;
    constexpr int NJW = TN / 16;
    constexpr int NA  = (PREC == 0) ? 2 : 1;
    constexpr int NB  = (PREC == 2) ? 1 : 2;
    constexpr int ASZ = TM * 64;
    constexpr int BSZ = TN * 64;
    constexpr int BUF = NA * ASZ + NB * BSZ;

    extern __shared__ char smem[];
    const u32 base = smem_u32(smem);
    const int t = threadIdx.x, lane = t & 31, warp = t >> 5;
    const int mBase = blockIdx.y * TM, nBase = blockIdx.x * TN;
    const int kOff = blockIdx.z * Klen;
    const int wm = (warp >> 1) * (TM / 4), wn = (warp & 1) * (TN / 2);
    const int ar0 = wm + (lane & 15);
    const int ahi = lane >> 4;
    const int br0 = wn + (lane & 7) + ((lane >> 4) << 3);
    const int bhi = (lane >> 3) & 1;

    float acc[MI][NJW][4];
    #pragma unroll
    for (int mi = 0; mi < MI; mi++)
        #pragma unroll
        for (int nj = 0; nj < NJW; nj++)
            #pragma unroll
            for (int r = 0; r < 4; r++) acc[mi][nj][r] = 0.f;

    const int S = (Klen + 31) / 32;

    auto loadSlab = [&](int s) {
        const int k0 = s * 32;
        const u32 bb = base + (s % 3) * BUF;
        #pragma unroll
        for (int p = 0; p < TM / 64; p++) {
            int c = p * 256 + t, row = c >> 2, ch = c & 3;
            int kk = k0 + ch * 8;
            int avail = Klen - kk;
            int sz = (avail >= 8) ? 16 : (avail > 0 ? avail * 2 : 0);
            u32 off = row * 64 + ((u32)(ch ^ ((row >> 1) & 3)) << 4);
            cp_async16(bb + off, Ah + (size_t)(mBase + row) * lda + kOff + kk, sz);
            if (PREC == 0)
                cp_async16(bb + ASZ + off, Al + (size_t)(mBase + row) * lda + kOff + kk, sz);
        }
        #pragma unroll
        for (int p = 0; p < TN / 64; p++) {
            int c = p * 256 + t, row = c >> 2, ch = c & 3;
            int kk = k0 + ch * 8;
            int avail = Klen - kk;
            int sz = (avail >= 8) ? 16 : (avail > 0 ? avail * 2 : 0);
            if (nBase + row >= N) sz = 0;
            u32 off = row * 64 + ((u32)(ch ^ ((row >> 1) & 3)) << 4);
            cp_async16(bb + NA * ASZ + off, Bh + (size_t)(nBase + row) * ldb + kOff + kk, sz);
            if (PREC < 2)
                cp_async16(bb + NA * ASZ + BSZ + off, Bl + (size_t)(nBase + row) * ldb + kOff + kk, sz);
        }
    };

    loadSlab(0);
    CP_COMMIT();
    if (S > 1) loadSlab(1);
    CP_COMMIT();

    for (int s = 0; s < S; s++) {
        CP_WAIT1();
        __syncthreads();
        if (s + 2 < S) loadSlab(s + 2);
        CP_COMMIT();

        const u32 bb = base + (s % 3) * BUF;
        const u32 aB0 = bb, aB1 = bb + ASZ;
        const u32 bB0 = bb + NA * ASZ, bB1 = bb + NA * ASZ + BSZ;

        #pragma unroll
        for (int ks = 0; ks < 2; ks++) {
            u32 ahf[MI][4], alf[MI][4];
            #pragma unroll
            for (int mi = 0; mi < MI; mi++) {
                int row = ar0 + mi * 16;
                u32 off = row * 64 + ((u32)((ks * 2 + ahi) ^ ((row >> 1) & 3)) << 4);
                ldsm4(aB0 + off, ahf[mi][0], ahf[mi][1], ahf[mi][2], ahf[mi][3]);
                if (PREC == 0)
                    ldsm4(aB1 + off, alf[mi][0], alf[mi][1], alf[mi][2], alf[mi][3]);
            }
            #pragma unroll
            for (int j = 0; j < NJW / 2; j++) {
                int row = br0 + j * 16;
                u32 off = row * 64 + ((u32)((ks * 2 + bhi) ^ ((row >> 1) & 3)) << 4);
                u32 b0, b1, b2, b3, l0, l1, l2, l3;
                ldsm4(bB0 + off, b0, b1, b2, b3);
                if (PREC < 2) ldsm4(bB1 + off, l0, l1, l2, l3);
                // term-major ordering: same-acc reuse distance = 2*MI mmas
                if (PREC == 0) {
                    #pragma unroll
                    for (int mi = 0; mi < MI; mi++) {
                        mma_bf16(acc[mi][2 * j],     ahf[mi], b0, b1);
                        mma_bf16(acc[mi][2 * j + 1], ahf[mi], b2, b3);
                    }
                    #pragma unroll
                    for (int mi = 0; mi < MI; mi++) {
                        mma_bf16(acc[mi][2 * j],     ahf[mi], l0, l1);
                        mma_bf16(acc[mi][2 * j + 1], ahf[mi], l2, l3);
                    }
                    #pragma unroll
                    for (int mi = 0; mi < MI; mi++) {
                        mma_bf16(acc[mi][2 * j],     alf[mi], b0, b1);
                        mma_bf16(acc[mi][2 * j + 1], alf[mi], b2, b3);
                    }
                } else if (PREC == 1) {
                    #pragma unroll
                    for (int mi = 0; mi < MI; mi++) {
                        mma_f16(acc[mi][2 * j],     ahf[mi], b0, b1);
                        mma_f16(acc[mi][2 * j + 1], ahf[mi], b2, b3);
                    }
                    #pragma unroll
                    for (int mi = 0; mi < MI; mi++) {
                        mma_f16(acc[mi][2 * j],     ahf[mi], l0, l1);
                        mma_f16(acc[mi][2 * j + 1], ahf[mi], l2, l3);
                    }
                } else {
                    #pragma unroll
                    for (int mi = 0; mi < MI; mi++) {
                        mma_f16(acc[mi][2 * j],     ahf[mi], b0, b1);
                        mma_f16(acc[mi][2 * j + 1], ahf[mi], b2, b3);
                    }
                }
            }
        }
    }

    // epilogue
    float* Cz = C + (size_t)blockIdx.z * M * ldout;
    const int g = lane >> 2, tg = lane & 3;
    #pragma unroll
    for (int mi = 0; mi < MI; mi++) {
        int row0 = mBase + wm + mi * 16 + g;
        #pragma unroll
        for (int nj = 0; nj < NJW; nj++) {
            int col0 = nBase + wn + nj * 8 + 2 * tg;
            if (col0 < padN) {
                #pragma unroll
                for (int rr = 0; rr < 2; rr++) {
                    int row = row0 + rr * 8;
                    float v0 = 0.f, v1 = 0.f;
                    if (col0 < N) {
                        v0 = acc[mi][nj][rr * 2 + 0] + (bias ? bias[col0] : 0.f);
                        v1 = acc[mi][nj][rr * 2 + 1] + (bias ? bias[col0 + 1] : 0.f);
                        if (RELU) { v0 = fmaxf(v0, 0.f); v1 = fmaxf(v1, 0.f); }
                    }
                    size_t idx = (size_t)row * ldout + col0;
                    if (SPLIT == 1)      split_store2(Ch, Cl, idx, v0, v1);
                    else if (SPLIT == 2) *(u32*)(Ch + idx) = pack_h2(v0, v1);
                    else                 *(float2*)(Cz + idx) = make_float2(v0, v1);
                }
            }
        }
    }
}

// ----------------------------------------------------------------------------
// Fused attention: one CTA per (b,h), 8 warps x 16 Q-rows. 2 CTAs/SM.
// ----------------------------------------------------------------------------
__global__ __launch_bounds__(256, 2)
void attn_fused(const bf16* __restrict__ qkvh, const bf16* __restrict__ qkvl,
                bf16* __restrict__ aoh, bf16* __restrict__ aol)
{
    extern __shared__ char smem[];
    const u32 base = smem_u32(smem);
    const int t = threadIdx.x, lane = t & 31, warp = t >> 5;
    const int bh = blockIdx.x, b = bh / HH, h = bh % HH;
    const size_t rowBase = (size_t)b * MM;
    const int g = lane >> 2, tg = lane & 3;

    #pragma unroll
    for (int m = 0; m < 6; m++) {
        const bf16* src = (m & 1) ? qkvl : qkvh;
        int colOff = (m >> 1) * DD + h * HD;
        u32 dst = base + m * 16384;
        #pragma unroll
        for (int p = 0; p < 4; p++) {
            int c = p * 256 + t;
            int row = c >> 3, ch = c & 7;
            u32 off = row * 128 + ((u32)(ch ^ (row & 7)) << 4);
            cp_async16(dst + off,
                       src + (rowBase + row) * (3 * DD) + colOff + ch * 8, 16);
        }
    }
    CP_COMMIT(); CP_WAIT0();
    __syncthreads();

    const u32 sQh = base, sQl = base + 16384;
    const u32 sKh = base + 32768, sKl = base + 49152;
    const u32 sVh = base + 65536, sVl = base + 81920;
    const int m0 = warp * 16;

    float acc[16][4];
    #pragma unroll
    for (int nj = 0; nj < 16; nj++)
        #pragma unroll
        for (int r = 0; r < 4; r++) acc[nj][r] = 0.f;

    const int tile = lane >> 3, wr = lane & 7;
    #pragma unroll
    for (int kk = 0; kk < 4; kk++) {
        u32 qh4[4], ql4[4];
        {
            int row = m0 + wr + (tile & 1) * 8;
            int ch = kk * 2 + (tile >> 1);
            u32 off = row * 128 + ((u32)(ch ^ (row & 7)) << 4);
            ldsm4(sQh + off, qh4[0], qh4[1], qh4[2], qh4[3]);
            ldsm4(sQl + off, ql4[0], ql4[1], ql4[2], ql4[3]);
        }
        #pragma unroll
        for (int nj2 = 0; nj2 < 8; nj2++) {
            int row = nj2 * 16 + wr + (tile >> 1) * 8;
            int ch = kk * 2 + (tile & 1);
            u32 off = row * 128 + ((u32)(ch ^ (row & 7)) << 4);
            u32 b0, b1, b2, b3, l0, l1, l2, l3;
            ldsm4(sKh + off, b0, b1, b2, b3);
            ldsm4(sKl + off, l0, l1, l2, l3);
            mma_bf16(acc[2 * nj2],     qh4, b0, b1);
            mma_bf16(acc[2 * nj2 + 1], qh4, b2, b3);
            mma_bf16(acc[2 * nj2],     qh4, l0, l1);
            mma_bf16(acc[2 * nj2 + 1], qh4, l2, l3);
            mma_bf16(acc[2 * nj2],     ql4, b0, b1);
            mma_bf16(acc[2 * nj2 + 1], ql4, b2, b3);
        }
    }

    {
        float mx0 = -1e30f, mx1 = -1e30f;
        #pragma unroll
        for (int nj = 0; nj < 16; nj++) {
            acc[nj][0] *= 0.125f; acc[nj][1] *= 0.125f;
            acc[nj][2] *= 0.125f; acc[nj][3] *= 0.125f;
            mx0 = fmaxf(mx0, fmaxf(acc[nj][0], acc[nj][1]));
            mx1 = fmaxf(mx1, fmaxf(acc[nj][2], acc[nj][3]));
        }
        mx0 = fmaxf(mx0, __shfl_xor_sync(~0u, mx0, 1));
        mx0 = fmaxf(mx0, __shfl_xor_sync(~0u, mx0, 2));
        mx1 = fmaxf(mx1, __shfl_xor_sync(~0u, mx1, 1));
        mx1 = fmaxf(mx1, __shfl_xor_sync(~0u, mx1, 2));
        float s0 = 0.f, s1 = 0.f;
        #pragma unroll
        for (int nj = 0; nj < 16; nj++) {
            acc[nj][0] = expf(acc[nj][0] - mx0);
            acc[nj][1] = expf(acc[nj][1] - mx0);
            acc[nj][2] = expf(acc[nj][2] - mx1);
            acc[nj][3] = expf(acc[nj][3] - mx1);
            s0 += acc[nj][0] + acc[nj][1];
            s1 += acc[nj][2] + acc[nj][3];
        }
        s0 += __shfl_xor_sync(~0u, s0, 1);
        s0 += __shfl_xor_sync(~0u, s0, 2);
        s1 += __shfl_xor_sync(~0u, s1, 1);
        s1 += __shfl_xor_sync(~0u, s1, 2);
        float i0 = 1.f / s0, i1 = 1.f / s1;
        #pragma unroll
        for (int nj = 0; nj < 16; nj++) {
            acc[nj][0] *= i0; acc[nj][1] *= i0;
            acc[nj][2] *= i1; acc[nj][3] *= i1;
        }
    }

    float o[8][4];
    #pragma unroll
    for (int nj = 0; nj < 8; nj++)
        #pragma unroll
        for (int r = 0; r < 4; r++) o[nj][r] = 0.f;

    #pragma unroll
    for (int j = 0; j < 8; j++) {
        u32 pa_h[4], pa_l[4];
        #pragma unroll
        for (int q = 0; q < 2; q++) {
            float p0 = acc[2 * j + q][0], p1 = acc[2 * j + q][1];
            float p2 = acc[2 * j + q][2], p3 = acc[2 * j + q][3];
            float h0 = bf_round(p0), h1 = bf_round(p1);
            float h2 = bf_round(p2), h3 = bf_round(p3);
            pa_h[0 + 2 * q] = pack_bf(h0, h1);
            pa_h[1 + 2 * q] = pack_bf(h2, h3);
            pa_l[0 + 2 * q] = pack_bf(p0 - h0, p1 - h1);
            pa_l[1 + 2 * q] = pack_bf(p2 - h2, p3 - h3);
        }
        #pragma unroll
        for (int c2 = 0; c2 < 4; c2++) {
            int row = j * 16 + wr + (tile & 1) * 8;
            int ch = 2 * c2 + (tile >> 1);
            u32 off = row * 128 + ((u32)(ch ^ (row & 7)) << 4);
            u32 v0, v1, v2, v3, w0, w1, w2, w3;
            ldsm4t(sVh + off, v0, v1, v2, v3);
            ldsm4t(sVl + off, w0, w1, w2, w3);
            mma_bf16(o[2 * c2],     pa_h, v0, v1);
            mma_bf16(o[2 * c2 + 1], pa_h, v2, v3);
            mma_bf16(o[2 * c2],     pa_h, w0, w1);
            mma_bf16(o[2 * c2 + 1], pa_h, w2, w3);
            mma_bf16(o[2 * c2],     pa_l, v0, v1);
            mma_bf16(o[2 * c2 + 1], pa_l, v2, v3);
        }
    }

    {
        size_t gr = rowBase + m0 + g;
        #pragma unroll
        for (int nj = 0; nj < 8; nj++) {
            int col = h * HD + nj * 8 + 2 * tg;
            split_store2(aoh, aol, gr * DD + col, o[nj][0], o[nj][1]);
            split_store2(aoh, aol, (gr + 8) * DD + col, o[nj][2], o[nj][3]);
        }
    }
}

// ----------------------------------------------------------------------------
// x = LayerNorm(x + d0 + d1 + bias) * w + b; writes bf16 split of x
// ----------------------------------------------------------------------------
__global__ __launch_bounds__(256)
void add_ln_kernel(float* __restrict__ x,
                   const float* __restrict__ d0p, const float* __restrict__ d1p,
                   const float* __restrict__ bias,
                   const float* __restrict__ w, const float* __restrict__ b,
                   bf16* __restrict__ xh, bf16* __restrict__ xl)
{
    int row = blockIdx.x, t = threadIdx.x;
    float* xp = x + (size_t)row * DD;
    const float* a0 = d0p + (size_t)row * DD;
    const float* a1 = d1p + (size_t)row * DD;
    float v0 = xp[t]       + a0[t]       + a1[t]       + bias[t];
    float v1 = xp[t + 256] + a0[t + 256] + a1[t + 256] + bias[t + 256];
    float v2 = xp[t + 512] + a0[t + 512] + a1[t + 512] + bias[t + 512];
    float s = v0 + v1 + v2;
    __shared__ float red[8];
    #pragma unroll
    for (int o = 16; o; o >>= 1) s += __shfl_xor_sync(~0u, s, o);
    if ((t & 31) == 0) red[t >> 5] = s;
    __syncthreads();
    float tot = red[0] + red[1] + red[2] + red[3] + red[4] + red[5] + red[6] + red[7];
    float mu = tot * (1.f / 768.f);
    float d0 = v0 - mu, d1 = v1 - mu, d2 = v2 - mu;
    float q = d0 * d0 + d1 * d1 + d2 * d2;
    #pragma unroll
    for (int o = 16; o; o >>= 1) q += __shfl_xor_sync(~0u, q, o);
    __syncthreads();
    if ((t & 31) == 0) red[t >> 5] = q;
    __syncthreads();
    float qt = red[0] + red[1] + red[2] + red[3] + red[4] + red[5] + red[6] + red[7];
    float inv = rsqrtf(qt * (1.f / 768.f) + 1e-5f);
    float o0 = d0 * inv * w[t]       + b[t];
    float o1 = d1 * inv * w[t + 256] + b[t + 256];
    float o2 = d2 * inv * w[t + 512] + b[t + 512];
    size_t rb = (size_t)row * DD;
    xp[t] = o0;       split_write(xh, xl, rb + t,       o0);
    xp[t + 256] = o1; split_write(xh, xl, rb + t + 256, o1);
    xp[t + 512] = o2; split_write(xh, xl, rb + t + 512, o2);
}

// ----------------------------------------------------------------------------
// Host-side launch
// ----------------------------------------------------------------------------
template<typename T>
static T* sym(const void* s)
{
    void* p = nullptr;
    cudaGetSymbolAddress(&p, s);
    return (T*)p;
}

#define SMEM_G(TM, TN, NA, NB) (3 * ((NA) * (TM) * 64 + (NB) * (TN) * 64))
#define SMEMATT (6 * 16384)

extern "C" void kernel_launch(void* const* d_in, const int* in_sizes, int n_in,
                              void* d_out, int out_size)
{
    static const long long want[20] = {
        6291456LL, 65536LL, 2048LL, 768LL, 1LL,
        7077888LL, 9216LL, 2359296LL, 3072LL, 3072LL, 3072LL,
        9437184LL, 12288LL, 9437184LL, 3072LL, 3072LL, 3072LL,
        76800LL, 5000000LL, 50000LL
    };
    const void* slot[20];
    bool used[64];
    for (int i = 0; i < 20; i++) slot[i] = nullptr;
    for (int i = 0; i < n_in && i < 64; i++) used[i] = false;
    for (int w = 0; w < 20; w++) {
        for (int i = 0; i < n_in && i < 64; i++) {
            if (!used[i] && (long long)in_sizes[i] == want[w]) {
                slot[w] = d_in[i];
                used[i] = true;
                break;
            }
        }
    }
    if (!slot[0]) {
        for (int w = 0; w < 20 && w < n_in; w++) slot[w] = d_in[w];
    }

    const float* lhs    = (const float*)slot[0];
    const int*   pos    = (const int*)slot[1];
    const int*   mask   = (const int*)slot[2];
    const float* attn_w = (const float*)slot[3];
    const float* qkv_w  = (const float*)slot[5];
    const float* qkv_b  = (const float*)slot[6];
    const float* out_w  = (const float*)slot[7];
    const float* out_b  = (const float*)slot[8];
    const float* ln1_w  = (const float*)slot[9];
    const float* ln1_b  = (const float*)slot[10];
    const float* ff1_w  = (const float*)slot[11];
    const float* ff1_b  = (const float*)slot[12];
    const float* ff2_w  = (const float*)slot[13];
    const float* ff2_b  = (const float*)slot[14];
    const float* ln2_w  = (const float*)slot[15];
    const float* ln2_b  = (const float*)slot[16];
    const float* cls_w1 = (const float*)slot[17];
    const float* cls_w2 = (const float*)slot[18];
    const float* cls_b2 = (const float*)slot[19];
    float* out = (float*)d_out;

    float* x   = sym<float>(g_x);
    float* tmp = sym<float>(g_tmp);
    bf16*  wh  = sym<bf16>(g_wh);
    bf16*  wl  = sym<bf16>(g_wl);
    bf16*  ah  = sym<bf16>(g_ah);
    bf16*  al  = sym<bf16>(g_al);
    bf16*  bh2 = sym<bf16>(g_bh);
    bf16*  bl2 = sym<bf16>(g_bl);

    cudaFuncSetAttribute(gemm_tc<128, 128, 0, 1, 0, 2>, cudaFuncAttributeMaxDynamicSharedMemorySize, SMEM_G(128, 128, 2, 2));
    cudaFuncSetAttribute(gemm_tc<128, 64, 0, 0, 0, 3>,  cudaFuncAttributeMaxDynamicSharedMemorySize, SMEM_G(128, 64, 2, 2));
    cudaFuncSetAttribute(gemm_tc<128, 64, 1, 1, 0, 3>,  cudaFuncAttributeMaxDynamicSharedMemorySize, SMEM_G(128, 64, 2, 2));
    cudaFuncSetAttribute(gemm_tc<128, 64, 0, 2, 0, 3>,  cudaFuncAttributeMaxDynamicSharedMemorySize, SMEM_G(128, 64, 2, 2));
    cudaFuncSetAttribute(gemm_tc<128, 128, 0, 0, 2, 2>, cudaFuncAttributeMaxDynamicSharedMemorySize, SMEM_G(128, 128, 1, 1));
    cudaFuncSetAttribute(attn_fused, cudaFuncAttributeMaxDynamicSharedMemorySize, SMEMATT);

    // --- fork: pool + cls2 weight pad on side stream, overlapped with cvt_all
    cudaStream_t s2;
    cudaStreamCreateWithFlags(&s2, cudaStreamNonBlocking);
    cudaEvent_t eFork, eJoin;
    cudaEventCreateWithFlags(&eFork, cudaEventDisableTiming);
    cudaEventCreateWithFlags(&eJoin, cudaEventDisableTiming);

    cudaEventRecord(eFork, 0);
    cudaStreamWaitEvent(s2, eFork, 0);
    pool_kernel<<<ROWS, 256, 0, s2>>>(lhs, pos, mask, attn_w, x, ah, al);
    cvt_pad_kernel<<<2736, 256, 0, s2>>>(cls_w2, wh + OW_CLS2);
    cudaEventRecord(eJoin, s2);

    cvt_all_kernel<<<6934, 256>>>(qkv_w, out_w, ff1_w, ff2_w, cls_w1, wh, wl);
    cudaStreamWaitEvent(0, eJoin, 0);

    // --- transformer layers ---
    for (int i = 0; i < NL; i++) {
        // qkv: TN=128/OCC=2 -> 288 CTAs = 0.97 wave
        gemm_tc<128, 128, 0, 1, 0, 2><<<dim3(18, 16, 1), 256, SMEM_G(128, 128, 2, 2)>>>(
            ah, al, wh + OW_QKV + (size_t)i * 3 * DD * DD,
            wl + OW_QKV + (size_t)i * 3 * DD * DD,
            qkv_b + (size_t)i * 3 * DD, nullptr, bh2, bl2,
            ROWS, 3 * DD, DD, DD, DD, 3 * DD, 3 * DD);
        attn_fused<<<BB * HH, 256, SMEMATT>>>(bh2, bl2, ah, al);
        // out-proj: split-K 2, partials to tmp[0], tmp[1]
        gemm_tc<128, 64, 0, 0, 0, 3><<<dim3(12, 16, 2), 256, SMEM_G(128, 64, 2, 2)>>>(
            ah, al, wh + OW_OUT + (size_t)i * DD * DD,
            wl + OW_OUT + (size_t)i * DD * DD,
            nullptr, tmp, nullptr, nullptr,
            ROWS, DD, DD, DD, DD / 2, DD, DD);
        add_ln_kernel<<<ROWS, 256>>>(x, tmp, tmp + (size_t)ROWS * DD,
                                     out_b + (size_t)i * DD,
                                     ln1_w + (size_t)i * DD, ln1_b + (size_t)i * DD,
                                     ah, al);
        gemm_tc<128, 64, 1, 1, 0, 3><<<dim3(48, 16, 1), 256, SMEM_G(128, 64, 2, 2)>>>(
            ah, al, wh + OW_FF1 + (size_t)i * DFF * DD,
            wl + OW_FF1 + (size_t)i * DFF * DD,
            ff1_b + (size_t)i * DFF, nullptr, bh2, bl2,
            ROWS, DFF, DD, DD, DD, DFF, DFF);
        // ff2: split-K 2
        gemm_tc<128, 64, 0, 0, 0, 3><<<dim3(12, 16, 2), 256, SMEM_G(128, 64, 2, 2)>>>(
            bh2, bl2, wh + OW_FF2 + (size_t)i * DD * DFF,
            wl + OW_FF2 + (size_t)i * DD * DFF,
            nullptr, tmp, nullptr, nullptr,
            ROWS, DD, DFF, DFF, DFF / 2, DD, DD);
        add_ln_kernel<<<ROWS, 256>>>(x, tmp, tmp + (size_t)ROWS * DD,
                                     ff2_b + (size_t)i * DD,
                                     ln2_w + (size_t)i * DD, ln2_b + (size_t)i * DD,
                                     ah, al);
    }

    // --- classifier head ---
    // cls1: bf16 3-term, output y as fp16 single into bh2 ([ROWS, KPAD])
    gemm_tc<128, 64, 0, 2, 0, 3><<<dim3(2, 16, 1), 256, SMEM_G(128, 64, 2, 2)>>>(
        ah, al, wh + OW_CLS1, wl + OW_CLS1, nullptr,
        nullptr, bh2, nullptr, ROWS, 100, DD, DD, DD, KPAD, KPAD);
    // cls2: fp16 1-term (A = y fp16 single, B = cls_w2 fp16 single)
    gemm_tc<128, 128, 0, 0, 2, 2><<<dim3((NE + 127) / 128, 16, 1), 256, SMEM_G(128, 128, 1, 1)>>>(
        bh2, nullptr, wh + OW_CLS2, nullptr, cls_b2,
        out, nullptr, nullptr, ROWS, NE, KPAD, KPAD, KPAD, NE, NE);
}

// round 14
// speedup vs baseline: 4.7566x; 1.0169x over previous
#include <cuda_runtime.h>
#include <cuda_bf16.h>
#include <cuda_fp16.h>
#include <math.h>
#include <cstdint>

// ----------------------------------------------------------------------------
// Problem constants
// ----------------------------------------------------------------------------
#define BB   16
#define MM   128
#define LL   32
#define SS   512
#define DD   768
#define HH   12
#define HD   64
#define DFF  3072
#define NL   4
#define NE   50000
#define ROWS (BB*MM)          // 2048
#define KPAD 112              // padded K for classifier stage 2

typedef unsigned long long ull;
typedef unsigned int u32;
typedef __nv_bfloat16 bf16;

// weight scratch offsets (elements)
#define OW_QKV  0ULL
#define OW_OUT  7077888ULL
#define OW_FF1  9437184ULL
#define OW_FF2  18874368ULL
#define OW_CLS1 28311552ULL
#define OW_CLS2 28388352ULL
#define NW_TOT  (28388352ULL + 50000ULL*KPAD)

// ----------------------------------------------------------------------------
// Device scratch (static allocation — no cudaMalloc allowed)
// ----------------------------------------------------------------------------
__device__ float g_x [ROWS*DD];
__device__ float g_tmp[ROWS*DFF];            // split-K partials (2 x ROWS*DD)
__device__ __align__(256) bf16 g_wh[NW_TOT];
__device__ __align__(256) bf16 g_wl[NW_TOT];
__device__ __align__(256) bf16 g_ah[ROWS*DFF];
__device__ __align__(256) bf16 g_al[ROWS*DFF];
__device__ __align__(256) bf16 g_bh[ROWS*DFF];
__device__ __align__(256) bf16 g_bl[ROWS*DFF];

// ----------------------------------------------------------------------------
// PTX helpers
// ----------------------------------------------------------------------------
__device__ __forceinline__ u32 smem_u32(const void* p)
{
    u32 a;
    asm("{ .reg .u64 t; cvta.to.shared.u64 t, %1; cvt.u32.u64 %0, t; }"
        : "=r"(a) : "l"(p));
    return a;
}

__device__ __forceinline__ void cp_async16(u32 dst, const void* src, int sz)
{
    asm volatile("cp.async.cg.shared.global [%0], [%1], 16, %2;"
        :: "r"(dst), "l"(src), "r"(sz));
}
#define CP_COMMIT() asm volatile("cp.async.commit_group;" ::: "memory")
#define CP_WAIT1()  asm volatile("cp.async.wait_group 1;" ::: "memory")
#define CP_WAIT0()  asm volatile("cp.async.wait_group 0;" ::: "memory")

__device__ __forceinline__ void ldsm4(u32 addr, u32& r0, u32& r1, u32& r2, u32& r3)
{
    asm volatile("ldmatrix.sync.aligned.m8n8.x4.shared.b16 {%0,%1,%2,%3}, [%4];"
        : "=r"(r0), "=r"(r1), "=r"(r2), "=r"(r3) : "r"(addr));
}
__device__ __forceinline__ void ldsm4t(u32 addr, u32& r0, u32& r1, u32& r2, u32& r3)
{
    asm volatile("ldmatrix.sync.aligned.m8n8.x4.trans.shared.b16 {%0,%1,%2,%3}, [%4];"
        : "=r"(r0), "=r"(r1), "=r"(r2), "=r"(r3) : "r"(addr));
}

__device__ __forceinline__ void mma_bf16(float* d, const u32* a, u32 b0, u32 b1)
{
    asm volatile(
        "mma.sync.aligned.m16n8k16.row.col.f32.bf16.bf16.f32 "
        "{%0,%1,%2,%3},{%4,%5,%6,%7},{%8,%9},{%0,%1,%2,%3};"
        : "+f"(d[0]), "+f"(d[1]), "+f"(d[2]), "+f"(d[3])
        : "r"(a[0]), "r"(a[1]), "r"(a[2]), "r"(a[3]), "r"(b0), "r"(b1));
}
__device__ __forceinline__ void mma_f16(float* d, const u32* a, u32 b0, u32 b1)
{
    asm volatile(
        "mma.sync.aligned.m16n8k16.row.col.f32.f16.f16.f32 "
        "{%0,%1,%2,%3},{%4,%5,%6,%7},{%8,%9},{%0,%1,%2,%3};"
        : "+f"(d[0]), "+f"(d[1]), "+f"(d[2]), "+f"(d[3])
        : "r"(a[0]), "r"(a[1]), "r"(a[2]), "r"(a[3]), "r"(b0), "r"(b1));
}

// pack two fp32 into bf16x2 word: first arg -> lower halfword
__device__ __forceinline__ u32 pack_bf(float lo, float hi)
{
    u32 r;
    asm("cvt.rn.bf16x2.f32 %0, %1, %2;" : "=r"(r) : "f"(hi), "f"(lo));
    return r;
}
__device__ __forceinline__ u32 pack_h2(float lo, float hi)
{
    __half2 h = __floats2half2_rn(lo, hi);
    return *(u32*)&h;
}

__device__ __forceinline__ float bf_round(float v)
{
    return __bfloat162float(__float2bfloat16(v));
}

__device__ __forceinline__ void split_write(bf16* h, bf16* l, size_t idx, float v)
{
    bf16 hh = __float2bfloat16(v);
    h[idx] = hh;
    l[idx] = __float2bfloat16(v - __bfloat162float(hh));
}

__device__ __forceinline__ void split_store2(bf16* h, bf16* l, size_t idx,
                                             float v0, float v1)
{
    float h0 = bf_round(v0), h1 = bf_round(v1);
    *(u32*)(h + idx) = pack_bf(h0, h1);
    *(u32*)(l + idx) = pack_bf(v0 - h0, v1 - h1);
}

// ----------------------------------------------------------------------------
// Weight conversion: one contiguous segment -> bf16 hi/lo (n8 8-elem units)
// ----------------------------------------------------------------------------
__global__ void cvt_seg_kernel(const float* __restrict__ src,
                               bf16* __restrict__ h, bf16* __restrict__ l,
                               long long n8)
{
    for (long long i = (long long)blockIdx.x * 256 + threadIdx.x; i < n8;
         i += (long long)gridDim.x * 256) {
        const float4* xp = (const float4*)src + 2 * i;
        float4 a = xp[0], b = xp[1];
        float h0 = bf_round(a.x), h1 = bf_round(a.y),
              h2 = bf_round(a.z), h3 = bf_round(a.w),
              h4 = bf_round(b.x), h5 = bf_round(b.y),
              h6 = bf_round(b.z), h7 = bf_round(b.w);
        uint4 H, L;
        H.x = pack_bf(h0, h1); H.y = pack_bf(h2, h3);
        H.z = pack_bf(h4, h5); H.w = pack_bf(h6, h7);
        L.x = pack_bf(a.x - h0, a.y - h1); L.y = pack_bf(a.z - h2, a.w - h3);
        L.z = pack_bf(b.x - h4, b.y - h5); L.w = pack_bf(b.z - h6, b.w - h7);
        ((uint4*)h)[i] = H;
        ((uint4*)l)[i] = L;
    }
}

// cls_w2: [NE,100] -> [NE,112] zero-padded FP16 single (hi only; 1-term cls2)
__global__ void cvt_pad_kernel(const float* __restrict__ x,
                               bf16* __restrict__ h)
{
    int total = NE * 28;
    for (int i = blockIdx.x * 256 + threadIdx.x; i < total; i += gridDim.x * 256) {
        int r = i / 28, c4 = (i - r * 28) * 4;
        u32 ha = 0, hb = 0;
        if (c4 < 100) {
            float4 v = *(const float4*)(x + (size_t)r * 100 + c4);
            ha = pack_h2(v.x, v.y); hb = pack_h2(v.z, v.w);
        }
        size_t o = (size_t)r * KPAD + c4;
        *(uint2*)(h + o) = make_uint2(ha, hb);
    }
}

// ----------------------------------------------------------------------------
// Mention pooling (pos/mask int32), inline attention logits.
// ----------------------------------------------------------------------------
__global__ __launch_bounds__(256)
void pool_kernel(const float* __restrict__ lhs,
                 const int* __restrict__ pos,
                 const int* __restrict__ mask,
                 const float* __restrict__ aw,
                 float* __restrict__ x,
                 bf16* __restrict__ xh, bf16* __restrict__ xl)
{
    int bm = blockIdx.x;
    int b = bm >> 7;
    int t = threadIdx.x;
    __shared__ float dots[LL];
    __shared__ float ws[LL];
    __shared__ int s_nv;

    {
        int l = t >> 3, sub = t & 7;
        const float* row = lhs + ((size_t)b * SS + l) * DD;
        float p = 0.f;
        for (int j = sub; j < DD; j += 8) p += row[j] * aw[j];
        #pragma unroll
        for (int o = 4; o; o >>= 1) p += __shfl_xor_sync(~0u, p, o);
        if (sub == 0) dots[l] = p;
    }
    __syncthreads();

    if (t < 32) {
        int p = pos[(size_t)bm * LL + t];
        unsigned bits = __ballot_sync(0xffffffffu, p != -1);
        int nv;
        if (mask[bm] == 0) nv = 0;
        else if (~bits == 0u) nv = 32;
        else nv = __ffs(~bits) - 1;
        float logit = (t < nv) ? dots[t] : 0.f;
        float mx = logit;
        #pragma unroll
        for (int o = 16; o; o >>= 1) mx = fmaxf(mx, __shfl_xor_sync(~0u, mx, o));
        float e = expf(logit - mx);
        float s = e;
        #pragma unroll
        for (int o = 16; o; o >>= 1) s += __shfl_xor_sync(~0u, s, o);
        ws[t] = e / s;
        if (t == 0) s_nv = nv;
    }
    __syncthreads();
    int nv = s_nv;
    for (int d = t; d < DD; d += 256) {
        float acc = 0.f;
        for (int l = 0; l < nv; l++)
            acc += ws[l] * lhs[((size_t)b * SS + l) * DD + d];
        size_t idx = (size_t)bm * DD + d;
        x[idx] = acc;
        split_write(xh, xl, idx, acc);
    }
}

// ----------------------------------------------------------------------------
// Tensor-core split NT GEMM (unchanged machinery).
// ----------------------------------------------------------------------------
template<int TM, int TN, int RELU, int SPLIT, int PREC, int OCC>
__global__ __launch_bounds__(256, OCC)
void gemm_tc(const bf16* __restrict__ Ah, const bf16* __restrict__ Al,
             const bf16* __restrict__ Bh, const bf16* __restrict__ Bl,
             const float* __restrict__ bias,
             float* __restrict__ C, bf16* __restrict__ Ch, bf16* __restrict__ Cl,
             int M, int N, int lda, int ldb, int Klen, int ldout, int padN)
{
    constexpr int MI  = TM / 64;
    constexpr int NJW = TN / 16;
    constexpr int NA  = (PREC == 0) ? 2 : 1;
    constexpr int NB  = (PREC == 2) ? 1 : 2;
    constexpr int ASZ = TM * 64;
    constexpr int BSZ = TN * 64;
    constexpr int BUF = NA * ASZ + NB * BSZ;

    extern __shared__ char smem[];
    const u32 base = smem_u32(smem);
    const int t = threadIdx.x, lane = t & 31, warp = t >> 5;
    const int mBase = blockIdx.y * TM, nBase = blockIdx.x * TN;
    const int kOff = blockIdx.z * Klen;
    const int wm = (warp >> 1) * (TM / 4), wn = (warp & 1) * (TN / 2);
    const int ar0 = wm + (lane & 15);
    const int ahi = lane >> 4;
    const int br0 = wn + (lane & 7) + ((lane >> 4) << 3);
    const int bhi = (lane >> 3) & 1;

    float acc[MI][NJW][4];
    #pragma unroll
    for (int mi = 0; mi < MI; mi++)
        #pragma unroll
        for (int nj = 0; nj < NJW; nj++)
            #pragma unroll
            for (int r = 0; r < 4; r++) acc[mi][nj][r] = 0.f;

    const int S = (Klen + 31) / 32;

    auto loadSlab = [&](int s) {
        const int k0 = s * 32;
        const u32 bb = base + (s % 3) * BUF;
        #pragma unroll
        for (int p = 0; p < TM / 64; p++) {
            int c = p * 256 + t, row = c >> 2, ch = c & 3;
            int kk = k0 + ch * 8;
            int avail = Klen - kk;
            int sz = (avail >= 8) ? 16 : (avail > 0 ? avail * 2 : 0);
            u32 off = row * 64 + ((u32)(ch ^ ((row >> 1) & 3)) << 4);
            cp_async16(bb + off, Ah + (size_t)(mBase + row) * lda + kOff + kk, sz);
            if (PREC == 0)
                cp_async16(bb + ASZ + off, Al + (size_t)(mBase + row) * lda + kOff + kk, sz);
        }
        #pragma unroll
        for (int p = 0; p < TN / 64; p++) {
            int c = p * 256 + t, row = c >> 2, ch = c & 3;
            int kk = k0 + ch * 8;
            int avail = Klen - kk;
            int sz = (avail >= 8) ? 16 : (avail > 0 ? avail * 2 : 0);
            if (nBase + row >= N) sz = 0;
            u32 off = row * 64 + ((u32)(ch ^ ((row >> 1) & 3)) << 4);
            cp_async16(bb + NA * ASZ + off, Bh + (size_t)(nBase + row) * ldb + kOff + kk, sz);
            if (PREC < 2)
                cp_async16(bb + NA * ASZ + BSZ + off, Bl + (size_t)(nBase + row) * ldb + kOff + kk, sz);
        }
    };

    loadSlab(0);
    CP_COMMIT();
    if (S > 1) loadSlab(1);
    CP_COMMIT();

    for (int s = 0; s < S; s++) {
        CP_WAIT1();
        __syncthreads();
        if (s + 2 < S) loadSlab(s + 2);
        CP_COMMIT();

        const u32 bb = base + (s % 3) * BUF;
        const u32 aB0 = bb, aB1 = bb + ASZ;
        const u32 bB0 = bb + NA * ASZ, bB1 = bb + NA * ASZ + BSZ;

        #pragma unroll
        for (int ks = 0; ks < 2; ks++) {
            u32 ahf[MI][4], alf[MI][4];
            #pragma unroll
            for (int mi = 0; mi < MI; mi++) {
                int row = ar0 + mi * 16;
                u32 off = row * 64 + ((u32)((ks * 2 + ahi) ^ ((row >> 1) & 3)) << 4);
                ldsm4(aB0 + off, ahf[mi][0], ahf[mi][1], ahf[mi][2], ahf[mi][3]);
                if (PREC == 0)
                    ldsm4(aB1 + off, alf[mi][0], alf[mi][1], alf[mi][2], alf[mi][3]);
            }
            #pragma unroll
            for (int j = 0; j < NJW / 2; j++) {
                int row = br0 + j * 16;
                u32 off = row * 64 + ((u32)((ks * 2 + bhi) ^ ((row >> 1) & 3)) << 4);
                u32 b0, b1, b2, b3, l0, l1, l2, l3;
                ldsm4(bB0 + off, b0, b1, b2, b3);
                if (PREC < 2) ldsm4(bB1 + off, l0, l1, l2, l3);
                if (PREC == 0) {
                    #pragma unroll
                    for (int mi = 0; mi < MI; mi++) {
                        mma_bf16(acc[mi][2 * j],     ahf[mi], b0, b1);
                        mma_bf16(acc[mi][2 * j + 1], ahf[mi], b2, b3);
                    }
                    #pragma unroll
                    for (int mi = 0; mi < MI; mi++) {
                        mma_bf16(acc[mi][2 * j],     ahf[mi], l0, l1);
                        mma_bf16(acc[mi][2 * j + 1], ahf[mi], l2, l3);
                    }
                    #pragma unroll
                    for (int mi = 0; mi < MI; mi++) {
                        mma_bf16(acc[mi][2 * j],     alf[mi], b0, b1);
                        mma_bf16(acc[mi][2 * j + 1], alf[mi], b2, b3);
                    }
                } else if (PREC == 1) {
                    #pragma unroll
                    for (int mi = 0; mi < MI; mi++) {
                        mma_f16(acc[mi][2 * j],     ahf[mi], b0, b1);
                        mma_f16(acc[mi][2 * j + 1], ahf[mi], b2, b3);
                    }
                    #pragma unroll
                    for (int mi = 0; mi < MI; mi++) {
                        mma_f16(acc[mi][2 * j],     ahf[mi], l0, l1);
                        mma_f16(acc[mi][2 * j + 1], ahf[mi], l2, l3);
                    }
                } else {
                    #pragma unroll
                    for (int mi = 0; mi < MI; mi++) {
                        mma_f16(acc[mi][2 * j],     ahf[mi], b0, b1);
                        mma_f16(acc[mi][2 * j + 1], ahf[mi], b2, b3);
                    }
                }
            }
        }
    }

    // epilogue
    float* Cz = C + (size_t)blockIdx.z * M * ldout;
    const int g = lane >> 2, tg = lane & 3;
    #pragma unroll
    for (int mi = 0; mi < MI; mi++) {
        int row0 = mBase + wm + mi * 16 + g;
        #pragma unroll
        for (int nj = 0; nj < NJW; nj++) {
            int col0 = nBase + wn + nj * 8 + 2 * tg;
            if (col0 < padN) {
                #pragma unroll
                for (int rr = 0; rr < 2; rr++) {
                    int row = row0 + rr * 8;
                    float v0 = 0.f, v1 = 0.f;
                    if (col0 < N) {
                        v0 = acc[mi][nj][rr * 2 + 0] + (bias ? bias[col0] : 0.f);
                        v1 = acc[mi][nj][rr * 2 + 1] + (bias ? bias[col0 + 1] : 0.f);
                        if (RELU) { v0 = fmaxf(v0, 0.f); v1 = fmaxf(v1, 0.f); }
                    }
                    size_t idx = (size_t)row * ldout + col0;
                    if (SPLIT == 1)      split_store2(Ch, Cl, idx, v0, v1);
                    else if (SPLIT == 2) *(u32*)(Ch + idx) = pack_h2(v0, v1);
                    else                 *(float2*)(Cz + idx) = make_float2(v0, v1);
                }
            }
        }
    }
}

// ----------------------------------------------------------------------------
// Fused attention, Q-split: one CTA per (b,h,half). 4 warps x 16 Q-rows = 64.
// 128 threads, 2 CTAs/SM. Full K/V tiles; Q covers rows [half*64, half*64+64).
// ----------------------------------------------------------------------------
#define SMEMATT (2 * 8192 + 4 * 16384)     // 81920

__global__ __launch_bounds__(128, 2)
void attn_fused(const bf16* __restrict__ qkvh, const bf16* __restrict__ qkvl,
                bf16* __restrict__ aoh, bf16* __restrict__ aol)
{
    extern __shared__ char smem[];
    const u32 base = smem_u32(smem);
    const int t = threadIdx.x, lane = t & 31, warp = t >> 5;
    const int bh2 = blockIdx.x, bh = bh2 >> 1, half = bh2 & 1;
    const int b = bh / HH, h = bh % HH;
    const size_t rowBase = (size_t)b * MM;
    const int qOff = half * 64;
    const int g = lane >> 2, tg = lane & 3;

    const u32 sQh = base, sQl = base + 8192;
    const u32 sKh = base + 16384, sKl = base + 32768;
    const u32 sVh = base + 49152, sVl = base + 65536;

    // Q loads: 64 rows x 8 chunks per split; 4 iters of 128 threads
    #pragma unroll
    for (int m = 0; m < 2; m++) {
        const bf16* src = m ? qkvl : qkvh;
        u32 dst = m ? sQl : sQh;
        #pragma unroll
        for (int p = 0; p < 4; p++) {
            int c = p * 128 + t;
            int row = c >> 3, ch = c & 7;
            u32 off = row * 128 + ((u32)(ch ^ (row & 7)) << 4);
            cp_async16(dst + off,
                       src + (rowBase + qOff + row) * (3 * DD) + h * HD + ch * 8, 16);
        }
    }
    // K/V loads: 128 rows x 8 chunks per split; 8 iters
    #pragma unroll
    for (int m = 0; m < 4; m++) {
        const bf16* src = (m & 1) ? qkvl : qkvh;
        int colOff = (1 + (m >> 1)) * DD + h * HD;   // K then V
        u32 dst = (m == 0) ? sKh : (m == 1) ? sKl : (m == 2) ? sVh : sVl;
        #pragma unroll
        for (int p = 0; p < 8; p++) {
            int c = p * 128 + t;
            int row = c >> 3, ch = c & 7;
            u32 off = row * 128 + ((u32)(ch ^ (row & 7)) << 4);
            cp_async16(dst + off,
                       src + (rowBase + row) * (3 * DD) + colOff + ch * 8, 16);
        }
    }
    CP_COMMIT(); CP_WAIT0();
    __syncthreads();

    const int m0 = warp * 16;

    float acc[16][4];
    #pragma unroll
    for (int nj = 0; nj < 16; nj++)
        #pragma unroll
        for (int r = 0; r < 4; r++) acc[nj][r] = 0.f;

    const int tile = lane >> 3, wr = lane & 7;
    #pragma unroll
    for (int kk = 0; kk < 4; kk++) {
        u32 qh4[4], ql4[4];
        {
            int row = m0 + wr + (tile & 1) * 8;
            int ch = kk * 2 + (tile >> 1);
            u32 off = row * 128 + ((u32)(ch ^ (row & 7)) << 4);
            ldsm4(sQh + off, qh4[0], qh4[1], qh4[2], qh4[3]);
            ldsm4(sQl + off, ql4[0], ql4[1], ql4[2], ql4[3]);
        }
        #pragma unroll
        for (int nj2 = 0; nj2 < 8; nj2++) {
            int row = nj2 * 16 + wr + (tile >> 1) * 8;
            int ch = kk * 2 + (tile & 1);
            u32 off = row * 128 + ((u32)(ch ^ (row & 7)) << 4);
            u32 b0, b1, b2, b3, l0, l1, l2, l3;
            ldsm4(sKh + off, b0, b1, b2, b3);
            ldsm4(sKl + off, l0, l1, l2, l3);
            mma_bf16(acc[2 * nj2],     qh4, b0, b1);
            mma_bf16(acc[2 * nj2 + 1], qh4, b2, b3);
            mma_bf16(acc[2 * nj2],     qh4, l0, l1);
            mma_bf16(acc[2 * nj2 + 1], qh4, l2, l3);
            mma_bf16(acc[2 * nj2],     ql4, b0, b1);
            mma_bf16(acc[2 * nj2 + 1], ql4, b2, b3);
        }
    }

    {
        float mx0 = -1e30f, mx1 = -1e30f;
        #pragma unroll
        for (int nj = 0; nj < 16; nj++) {
            acc[nj][0] *= 0.125f; acc[nj][1] *= 0.125f;
            acc[nj][2] *= 0.125f; acc[nj][3] *= 0.125f;
            mx0 = fmaxf(mx0, fmaxf(acc[nj][0], acc[nj][1]));
            mx1 = fmaxf(mx1, fmaxf(acc[nj][2], acc[nj][3]));
        }
        mx0 = fmaxf(mx0, __shfl_xor_sync(~0u, mx0, 1));
        mx0 = fmaxf(mx0, __shfl_xor_sync(~0u, mx0, 2));
        mx1 = fmaxf(mx1, __shfl_xor_sync(~0u, mx1, 1));
        mx1 = fmaxf(mx1, __shfl_xor_sync(~0u, mx1, 2));
        float s0 = 0.f, s1 = 0.f;
        #pragma unroll
        for (int nj = 0; nj < 16; nj++) {
            acc[nj][0] = expf(acc[nj][0] - mx0);
            acc[nj][1] = expf(acc[nj][1] - mx0);
            acc[nj][2] = expf(acc[nj][2] - mx1);
            acc[nj][3] = expf(acc[nj][3] - mx1);
            s0 += acc[nj][0] + acc[nj][1];
            s1 += acc[nj][2] + acc[nj][3];
        }
        s0 += __shfl_xor_sync(~0u, s0, 1);
        s0 += __shfl_xor_sync(~0u, s0, 2);
        s1 += __shfl_xor_sync(~0u, s1, 1);
        s1 += __shfl_xor_sync(~0u, s1, 2);
        float i0 = 1.f / s0, i1 = 1.f / s1;
        #pragma unroll
        for (int nj = 0; nj < 16; nj++) {
            acc[nj][0] *= i0; acc[nj][1] *= i0;
            acc[nj][2] *= i1; acc[nj][3] *= i1;
        }
    }

    float o[8][4];
    #pragma unroll
    for (int nj = 0; nj < 8; nj++)
        #pragma unroll
        for (int r = 0; r < 4; r++) o[nj][r] = 0.f;

    #pragma unroll
    for (int j = 0; j < 8; j++) {
        u32 pa_h[4], pa_l[4];
        #pragma unroll
        for (int q = 0; q < 2; q++) {
            float p0 = acc[2 * j + q][0], p1 = acc[2 * j + q][1];
            float p2 = acc[2 * j + q][2], p3 = acc[2 * j + q][3];
            float h0 = bf_round(p0), h1 = bf_round(p1);
            float h2 = bf_round(p2), h3 = bf_round(p3);
            pa_h[0 + 2 * q] = pack_bf(h0, h1);
            pa_h[1 + 2 * q] = pack_bf(h2, h3);
            pa_l[0 + 2 * q] = pack_bf(p0 - h0, p1 - h1);
            pa_l[1 + 2 * q] = pack_bf(p2 - h2, p3 - h3);
        }
        #pragma unroll
        for (int c2 = 0; c2 < 4; c2++) {
            int row = j * 16 + wr + (tile & 1) * 8;
            int ch = 2 * c2 + (tile >> 1);
            u32 off = row * 128 + ((u32)(ch ^ (row & 7)) << 4);
            u32 v0, v1, v2, v3, w0, w1, w2, w3;
            ldsm4t(sVh + off, v0, v1, v2, v3);
            ldsm4t(sVl + off, w0, w1, w2, w3);
            mma_bf16(o[2 * c2],     pa_h, v0, v1);
            mma_bf16(o[2 * c2 + 1], pa_h, v2, v3);
            mma_bf16(o[2 * c2],     pa_h, w0, w1);
            mma_bf16(o[2 * c2 + 1], pa_h, w2, w3);
            mma_bf16(o[2 * c2],     pa_l, v0, v1);
            mma_bf16(o[2 * c2 + 1], pa_l, v2, v3);
        }
    }

    {
        size_t gr = rowBase + qOff + m0 + g;
        #pragma unroll
        for (int nj = 0; nj < 8; nj++) {
            int col = h * HD + nj * 8 + 2 * tg;
            split_store2(aoh, aol, gr * DD + col, o[nj][0], o[nj][1]);
            split_store2(aoh, aol, (gr + 8) * DD + col, o[nj][2], o[nj][3]);
        }
    }
}

// ----------------------------------------------------------------------------
// x = LayerNorm(x + d0 + d1 + bias) * w + b; writes bf16 split of x
// ----------------------------------------------------------------------------
__global__ __launch_bounds__(256)
void add_ln_kernel(float* __restrict__ x,
                   const float* __restrict__ d0p, const float* __restrict__ d1p,
                   const float* __restrict__ bias,
                   const float* __restrict__ w, const float* __restrict__ b,
                   bf16* __restrict__ xh, bf16* __restrict__ xl)
{
    int row = blockIdx.x, t = threadIdx.x;
    float* xp = x + (size_t)row * DD;
    const float* a0 = d0p + (size_t)row * DD;
    const float* a1 = d1p + (size_t)row * DD;
    float v0 = xp[t]       + a0[t]       + a1[t]       + bias[t];
    float v1 = xp[t + 256] + a0[t + 256] + a1[t + 256] + bias[t + 256];
    float v2 = xp[t + 512] + a0[t + 512] + a1[t + 512] + bias[t + 512];
    float s = v0 + v1 + v2;
    __shared__ float red[8];
    #pragma unroll
    for (int o = 16; o; o >>= 1) s += __shfl_xor_sync(~0u, s, o);
    if ((t & 31) == 0) red[t >> 5] = s;
    __syncthreads();
    float tot = red[0] + red[1] + red[2] + red[3] + red[4] + red[5] + red[6] + red[7];
    float mu = tot * (1.f / 768.f);
    float d0 = v0 - mu, d1 = v1 - mu, d2 = v2 - mu;
    float q = d0 * d0 + d1 * d1 + d2 * d2;
    #pragma unroll
    for (int o = 16; o; o >>= 1) q += __shfl_xor_sync(~0u, q, o);
    __syncthreads();
    if ((t & 31) == 0) red[t >> 5] = q;
    __syncthreads();
    float qt = red[0] + red[1] + red[2] + red[3] + red[4] + red[5] + red[6] + red[7];
    float inv = rsqrtf(qt * (1.f / 768.f) + 1e-5f);
    float o0 = d0 * inv * w[t]       + b[t];
    float o1 = d1 * inv * w[t + 256] + b[t + 256];
    float o2 = d2 * inv * w[t + 512] + b[t + 512];
    size_t rb = (size_t)row * DD;
    xp[t] = o0;       split_write(xh, xl, rb + t,       o0);
    xp[t + 256] = o1; split_write(xh, xl, rb + t + 256, o1);
    xp[t + 512] = o2; split_write(xh, xl, rb + t + 512, o2);
}

// ----------------------------------------------------------------------------
// Host-side launch
// ----------------------------------------------------------------------------
template<typename T>
static T* sym(const void* s)
{
    void* p = nullptr;
    cudaGetSymbolAddress(&p, s);
    return (T*)p;
}

#define SMEM_G(TM, TN, NA, NB) (3 * ((NA) * (TM) * 64 + (NB) * (TN) * 64))

extern "C" void kernel_launch(void* const* d_in, const int* in_sizes, int n_in,
                              void* d_out, int out_size)
{
    static const long long want[20] = {
        6291456LL, 65536LL, 2048LL, 768LL, 1LL,
        7077888LL, 9216LL, 2359296LL, 3072LL, 3072LL, 3072LL,
        9437184LL, 12288LL, 9437184LL, 3072LL, 3072LL, 3072LL,
        76800LL, 5000000LL, 50000LL
    };
    const void* slot[20];
    bool used[64];
    for (int i = 0; i < 20; i++) slot[i] = nullptr;
    for (int i = 0; i < n_in && i < 64; i++) used[i] = false;
    for (int w = 0; w < 20; w++) {
        for (int i = 0; i < n_in && i < 64; i++) {
            if (!used[i] && (long long)in_sizes[i] == want[w]) {
                slot[w] = d_in[i];
                used[i] = true;
                break;
            }
        }
    }
    if (!slot[0]) {
        for (int w = 0; w < 20 && w < n_in; w++) slot[w] = d_in[w];
    }

    const float* lhs    = (const float*)slot[0];
    const int*   pos    = (const int*)slot[1];
    const int*   mask   = (const int*)slot[2];
    const float* attn_w = (const float*)slot[3];
    const float* qkv_w  = (const float*)slot[5];
    const float* qkv_b  = (const float*)slot[6];
    const float* out_w  = (const float*)slot[7];
    const float* out_b  = (const float*)slot[8];
    const float* ln1_w  = (const float*)slot[9];
    const float* ln1_b  = (const float*)slot[10];
    const float* ff1_w  = (const float*)slot[11];
    const float* ff1_b  = (const float*)slot[12];
    const float* ff2_w  = (const float*)slot[13];
    const float* ff2_b  = (const float*)slot[14];
    const float* ln2_w  = (const float*)slot[15];
    const float* ln2_b  = (const float*)slot[16];
    const float* cls_w1 = (const float*)slot[17];
    const float* cls_w2 = (const float*)slot[18];
    const float* cls_b2 = (const float*)slot[19];
    float* out = (float*)d_out;

    float* x   = sym<float>(g_x);
    float* tmp = sym<float>(g_tmp);
    bf16*  wh  = sym<bf16>(g_wh);
    bf16*  wl  = sym<bf16>(g_wl);
    bf16*  ah  = sym<bf16>(g_ah);
    bf16*  al  = sym<bf16>(g_al);
    bf16*  bh2 = sym<bf16>(g_bh);
    bf16*  bl2 = sym<bf16>(g_bl);

    cudaFuncSetAttribute(gemm_tc<128, 128, 0, 1, 0, 2>, cudaFuncAttributeMaxDynamicSharedMemorySize, SMEM_G(128, 128, 2, 2));
    cudaFuncSetAttribute(gemm_tc<128, 64, 0, 0, 0, 3>,  cudaFuncAttributeMaxDynamicSharedMemorySize, SMEM_G(128, 64, 2, 2));
    cudaFuncSetAttribute(gemm_tc<128, 64, 1, 1, 0, 3>,  cudaFuncAttributeMaxDynamicSharedMemorySize, SMEM_G(128, 64, 2, 2));
    cudaFuncSetAttribute(gemm_tc<128, 64, 0, 2, 0, 3>,  cudaFuncAttributeMaxDynamicSharedMemorySize, SMEM_G(128, 64, 2, 2));
    cudaFuncSetAttribute(gemm_tc<128, 128, 0, 0, 2, 2>, cudaFuncAttributeMaxDynamicSharedMemorySize, SMEM_G(128, 128, 1, 1));
    cudaFuncSetAttribute(attn_fused, cudaFuncAttributeMaxDynamicSharedMemorySize, SMEMATT);

    // --- prologue pipeline ---
    // main: qkv-weight cvt (needed first). side: pool (needed before qkv
    // layer 0), then remaining weight cvts (needed before out-proj layer 0).
    cudaStream_t s2;
    cudaStreamCreateWithFlags(&s2, cudaStreamNonBlocking);
    cudaEvent_t eFork, ePool, eJoin;
    cudaEventCreateWithFlags(&eFork, cudaEventDisableTiming);
    cudaEventCreateWithFlags(&ePool, cudaEventDisableTiming);
    cudaEventCreateWithFlags(&eJoin, cudaEventDisableTiming);

    cudaEventRecord(eFork, 0);
    cudaStreamWaitEvent(s2, eFork, 0);
    pool_kernel<<<ROWS, 256, 0, s2>>>(lhs, pos, mask, attn_w, x, ah, al);
    cudaEventRecord(ePool, s2);
    cvt_seg_kernel<<<2048, 256, 0, s2>>>(out_w,  wh + OW_OUT,  wl + OW_OUT,  294912);
    cvt_seg_kernel<<<4096, 256, 0, s2>>>(ff1_w,  wh + OW_FF1,  wl + OW_FF1,  1179648);
    cvt_seg_kernel<<<4096, 256, 0, s2>>>(ff2_w,  wh + OW_FF2,  wl + OW_FF2,  1179648);
    cvt_seg_kernel<<<64,   256, 0, s2>>>(cls_w1, wh + OW_CLS1, wl + OW_CLS1, 9600);
    cvt_pad_kernel<<<2736, 256, 0, s2>>>(cls_w2, wh + OW_CLS2);
    cudaEventRecord(eJoin, s2);

    cvt_seg_kernel<<<3456, 256>>>(qkv_w, wh + OW_QKV, wl + OW_QKV, 884736);
    cudaStreamWaitEvent(0, ePool, 0);

    // --- transformer layers ---
    for (int i = 0; i < NL; i++) {
        gemm_tc<128, 128, 0, 1, 0, 2><<<dim3(18, 16, 1), 256, SMEM_G(128, 128, 2, 2)>>>(
            ah, al, wh + OW_QKV + (size_t)i * 3 * DD * DD,
            wl + OW_QKV + (size_t)i * 3 * DD * DD,
            qkv_b + (size_t)i * 3 * DD, nullptr, bh2, bl2,
            ROWS, 3 * DD, DD, DD, DD, 3 * DD, 3 * DD);
        attn_fused<<<BB * HH * 2, 128, SMEMATT>>>(bh2, bl2, ah, al);
        if (i == 0) cudaStreamWaitEvent(0, eJoin, 0);
        gemm_tc<128, 64, 0, 0, 0, 3><<<dim3(12, 16, 2), 256, SMEM_G(128, 64, 2, 2)>>>(
            ah, al, wh + OW_OUT + (size_t)i * DD * DD,
            wl + OW_OUT + (size_t)i * DD * DD,
            nullptr, tmp, nullptr, nullptr,
            ROWS, DD, DD, DD, DD / 2, DD, DD);
        add_ln_kernel<<<ROWS, 256>>>(x, tmp, tmp + (size_t)ROWS * DD,
                                     out_b + (size_t)i * DD,
                                     ln1_w + (size_t)i * DD, ln1_b + (size_t)i * DD,
                                     ah, al);
        gemm_tc<128, 64, 1, 1, 0, 3><<<dim3(48, 16, 1), 256, SMEM_G(128, 64, 2, 2)>>>(
            ah, al, wh + OW_FF1 + (size_t)i * DFF * DD,
            wl + OW_FF1 + (size_t)i * DFF * DD,
            ff1_b + (size_t)i * DFF, nullptr, bh2, bl2,
            ROWS, DFF, DD, DD, DD, DFF, DFF);
        gemm_tc<128, 64, 0, 0, 0, 3><<<dim3(12, 16, 2), 256, SMEM_G(128, 64, 2, 2)>>>(
            bh2, bl2, wh + OW_FF2 + (size_t)i * DD * DFF,
            wl + OW_FF2 + (size_t)i * DD * DFF,
            nullptr, tmp, nullptr, nullptr,
            ROWS, DD, DFF, DFF, DFF / 2, DD, DD);
        add_ln_kernel<<<ROWS, 256>>>(x, tmp, tmp + (size_t)ROWS * DD,
                                     ff2_b + (size_t)i * DD,
                                     ln2_w + (size_t)i * DD, ln2_b + (size_t)i * DD,
                                     ah, al);
    }

    // --- classifier head ---
    gemm_tc<128, 64, 0, 2, 0, 3><<<dim3(2, 16, 1), 256, SMEM_G(128, 64, 2, 2)>>>(
        ah, al, wh + OW_CLS1, wl + OW_CLS1, nullptr,
        nullptr, bh2, nullptr, ROWS, 100, DD, DD, DD, KPAD, KPAD);
    gemm_tc<128, 128, 0, 0, 2, 2><<<dim3((NE + 127) / 128, 16, 1), 256, SMEM_G(128, 128, 1, 1)>>>(
        bh2, nullptr, wh + OW_CLS2, nullptr, cls_b2,
        out, nullptr, nullptr, ROWS, NE, KPAD, KPAD, KPAD, NE, NE);
}